// round 6
// baseline (speedup 1.0000x reference)
#include <cuda_runtime.h>
#include <cuda_bf16.h>
#include <cstdint>

#define S 2048
#define D 4096
#define H 32
#define KVH 8
#define HD 128
#define NREP (H / KVH)
#define KVD (KVH * HD)

// ---------------- scratch (static device arrays; no allocation) ----------------
__device__ __nv_bfloat16 g_xhi[S * D], g_xlo[S * D];
__device__ __nv_bfloat16 g_ahi[S * D], g_alo[S * D];
__device__ __nv_bfloat16 g_qhi[S * D], g_qlo[S * D];
__device__ __nv_bfloat16 g_khi[S * KVD], g_klo[S * KVD];
__device__ __nv_bfloat16 g_vthi[KVD * S], g_vtlo[KVD * S];
__device__ __nv_bfloat16 g_wqhi[D * D], g_wqlo[D * D];       // transposed [N,K]
__device__ __nv_bfloat16 g_wkhi[KVD * D], g_wklo[KVD * D];
__device__ __nv_bfloat16 g_wvhi[KVD * D], g_wvlo[KVD * D];
__device__ __nv_bfloat16 g_wohi[D * D], g_wolo[D * D];

// ---------------- helpers ----------------
__device__ __forceinline__ uint32_t s2u(const void* p) {
    uint32_t a;
    asm("{ .reg .u64 t; cvta.to.shared.u64 t, %1; cvt.u32.u64 %0, t; }" : "=r"(a) : "l"(p));
    return a;
}
__device__ __forceinline__ void cpasync16(uint32_t saddr, const void* gaddr) {
    asm volatile("cp.async.cg.shared.global [%0], [%1], 16;" :: "r"(saddr), "l"(gaddr));
}
__device__ __forceinline__ void ldmx4(uint32_t* r, uint32_t addr) {
    asm volatile("ldmatrix.sync.aligned.m8n8.x4.shared.b16 {%0,%1,%2,%3}, [%4];"
                 : "=r"(r[0]), "=r"(r[1]), "=r"(r[2]), "=r"(r[3]) : "r"(addr));
}
__device__ __forceinline__ void mma16816(float* d, const uint32_t* a, const uint32_t* b) {
    asm volatile(
        "mma.sync.aligned.m16n8k16.row.col.f32.bf16.bf16.f32 "
        "{%0,%1,%2,%3}, {%4,%5,%6,%7}, {%8,%9}, {%0,%1,%2,%3};"
        : "+f"(d[0]), "+f"(d[1]), "+f"(d[2]), "+f"(d[3])
        : "r"(a[0]), "r"(a[1]), "r"(a[2]), "r"(a[3]), "r"(b[0]), "r"(b[1]));
}
__device__ __forceinline__ uint32_t pack_bf16(float x, float y) {
    __nv_bfloat162 t = __floats2bfloat162_rn(x, y);
    return *reinterpret_cast<uint32_t*>(&t);
}
__device__ __forceinline__ void split2(float v0, float v1, __nv_bfloat162& ph, __nv_bfloat162& pl) {
    __nv_bfloat16 h0 = __float2bfloat16(v0), h1 = __float2bfloat16(v1);
    ph.x = h0; ph.y = h1;
    pl.x = __float2bfloat16(v0 - __bfloat162float(h0));
    pl.y = __float2bfloat16(v1 - __bfloat162float(h1));
}

// ---------------- split: fp32 -> (hi, lo) bf16, same layout ----------------
__global__ void split_kernel(const float* __restrict__ in,
                             __nv_bfloat16* __restrict__ hi,
                             __nv_bfloat16* __restrict__ lo, int n4)
{
    int i = blockIdx.x * blockDim.x + threadIdx.x;
    if (i >= n4) return;
    float4 v = reinterpret_cast<const float4*>(in)[i];
    __nv_bfloat162 ph, pl;
    split2(v.x, v.y, ph, pl);
    reinterpret_cast<__nv_bfloat162*>(hi)[2 * i] = ph;
    reinterpret_cast<__nv_bfloat162*>(lo)[2 * i] = pl;
    split2(v.z, v.w, ph, pl);
    reinterpret_cast<__nv_bfloat162*>(hi)[2 * i + 1] = ph;
    reinterpret_cast<__nv_bfloat162*>(lo)[2 * i + 1] = pl;
}

// ---------------- transpose+split: W[K,N] fp32 -> hi/lo bf16 [N,K] ----------------
__global__ void tsplit_kernel(const float* __restrict__ w,
                              __nv_bfloat16* __restrict__ hi,
                              __nv_bfloat16* __restrict__ lo, int K, int N)
{
    __shared__ float t[32][33];
    int n0 = blockIdx.x * 32, k0 = blockIdx.y * 32;
    int tx = threadIdx.x, ty = threadIdx.y;
    for (int r = ty; r < 32; r += 8)
        t[r][tx] = w[(size_t)(k0 + r) * N + n0 + tx];
    __syncthreads();
    for (int r = ty; r < 32; r += 8) {
        float v = t[tx][r];
        __nv_bfloat16 h = __float2bfloat16(v);
        __nv_bfloat16 l = __float2bfloat16(v - __bfloat162float(h));
        size_t o = (size_t)(n0 + r) * K + k0 + tx;
        hi[o] = h; lo[o] = l;
    }
}

// ---------------- mma.sync bf16-split GEMM v3 ----------------
// 128x128 tile, BK=32, 256 threads (8 warps of 64x32), 3-stage cp.async,
// XOR-swizzled 64B rows, ldmatrix, fused epilogues:
//   mode 0: fp32 C      mode 1: RoPE+scale+split bf16   mode 2: transpose+split bf16
#define GTILE  8192u
#define GSTAGE 32768u

__global__ __launch_bounds__(256, 2) void gemm_kernel(
    const __nv_bfloat16* __restrict__ Ahi, const __nv_bfloat16* __restrict__ Alo,
    const __nv_bfloat16* __restrict__ Bhi_, const __nv_bfloat16* __restrict__ Blo_,
    float* __restrict__ Cf,
    __nv_bfloat16* __restrict__ Chi_, __nv_bfloat16* __restrict__ Clo_,
    int Ndim, int Kdim, int mode_,
    const float* __restrict__ cosb, const float* __restrict__ sinb, float scale,
    const __nv_bfloat16* __restrict__ Bhi2, const __nv_bfloat16* __restrict__ Blo2,
    __nv_bfloat16* __restrict__ Chi2, __nv_bfloat16* __restrict__ Clo2,
    int mode2, int nx1)
{
    extern __shared__ char dsm[];
    const uint32_t smem = s2u(dsm);

    const int tid = threadIdx.x;
    const int wid = tid >> 5;
    const int lane = tid & 31;
    const int by = blockIdx.y * 128;

    const __nv_bfloat16* Bhi = Bhi_;
    const __nv_bfloat16* Blo = Blo_;
    __nv_bfloat16* Chi = Chi_;
    __nv_bfloat16* Clo = Clo_;
    int mode = mode_;
    int bxi = blockIdx.x;
    if (bxi >= nx1) {
        Bhi = Bhi2; Blo = Blo2; Chi = Chi2; Clo = Clo2; mode = mode2; bxi -= nx1;
    }
    const int bx = bxi * 128;

    const int wm = (wid & 1) * 64;
    const int wn = (wid >> 1) * 32;

    const int grp = lane >> 3;
    const int ri = lane & 7;

    float acc[4][4][4];
#pragma unroll
    for (int i = 0; i < 4; i++)
#pragma unroll
        for (int j = 0; j < 4; j++)
#pragma unroll
            for (int e = 0; e < 4; e++) acc[i][j][e] = 0.0f;

    const int nchunks = Kdim >> 5;

    auto load_stage = [&](int c, int stage) {
        const uint32_t sb = smem + stage * GSTAGE;
        const int k0 = c << 5;
#pragma unroll
        for (int i = 0; i < 2; i++) {
            int idx = tid + i * 256;
            int row = idx >> 2, cc = idx & 3;
            uint32_t sc = (uint32_t)(cc ^ ((row >> 1) & 3));
            uint32_t so = (uint32_t)row * 64u + sc * 16u;
            size_t ga = (size_t)(by + row) * Kdim + k0 + cc * 8;
            size_t gb = (size_t)(bx + row) * Kdim + k0 + cc * 8;
            cpasync16(sb + so,              Ahi + ga);
            cpasync16(sb + GTILE + so,      Alo + ga);
            cpasync16(sb + 2 * GTILE + so,  Bhi + gb);
            cpasync16(sb + 3 * GTILE + so,  Blo + gb);
        }
    };

    load_stage(0, 0);
    asm volatile("cp.async.commit_group;");
    load_stage(1, 1);
    asm volatile("cp.async.commit_group;");

    for (int c = 0; c < nchunks; c++) {
        if (c + 1 < nchunks) asm volatile("cp.async.wait_group 1;");
        else                 asm volatile("cp.async.wait_group 0;");
        __syncthreads();
        if (c + 2 < nchunks) {
            load_stage(c + 2, (c + 2) % 3);
            asm volatile("cp.async.commit_group;");
        }

        const uint32_t sb = smem + (c % 3) * GSTAGE;

#pragma unroll
        for (int k16 = 0; k16 < 2; k16++) {
            const int lchunk = k16 * 2 + (grp >> 1);
            uint32_t ah[4][4], al[4][4];
#pragma unroll
            for (int fm = 0; fm < 4; fm++) {
                int row = wm + fm * 16 + (grp & 1) * 8 + ri;
                uint32_t ad = sb + (uint32_t)row * 64u
                            + (uint32_t)((lchunk ^ ((row >> 1) & 3)) * 16);
                ldmx4(ah[fm], ad);
                ldmx4(al[fm], ad + GTILE);
            }
#pragma unroll
            for (int fnp = 0; fnp < 2; fnp++) {
                int row = wn + fnp * 16 + (grp & 1) * 8 + ri;
                uint32_t bd = sb + 2 * GTILE + (uint32_t)row * 64u
                            + (uint32_t)((lchunk ^ ((row >> 1) & 3)) * 16);
                uint32_t bh4[4], bl4[4];
                ldmx4(bh4, bd);
                ldmx4(bl4, bd + GTILE);
                uint32_t be[2]  = {bh4[0], bh4[2]};
                uint32_t bo[2]  = {bh4[1], bh4[3]};
                uint32_t ble[2] = {bl4[0], bl4[2]};
                uint32_t blo[2] = {bl4[1], bl4[3]};
#pragma unroll
                for (int fm = 0; fm < 4; fm++) {
                    mma16816(acc[fm][2 * fnp],     ah[fm], be);
                    mma16816(acc[fm][2 * fnp],     al[fm], be);
                    mma16816(acc[fm][2 * fnp],     ah[fm], ble);
                    mma16816(acc[fm][2 * fnp + 1], ah[fm], bo);
                    mma16816(acc[fm][2 * fnp + 1], al[fm], bo);
                    mma16816(acc[fm][2 * fnp + 1], ah[fm], blo);
                }
            }
        }
    }

    const int erow = lane >> 2;
    const int ecol = (lane & 3) * 2;

    if (mode == 0) {
#pragma unroll
        for (int fm = 0; fm < 4; fm++) {
#pragma unroll
            for (int fn = 0; fn < 4; fn++) {
                float* cp0 = Cf + (size_t)(by + wm + fm * 16 + erow) * Ndim + bx + wn + fn * 8 + ecol;
                float* cp1 = cp0 + 8 * (size_t)Ndim;
                *reinterpret_cast<float2*>(cp0) = make_float2(acc[fm][fn][0], acc[fm][fn][1]);
                *reinterpret_cast<float2*>(cp1) = make_float2(acc[fm][fn][2], acc[fm][fn][3]);
            }
        }
    } else if (mode == 1) {
        // RoPE + scale + split
#pragma unroll
        for (int fm = 0; fm < 4; fm++) {
#pragma unroll
            for (int fn = 0; fn < 4; fn++) {
                int col = bx + wn + fn * 8 + ecol;
                int i = (col & 127) >> 1;
#pragma unroll
                for (int half = 0; half < 2; half++) {
                    int row = by + wm + fm * 16 + erow + half * 8;
                    float cv = cosb[row * 64 + i];
                    float sv = sinb[row * 64 + i];
                    float t0 = acc[fm][fn][half * 2], t1 = acc[fm][fn][half * 2 + 1];
                    float o0 = (t0 * cv - t1 * sv) * scale;
                    float o1 = (t0 * sv + t1 * cv) * scale;
                    __nv_bfloat162 ph, pl;
                    split2(o0, o1, ph, pl);
                    size_t o = (size_t)row * Ndim + col;
                    *reinterpret_cast<__nv_bfloat162*>(Chi + o) = ph;
                    *reinterpret_cast<__nv_bfloat162*>(Clo + o) = pl;
                }
            }
        }
    } else {
        // transpose + split: out[col][row], row stride S
#pragma unroll
        for (int fm = 0; fm < 4; fm++) {
#pragma unroll
            for (int fn = 0; fn < 4; fn++) {
                int col = bx + wn + fn * 8 + ecol;
#pragma unroll
                for (int half = 0; half < 2; half++) {
                    int row = by + wm + fm * 16 + erow + half * 8;
#pragma unroll
                    for (int e = 0; e < 2; e++) {
                        float v = acc[fm][fn][half * 2 + e];
                        __nv_bfloat16 hb = __float2bfloat16(v);
                        size_t o = (size_t)(col + e) * S + row;
                        Chi[o] = hb;
                        Clo[o] = __float2bfloat16(v - __bfloat162float(hb));
                    }
                }
            }
        }
    }
}

// ---------------- flash attention (mma.sync + ldmatrix, bf16 split) ----------------
#define KPAD 272u
#define VPAD 144u
#define SM_QH 0u
#define SM_QL 17408u
#define SM_KH 34816u
#define SM_KL 52224u
#define SM_VH 69632u
#define SM_VL 88064u
#define SM_TOT 106496u

__global__ __launch_bounds__(128) void fattn_kernel(
    const __nv_bfloat16* __restrict__ Qh, const __nv_bfloat16* __restrict__ Ql,
    const __nv_bfloat16* __restrict__ Kh, const __nv_bfloat16* __restrict__ Kl,
    const __nv_bfloat16* __restrict__ Vth, const __nv_bfloat16* __restrict__ Vtl,
    __nv_bfloat16* __restrict__ Ohi, __nv_bfloat16* __restrict__ Olo)
{
    extern __shared__ char dsm[];
    const uint32_t smem = s2u(dsm);
    const int tid = threadIdx.x;
    const int wid = tid >> 5, lane = tid & 31;
    const int qt = gridDim.x - 1 - blockIdx.x;
    const int h = blockIdx.y;
    const int kvh = h / NREP;
    const int q0 = qt * 64;

    const int r = lane >> 2;
    const int cgrp = lane & 3;
    const int grp = lane >> 3;
    const int ri = lane & 7;

    auto loadK = [&](int t) {
#pragma unroll
        for (int i = 0; i < 8; i++) {
            int idx = tid + i * 128;
            int row = idx >> 4, cc = idx & 15;
            size_t g = (size_t)(t * 64 + row) * KVD + kvh * HD + cc * 8;
            cpasync16(smem + SM_KH + row * KPAD + cc * 16, Kh + g);
            cpasync16(smem + SM_KL + row * KPAD + cc * 16, Kl + g);
        }
    };
    auto loadV = [&](int t) {
#pragma unroll
        for (int i = 0; i < 8; i++) {
            int idx = tid + i * 128;
            int row = idx >> 3, cc = idx & 7;
            size_t g = (size_t)(kvh * HD + row) * S + t * 64 + cc * 8;
            cpasync16(smem + SM_VH + row * VPAD + cc * 16, Vth + g);
            cpasync16(smem + SM_VL + row * VPAD + cc * 16, Vtl + g);
        }
    };

#pragma unroll
    for (int i = 0; i < 8; i++) {
        int idx = tid + i * 128;
        int row = idx >> 4, cc = idx & 15;
        size_t g = (size_t)(q0 + row) * D + h * HD + cc * 8;
        cpasync16(smem + SM_QH + row * KPAD + cc * 16, Qh + g);
        cpasync16(smem + SM_QL + row * KPAD + cc * 16, Ql + g);
    }
    loadK(0);
    asm volatile("cp.async.commit_group;");

    float m0 = -1e30f, m1 = -1e30f, l0 = 0.0f, l1 = 0.0f;
    float oacc[16][4];
#pragma unroll
    for (int f = 0; f < 16; f++)
#pragma unroll
        for (int e = 0; e < 4; e++) oacc[f][e] = 0.0f;

    const int rowA = wid * 16 + r;
    const int rowB = rowA + 8;

    for (int t = 0; t <= qt; t++) {
        asm volatile("cp.async.wait_group 0;");
        __syncthreads();
        loadV(t);
        asm volatile("cp.async.commit_group;");

        float sacc[8][4];
#pragma unroll
        for (int f = 0; f < 8; f++)
#pragma unroll
            for (int e = 0; e < 4; e++) sacc[f][e] = 0.0f;

#pragma unroll
        for (int ks = 0; ks < 8; ks++) {
            uint32_t ah[4], al[4];
            {
                int qrow = wid * 16 + (grp & 1) * 8 + ri;
                uint32_t qa = smem + SM_QH + (uint32_t)qrow * KPAD + ks * 32u + (grp >> 1) * 16u;
                ldmx4(ah, qa);
                ldmx4(al, qa + (SM_QL - SM_QH));
            }
#pragma unroll
            for (int fnp = 0; fnp < 4; fnp++) {
                int krow = fnp * 16 + (grp & 1) * 8 + ri;
                uint32_t ka = smem + SM_KH + (uint32_t)krow * KPAD + ks * 32u + (grp >> 1) * 16u;
                uint32_t bh4[4], bl4[4];
                ldmx4(bh4, ka);
                ldmx4(bl4, ka + (SM_KL - SM_KH));
                uint32_t be[2]  = {bh4[0], bh4[2]};
                uint32_t bo[2]  = {bh4[1], bh4[3]};
                uint32_t ble[2] = {bl4[0], bl4[2]};
                uint32_t blo[2] = {bl4[1], bl4[3]};
                mma16816(sacc[2 * fnp],     ah, be);
                mma16816(sacc[2 * fnp],     al, be);
                mma16816(sacc[2 * fnp],     ah, ble);
                mma16816(sacc[2 * fnp + 1], ah, bo);
                mma16816(sacc[2 * fnp + 1], al, bo);
                mma16816(sacc[2 * fnp + 1], ah, blo);
            }
        }

        if (t == qt) {
#pragma unroll
            for (int fn = 0; fn < 8; fn++) {
                int c0 = fn * 8 + cgrp * 2;
                if (c0 > rowA) sacc[fn][0] = -1e30f;
                if (c0 + 1 > rowA) sacc[fn][1] = -1e30f;
                if (c0 > rowB) sacc[fn][2] = -1e30f;
                if (c0 + 1 > rowB) sacc[fn][3] = -1e30f;
            }
        }

        float tm0 = -1e30f, tm1 = -1e30f;
#pragma unroll
        for (int fn = 0; fn < 8; fn++) {
            tm0 = fmaxf(tm0, fmaxf(sacc[fn][0], sacc[fn][1]));
            tm1 = fmaxf(tm1, fmaxf(sacc[fn][2], sacc[fn][3]));
        }
        tm0 = fmaxf(tm0, __shfl_xor_sync(0xFFFFFFFFu, tm0, 1));
        tm0 = fmaxf(tm0, __shfl_xor_sync(0xFFFFFFFFu, tm0, 2));
        tm1 = fmaxf(tm1, __shfl_xor_sync(0xFFFFFFFFu, tm1, 1));
        tm1 = fmaxf(tm1, __shfl_xor_sync(0xFFFFFFFFu, tm1, 2));

        float mn0 = fmaxf(m0, tm0), mn1 = fmaxf(m1, tm1);
        float corr0 = __expf(m0 - mn0), corr1 = __expf(m1 - mn1);
        m0 = mn0; m1 = mn1;

        float rs0 = 0.0f, rs1 = 0.0f;
#pragma unroll
        for (int fn = 0; fn < 8; fn++) {
            sacc[fn][0] = __expf(sacc[fn][0] - m0);
            sacc[fn][1] = __expf(sacc[fn][1] - m0);
            sacc[fn][2] = __expf(sacc[fn][2] - m1);
            sacc[fn][3] = __expf(sacc[fn][3] - m1);
            rs0 += sacc[fn][0] + sacc[fn][1];
            rs1 += sacc[fn][2] + sacc[fn][3];
        }
        rs0 += __shfl_xor_sync(0xFFFFFFFFu, rs0, 1);
        rs0 += __shfl_xor_sync(0xFFFFFFFFu, rs0, 2);
        rs1 += __shfl_xor_sync(0xFFFFFFFFu, rs1, 1);
        rs1 += __shfl_xor_sync(0xFFFFFFFFu, rs1, 2);
        l0 = l0 * corr0 + rs0;
        l1 = l1 * corr1 + rs1;

#pragma unroll
        for (int f = 0; f < 16; f++) {
            oacc[f][0] *= corr0; oacc[f][1] *= corr0;
            oacc[f][2] *= corr1; oacc[f][3] *= corr1;
        }

        asm volatile("cp.async.wait_group 0;");
        __syncthreads();
        if (t < qt) {
            loadK(t + 1);
            asm volatile("cp.async.commit_group;");
        }

#pragma unroll
        for (int kk = 0; kk < 4; kk++) {
            uint32_t aph[4], apl[4];
#pragma unroll
            for (int half = 0; half < 2; half++) {
                const float* sp = sacc[2 * kk + half];
                float h0 = __bfloat162float(__float2bfloat16(sp[0]));
                float h1 = __bfloat162float(__float2bfloat16(sp[1]));
                float h2 = __bfloat162float(__float2bfloat16(sp[2]));
                float h3 = __bfloat162float(__float2bfloat16(sp[3]));
                aph[half * 2 + 0] = pack_bf16(sp[0], sp[1]);
                aph[half * 2 + 1] = pack_bf16(sp[2], sp[3]);
                apl[half * 2 + 0] = pack_bf16(sp[0] - h0, sp[1] - h1);
                apl[half * 2 + 1] = pack_bf16(sp[2] - h2, sp[3] - h3);
            }
#pragma unroll
            for (int fnp = 0; fnp < 8; fnp++) {
                int vrow = fnp * 16 + (grp & 1) * 8 + ri;
                uint32_t va = smem + SM_VH + (uint32_t)vrow * VPAD + kk * 32u + (grp >> 1) * 16u;
                uint32_t bh4[4], bl4[4];
                ldmx4(bh4, va);
                ldmx4(bl4, va + (SM_VL - SM_VH));
                uint32_t be[2]  = {bh4[0], bh4[2]};
                uint32_t bo[2]  = {bh4[1], bh4[3]};
                uint32_t ble[2] = {bl4[0], bl4[2]};
                uint32_t blo[2] = {bl4[1], bl4[3]};
                mma16816(oacc[2 * fnp],     aph, be);
                mma16816(oacc[2 * fnp],     apl, be);
                mma16816(oacc[2 * fnp],     aph, ble);
                mma16816(oacc[2 * fnp + 1], aph, bo);
                mma16816(oacc[2 * fnp + 1], apl, bo);
                mma16816(oacc[2 * fnp + 1], aph, blo);
            }
        }
    }

    float inv0 = 1.0f / l0, inv1 = 1.0f / l1;
    const size_t gr0 = (size_t)(q0 + rowA) * D + h * HD + cgrp * 2;
    const size_t gr1 = (size_t)(q0 + rowB) * D + h * HD + cgrp * 2;
#pragma unroll
    for (int fn = 0; fn < 16; fn++) {
        float v0 = oacc[fn][0] * inv0, v1 = oacc[fn][1] * inv0;
        float v2 = oacc[fn][2] * inv1, v3 = oacc[fn][3] * inv1;
        __nv_bfloat162 ph, pl;
        split2(v0, v1, ph, pl);
        *reinterpret_cast<__nv_bfloat162*>(Ohi + gr0 + fn * 8) = ph;
        *reinterpret_cast<__nv_bfloat162*>(Olo + gr0 + fn * 8) = pl;
        split2(v2, v3, ph, pl);
        *reinterpret_cast<__nv_bfloat162*>(Ohi + gr1 + fn * 8) = ph;
        *reinterpret_cast<__nv_bfloat162*>(Olo + gr1 + fn * 8) = pl;
    }
}

// ---------------- launch ----------------
extern "C" void kernel_launch(void* const* d_in, const int* in_sizes, int n_in,
                              void* d_out, int out_size)
{
    const float* x    = (const float*)d_in[0];
    const float* wq   = (const float*)d_in[1];
    const float* wk   = (const float*)d_in[2];
    const float* wv   = (const float*)d_in[3];
    const float* wo   = (const float*)d_in[4];
    const float* cosb = (const float*)d_in[5];
    const float* sinb = (const float*)d_in[6];
    float* out = (float*)d_out;

    __nv_bfloat16 *xhi, *xlo, *ahi, *alo, *qhi, *qlo, *khi, *klo, *vthi, *vtlo;
    __nv_bfloat16 *wqhi, *wqlo, *wkhi, *wklo, *wvhi, *wvlo, *wohi, *wolo;
    cudaGetSymbolAddress((void**)&xhi, g_xhi);   cudaGetSymbolAddress((void**)&xlo, g_xlo);
    cudaGetSymbolAddress((void**)&ahi, g_ahi);   cudaGetSymbolAddress((void**)&alo, g_alo);
    cudaGetSymbolAddress((void**)&qhi, g_qhi);   cudaGetSymbolAddress((void**)&qlo, g_qlo);
    cudaGetSymbolAddress((void**)&khi, g_khi);   cudaGetSymbolAddress((void**)&klo, g_klo);
    cudaGetSymbolAddress((void**)&vthi, g_vthi); cudaGetSymbolAddress((void**)&vtlo, g_vtlo);
    cudaGetSymbolAddress((void**)&wqhi, g_wqhi); cudaGetSymbolAddress((void**)&wqlo, g_wqlo);
    cudaGetSymbolAddress((void**)&wkhi, g_wkhi); cudaGetSymbolAddress((void**)&wklo, g_wklo);
    cudaGetSymbolAddress((void**)&wvhi, g_wvhi); cudaGetSymbolAddress((void**)&wvlo, g_wvlo);
    cudaGetSymbolAddress((void**)&wohi, g_wohi); cudaGetSymbolAddress((void**)&wolo, g_wolo);

    const int shmem = 3 * (int)GSTAGE;   // 98304
    cudaFuncSetAttribute(gemm_kernel, cudaFuncAttributeMaxDynamicSharedMemorySize, shmem);
    cudaFuncSetAttribute(fattn_kernel, cudaFuncAttributeMaxDynamicSharedMemorySize, (int)SM_TOT);

    const float scale = 0.08838834764831845f;   // 1/sqrt(128)

    // input conversions
    split_kernel<<<(S * D / 4 + 255) / 256, 256>>>(x, xhi, xlo, S * D / 4);
    tsplit_kernel<<<dim3(D / 32, D / 32), dim3(32, 8)>>>(wq, wqhi, wqlo, D, D);
    tsplit_kernel<<<dim3(KVD / 32, D / 32), dim3(32, 8)>>>(wk, wkhi, wklo, D, KVD);
    tsplit_kernel<<<dim3(KVD / 32, D / 32), dim3(32, 8)>>>(wv, wvhi, wvlo, D, KVD);
    tsplit_kernel<<<dim3(D / 32, D / 32), dim3(32, 8)>>>(wo, wohi, wolo, D, D);

    // Q projection (fused RoPE+scale+split)
    gemm_kernel<<<dim3(D / 128, S / 128), 256, shmem>>>(
        xhi, xlo, wqhi, wqlo, nullptr, qhi, qlo, D, D, 1, cosb, sinb, scale,
        nullptr, nullptr, nullptr, nullptr, 0, D / 128);
    // K (RoPE+split) + V (transpose+split) merged
    gemm_kernel<<<dim3(2 * KVD / 128, S / 128), 256, shmem>>>(
        xhi, xlo, wkhi, wklo, nullptr, khi, klo, KVD, D, 1, cosb, sinb, 1.0f,
        wvhi, wvlo, vthi, vtlo, 2, KVD / 128);

    // flash attention
    fattn_kernel<<<dim3(S / 64, H), 128, SM_TOT>>>(qhi, qlo, khi, klo, vthi, vtlo, ahi, alo);

    // output projection (fp32 out)
    gemm_kernel<<<dim3(D / 128, S / 128), 256, shmem>>>(
        ahi, alo, wohi, wolo, out, nullptr, nullptr, D, D, 0, nullptr, nullptr, 1.0f,
        nullptr, nullptr, nullptr, nullptr, 0, D / 128);
}

// round 7
// speedup vs baseline: 1.1165x; 1.1165x over previous
#include <cuda_runtime.h>
#include <cuda_bf16.h>
#include <cuda_fp16.h>
#include <cstdint>

#define S 2048
#define D 4096
#define H 32
#define KVH 8
#define HD 128
#define NREP (H / KVH)
#define KVD (KVH * HD)

// ---------------- scratch (static device arrays; no allocation) ----------------
__device__ __nv_bfloat16 g_xhi[S * D], g_xlo[S * D];
__device__ __half        g_x16h[S * D], g_x16l[S * D];
__device__ __half        g_a16h[S * D], g_a16l[S * D];
__device__ __nv_bfloat16 g_qhi[S * D], g_qlo[S * D];
__device__ __nv_bfloat16 g_khi[S * KVD], g_klo[S * KVD];
__device__ __nv_bfloat16 g_vthi[KVD * S], g_vtlo[KVD * S];
__device__ __nv_bfloat16 g_wqhi[D * D], g_wqlo[D * D];       // transposed [N,K]
__device__ __nv_bfloat16 g_wkhi[KVD * D], g_wklo[KVD * D];
__device__ __half        g_wv16[KVD * D];                    // transposed [N,K], fp16
__device__ __half        g_wo16[D * D];                      // transposed [N,K], fp16

// ---------------- helpers ----------------
__device__ __forceinline__ uint32_t s2u(const void* p) {
    uint32_t a;
    asm("{ .reg .u64 t; cvta.to.shared.u64 t, %1; cvt.u32.u64 %0, t; }" : "=r"(a) : "l"(p));
    return a;
}
__device__ __forceinline__ void cpasync16(uint32_t saddr, const void* gaddr) {
    asm volatile("cp.async.cg.shared.global [%0], [%1], 16;" :: "r"(saddr), "l"(gaddr));
}
__device__ __forceinline__ void ldmx4(uint32_t* r, uint32_t addr) {
    asm volatile("ldmatrix.sync.aligned.m8n8.x4.shared.b16 {%0,%1,%2,%3}, [%4];"
                 : "=r"(r[0]), "=r"(r[1]), "=r"(r[2]), "=r"(r[3]) : "r"(addr));
}
__device__ __forceinline__ void mma16816(float* d, const uint32_t* a, const uint32_t* b) {
    asm volatile(
        "mma.sync.aligned.m16n8k16.row.col.f32.bf16.bf16.f32 "
        "{%0,%1,%2,%3}, {%4,%5,%6,%7}, {%8,%9}, {%0,%1,%2,%3};"
        : "+f"(d[0]), "+f"(d[1]), "+f"(d[2]), "+f"(d[3])
        : "r"(a[0]), "r"(a[1]), "r"(a[2]), "r"(a[3]), "r"(b[0]), "r"(b[1]));
}
__device__ __forceinline__ void mma16816h(float* d, const uint32_t* a, const uint32_t* b) {
    asm volatile(
        "mma.sync.aligned.m16n8k16.row.col.f32.f16.f16.f32 "
        "{%0,%1,%2,%3}, {%4,%5,%6,%7}, {%8,%9}, {%0,%1,%2,%3};"
        : "+f"(d[0]), "+f"(d[1]), "+f"(d[2]), "+f"(d[3])
        : "r"(a[0]), "r"(a[1]), "r"(a[2]), "r"(a[3]), "r"(b[0]), "r"(b[1]));
}
__device__ __forceinline__ uint32_t pack_bf16(float x, float y) {
    __nv_bfloat162 t = __floats2bfloat162_rn(x, y);
    return *reinterpret_cast<uint32_t*>(&t);
}
__device__ __forceinline__ void split2(float v0, float v1, __nv_bfloat162& ph, __nv_bfloat162& pl) {
    __nv_bfloat16 h0 = __float2bfloat16(v0), h1 = __float2bfloat16(v1);
    ph.x = h0; ph.y = h1;
    pl.x = __float2bfloat16(v0 - __bfloat162float(h0));
    pl.y = __float2bfloat16(v1 - __bfloat162float(h1));
}
__device__ __forceinline__ void split2h(float v0, float v1, __half2& ph, __half2& pl) {
    __half h0 = __float2half_rn(v0), h1 = __float2half_rn(v1);
    ph = __halves2half2(h0, h1);
    pl = __halves2half2(__float2half_rn(v0 - __half2float(h0)),
                        __float2half_rn(v1 - __half2float(h1)));
}

// ---------------- x: fp32 -> bf16 hi/lo AND fp16 hi/lo ----------------
__global__ void xsplit_all(const float* __restrict__ in,
                           __nv_bfloat16* __restrict__ bh, __nv_bfloat16* __restrict__ bl,
                           __half* __restrict__ fh, __half* __restrict__ fl, int n4)
{
    int i = blockIdx.x * blockDim.x + threadIdx.x;
    if (i >= n4) return;
    float4 v = reinterpret_cast<const float4*>(in)[i];
    __nv_bfloat162 ph, pl;
    split2(v.x, v.y, ph, pl);
    reinterpret_cast<__nv_bfloat162*>(bh)[2 * i] = ph;
    reinterpret_cast<__nv_bfloat162*>(bl)[2 * i] = pl;
    split2(v.z, v.w, ph, pl);
    reinterpret_cast<__nv_bfloat162*>(bh)[2 * i + 1] = ph;
    reinterpret_cast<__nv_bfloat162*>(bl)[2 * i + 1] = pl;
    __half2 hh, hl;
    split2h(v.x, v.y, hh, hl);
    reinterpret_cast<__half2*>(fh)[2 * i] = hh;
    reinterpret_cast<__half2*>(fl)[2 * i] = hl;
    split2h(v.z, v.w, hh, hl);
    reinterpret_cast<__half2*>(fh)[2 * i + 1] = hh;
    reinterpret_cast<__half2*>(fl)[2 * i + 1] = hl;
}

// ---------------- transpose+split: W[K,N] fp32 -> hi/lo bf16 [N,K] ----------------
__global__ void tsplit_kernel(const float* __restrict__ w,
                              __nv_bfloat16* __restrict__ hi,
                              __nv_bfloat16* __restrict__ lo, int K, int N)
{
    __shared__ float t[32][33];
    int n0 = blockIdx.x * 32, k0 = blockIdx.y * 32;
    int tx = threadIdx.x, ty = threadIdx.y;
    for (int r = ty; r < 32; r += 8)
        t[r][tx] = w[(size_t)(k0 + r) * N + n0 + tx];
    __syncthreads();
    for (int r = ty; r < 32; r += 8) {
        float v = t[tx][r];
        __nv_bfloat16 h = __float2bfloat16(v);
        __nv_bfloat16 l = __float2bfloat16(v - __bfloat162float(h));
        size_t o = (size_t)(n0 + r) * K + k0 + tx;
        hi[o] = h; lo[o] = l;
    }
}

// ---------------- transpose: W[K,N] fp32 -> fp16 [N,K] ----------------
__global__ void tsplit16_kernel(const float* __restrict__ w,
                                __half* __restrict__ out, int K, int N)
{
    __shared__ float t[32][33];
    int n0 = blockIdx.x * 32, k0 = blockIdx.y * 32;
    int tx = threadIdx.x, ty = threadIdx.y;
    for (int r = ty; r < 32; r += 8)
        t[r][tx] = w[(size_t)(k0 + r) * N + n0 + tx];
    __syncthreads();
    for (int r = ty; r < 32; r += 8)
        out[(size_t)(n0 + r) * K + k0 + tx] = __float2half_rn(t[tx][r]);
}

// ---------------- bf16 3-term GEMM: merged Q+K projections, RoPE epilogue ----------------
#define GTILE  8192u
#define GSTAGE 32768u
#define NXQ    (D / 128)   // 32 Q column-blocks, then KVD/128=8 K blocks

__global__ __launch_bounds__(256, 2) void gemmqk_kernel(
    const __nv_bfloat16* __restrict__ Ahi, const __nv_bfloat16* __restrict__ Alo,
    const __nv_bfloat16* __restrict__ Bq_hi, const __nv_bfloat16* __restrict__ Bq_lo,
    __nv_bfloat16* __restrict__ Cq_hi, __nv_bfloat16* __restrict__ Cq_lo,
    const __nv_bfloat16* __restrict__ Bk_hi, const __nv_bfloat16* __restrict__ Bk_lo,
    __nv_bfloat16* __restrict__ Ck_hi, __nv_bfloat16* __restrict__ Ck_lo,
    const float* __restrict__ cosb, const float* __restrict__ sinb)
{
    extern __shared__ char dsm[];
    const uint32_t smem = s2u(dsm);

    const int tid = threadIdx.x;
    const int wid = tid >> 5;
    const int lane = tid & 31;
    const int by = blockIdx.y * 128;

    const bool isQ = blockIdx.x < NXQ;
    const __nv_bfloat16* Bhi = isQ ? Bq_hi : Bk_hi;
    const __nv_bfloat16* Blo = isQ ? Bq_lo : Bk_lo;
    __nv_bfloat16* Chi = isQ ? Cq_hi : Ck_hi;
    __nv_bfloat16* Clo = isQ ? Cq_lo : Ck_lo;
    const int Ndim = isQ ? D : KVD;
    const float scale = isQ ? 0.08838834764831845f : 1.0f;
    const int bx = (isQ ? blockIdx.x : blockIdx.x - NXQ) * 128;

    const int wm = (wid & 1) * 64;
    const int wn = (wid >> 1) * 32;
    const int grp = lane >> 3;
    const int ri = lane & 7;

    float acc[4][4][4];
#pragma unroll
    for (int i = 0; i < 4; i++)
#pragma unroll
        for (int j = 0; j < 4; j++)
#pragma unroll
            for (int e = 0; e < 4; e++) acc[i][j][e] = 0.0f;

    const int nchunks = D >> 5;

    auto load_stage = [&](int c, int stage) {
        const uint32_t sb = smem + stage * GSTAGE;
        const int k0 = c << 5;
#pragma unroll
        for (int i = 0; i < 2; i++) {
            int idx = tid + i * 256;
            int row = idx >> 2, cc = idx & 3;
            uint32_t sc = (uint32_t)(cc ^ ((row >> 1) & 3));
            uint32_t so = (uint32_t)row * 64u + sc * 16u;
            size_t ga = (size_t)(by + row) * D + k0 + cc * 8;
            size_t gb = (size_t)(bx + row) * D + k0 + cc * 8;
            cpasync16(sb + so,              Ahi + ga);
            cpasync16(sb + GTILE + so,      Alo + ga);
            cpasync16(sb + 2 * GTILE + so,  Bhi + gb);
            cpasync16(sb + 3 * GTILE + so,  Blo + gb);
        }
    };

    load_stage(0, 0);
    asm volatile("cp.async.commit_group;");
    load_stage(1, 1);
    asm volatile("cp.async.commit_group;");

    for (int c = 0; c < nchunks; c++) {
        if (c + 1 < nchunks) asm volatile("cp.async.wait_group 1;");
        else                 asm volatile("cp.async.wait_group 0;");
        __syncthreads();
        if (c + 2 < nchunks) {
            load_stage(c + 2, (c + 2) % 3);
            asm volatile("cp.async.commit_group;");
        }

        const uint32_t sb = smem + (c % 3) * GSTAGE;

#pragma unroll
        for (int k16 = 0; k16 < 2; k16++) {
            const int lchunk = k16 * 2 + (grp >> 1);
            uint32_t ah[4][4], al[4][4];
#pragma unroll
            for (int fm = 0; fm < 4; fm++) {
                int row = wm + fm * 16 + (grp & 1) * 8 + ri;
                uint32_t ad = sb + (uint32_t)row * 64u
                            + (uint32_t)((lchunk ^ ((row >> 1) & 3)) * 16);
                ldmx4(ah[fm], ad);
                ldmx4(al[fm], ad + GTILE);
            }
#pragma unroll
            for (int fnp = 0; fnp < 2; fnp++) {
                int row = wn + fnp * 16 + (grp & 1) * 8 + ri;
                uint32_t bd = sb + 2 * GTILE + (uint32_t)row * 64u
                            + (uint32_t)((lchunk ^ ((row >> 1) & 3)) * 16);
                uint32_t bh4[4], bl4[4];
                ldmx4(bh4, bd);
                ldmx4(bl4, bd + GTILE);
                uint32_t be[2]  = {bh4[0], bh4[2]};
                uint32_t bo[2]  = {bh4[1], bh4[3]};
                uint32_t ble[2] = {bl4[0], bl4[2]};
                uint32_t blo[2] = {bl4[1], bl4[3]};
#pragma unroll
                for (int fm = 0; fm < 4; fm++) {
                    mma16816(acc[fm][2 * fnp],     ah[fm], be);
                    mma16816(acc[fm][2 * fnp],     al[fm], be);
                    mma16816(acc[fm][2 * fnp],     ah[fm], ble);
                    mma16816(acc[fm][2 * fnp + 1], ah[fm], bo);
                    mma16816(acc[fm][2 * fnp + 1], al[fm], bo);
                    mma16816(acc[fm][2 * fnp + 1], ah[fm], blo);
                }
            }
        }
    }

    // RoPE + scale + split epilogue
    const int erow = lane >> 2;
    const int ecol = (lane & 3) * 2;
#pragma unroll
    for (int fm = 0; fm < 4; fm++) {
#pragma unroll
        for (int fn = 0; fn < 4; fn++) {
            int col = bx + wn + fn * 8 + ecol;
            int i = (col & 127) >> 1;
#pragma unroll
            for (int half = 0; half < 2; half++) {
                int row = by + wm + fm * 16 + erow + half * 8;
                float cv = cosb[row * 64 + i];
                float sv = sinb[row * 64 + i];
                float t0 = acc[fm][fn][half * 2], t1 = acc[fm][fn][half * 2 + 1];
                float o0 = (t0 * cv - t1 * sv) * scale;
                float o1 = (t0 * sv + t1 * cv) * scale;
                __nv_bfloat162 ph, pl;
                split2(o0, o1, ph, pl);
                size_t o = (size_t)row * Ndim + col;
                *reinterpret_cast<__nv_bfloat162*>(Chi + o) = ph;
                *reinterpret_cast<__nv_bfloat162*>(Clo + o) = pl;
            }
        }
    }
}

// ---------------- fp16 2-term GEMM (A hi/lo fp16, B single fp16) ----------------
// mode 0: fp32 C[row*Ndim+col]    mode 2: transpose + bf16 split: C[col*S+row]
#define G16STAGE 24576u   // 3 tiles * 8192

__global__ __launch_bounds__(256, 2) void gemm16_kernel(
    const __half* __restrict__ Ah16, const __half* __restrict__ Al16,
    const __half* __restrict__ Bh16,
    float* __restrict__ Cf,
    __nv_bfloat16* __restrict__ Chi, __nv_bfloat16* __restrict__ Clo,
    int Ndim, int Kdim, int mode)
{
    extern __shared__ char dsm[];
    const uint32_t smem = s2u(dsm);

    const int tid = threadIdx.x;
    const int wid = tid >> 5;
    const int lane = tid & 31;
    const int by = blockIdx.y * 128;
    const int bx = blockIdx.x * 128;

    const int wm = (wid & 1) * 64;
    const int wn = (wid >> 1) * 32;
    const int grp = lane >> 3;
    const int ri = lane & 7;

    float acc[4][4][4];
#pragma unroll
    for (int i = 0; i < 4; i++)
#pragma unroll
        for (int j = 0; j < 4; j++)
#pragma unroll
            for (int e = 0; e < 4; e++) acc[i][j][e] = 0.0f;

    const int nchunks = Kdim >> 5;

    auto load_stage = [&](int c, int stage) {
        const uint32_t sb = smem + stage * G16STAGE;
        const int k0 = c << 5;
#pragma unroll
        for (int i = 0; i < 2; i++) {
            int idx = tid + i * 256;
            int row = idx >> 2, cc = idx & 3;
            uint32_t sc = (uint32_t)(cc ^ ((row >> 1) & 3));
            uint32_t so = (uint32_t)row * 64u + sc * 16u;
            size_t ga = (size_t)(by + row) * Kdim + k0 + cc * 8;
            size_t gb = (size_t)(bx + row) * Kdim + k0 + cc * 8;
            cpasync16(sb + so,              Ah16 + ga);
            cpasync16(sb + GTILE + so,      Al16 + ga);
            cpasync16(sb + 2 * GTILE + so,  Bh16 + gb);
        }
    };

    load_stage(0, 0);
    asm volatile("cp.async.commit_group;");
    load_stage(1, 1);
    asm volatile("cp.async.commit_group;");

    for (int c = 0; c < nchunks; c++) {
        if (c + 1 < nchunks) asm volatile("cp.async.wait_group 1;");
        else                 asm volatile("cp.async.wait_group 0;");
        __syncthreads();
        if (c + 2 < nchunks) {
            load_stage(c + 2, (c + 2) % 3);
            asm volatile("cp.async.commit_group;");
        }

        const uint32_t sb = smem + (c % 3) * G16STAGE;

#pragma unroll
        for (int k16 = 0; k16 < 2; k16++) {
            const int lchunk = k16 * 2 + (grp >> 1);
            uint32_t ah[4][4], al[4][4];
#pragma unroll
            for (int fm = 0; fm < 4; fm++) {
                int row = wm + fm * 16 + (grp & 1) * 8 + ri;
                uint32_t ad = sb + (uint32_t)row * 64u
                            + (uint32_t)((lchunk ^ ((row >> 1) & 3)) * 16);
                ldmx4(ah[fm], ad);
                ldmx4(al[fm], ad + GTILE);
            }
#pragma unroll
            for (int fnp = 0; fnp < 2; fnp++) {
                int row = wn + fnp * 16 + (grp & 1) * 8 + ri;
                uint32_t bd = sb + 2 * GTILE + (uint32_t)row * 64u
                            + (uint32_t)((lchunk ^ ((row >> 1) & 3)) * 16);
                uint32_t bh4[4];
                ldmx4(bh4, bd);
                uint32_t be[2] = {bh4[0], bh4[2]};
                uint32_t bo[2] = {bh4[1], bh4[3]};
#pragma unroll
                for (int fm = 0; fm < 4; fm++) {
                    mma16816h(acc[fm][2 * fnp],     ah[fm], be);
                    mma16816h(acc[fm][2 * fnp],     al[fm], be);
                    mma16816h(acc[fm][2 * fnp + 1], ah[fm], bo);
                    mma16816h(acc[fm][2 * fnp + 1], al[fm], bo);
                }
            }
        }
    }

    const int erow = lane >> 2;
    const int ecol = (lane & 3) * 2;
    if (mode == 0) {
#pragma unroll
        for (int fm = 0; fm < 4; fm++) {
#pragma unroll
            for (int fn = 0; fn < 4; fn++) {
                float* cp0 = Cf + (size_t)(by + wm + fm * 16 + erow) * Ndim + bx + wn + fn * 8 + ecol;
                float* cp1 = cp0 + 8 * (size_t)Ndim;
                *reinterpret_cast<float2*>(cp0) = make_float2(acc[fm][fn][0], acc[fm][fn][1]);
                *reinterpret_cast<float2*>(cp1) = make_float2(acc[fm][fn][2], acc[fm][fn][3]);
            }
        }
    } else {
        // transpose + bf16 split: out[col][row], row stride S
#pragma unroll
        for (int fm = 0; fm < 4; fm++) {
#pragma unroll
            for (int fn = 0; fn < 4; fn++) {
                int col = bx + wn + fn * 8 + ecol;
#pragma unroll
                for (int half = 0; half < 2; half++) {
                    int row = by + wm + fm * 16 + erow + half * 8;
#pragma unroll
                    for (int e = 0; e < 2; e++) {
                        float v = acc[fm][fn][half * 2 + e];
                        __nv_bfloat16 hb = __float2bfloat16(v);
                        size_t o = (size_t)(col + e) * S + row;
                        Chi[o] = hb;
                        Clo[o] = __float2bfloat16(v - __bfloat162float(hb));
                    }
                }
            }
        }
    }
}

// ---------------- flash attention (mma.sync + ldmatrix, bf16 split, Q in regs) ----------------
#define KPAD 272u
#define VPAD 144u
#define SM_QH 0u
#define SM_QL 17408u
#define SM_KH 34816u
#define SM_KL 52224u
#define SM_VH 69632u
#define SM_VL 88064u
#define SM_TOT 106496u

__global__ __launch_bounds__(128) void fattn_kernel(
    const __nv_bfloat16* __restrict__ Qh, const __nv_bfloat16* __restrict__ Ql,
    const __nv_bfloat16* __restrict__ Kh, const __nv_bfloat16* __restrict__ Kl,
    const __nv_bfloat16* __restrict__ Vth, const __nv_bfloat16* __restrict__ Vtl,
    __half* __restrict__ O16h, __half* __restrict__ O16l)
{
    extern __shared__ char dsm[];
    const uint32_t smem = s2u(dsm);
    const int tid = threadIdx.x;
    const int wid = tid >> 5, lane = tid & 31;
    const int qt = gridDim.x - 1 - blockIdx.x;
    const int h = blockIdx.y;
    const int kvh = h / NREP;
    const int q0 = qt * 64;

    const int r = lane >> 2;
    const int cgrp = lane & 3;
    const int grp = lane >> 3;
    const int ri = lane & 7;

    auto loadK = [&](int t) {
#pragma unroll
        for (int i = 0; i < 8; i++) {
            int idx = tid + i * 128;
            int row = idx >> 4, cc = idx & 15;
            size_t g = (size_t)(t * 64 + row) * KVD + kvh * HD + cc * 8;
            cpasync16(smem + SM_KH + row * KPAD + cc * 16, Kh + g);
            cpasync16(smem + SM_KL + row * KPAD + cc * 16, Kl + g);
        }
    };
    auto loadV = [&](int t) {
#pragma unroll
        for (int i = 0; i < 8; i++) {
            int idx = tid + i * 128;
            int row = idx >> 3, cc = idx & 7;
            size_t g = (size_t)(kvh * HD + row) * S + t * 64 + cc * 8;
            cpasync16(smem + SM_VH + row * VPAD + cc * 16, Vth + g);
            cpasync16(smem + SM_VL + row * VPAD + cc * 16, Vtl + g);
        }
    };

#pragma unroll
    for (int i = 0; i < 8; i++) {
        int idx = tid + i * 128;
        int row = idx >> 4, cc = idx & 15;
        size_t g = (size_t)(q0 + row) * D + h * HD + cc * 8;
        cpasync16(smem + SM_QH + row * KPAD + cc * 16, Qh + g);
        cpasync16(smem + SM_QL + row * KPAD + cc * 16, Ql + g);
    }
    loadK(0);
    asm volatile("cp.async.commit_group;");
    asm volatile("cp.async.wait_group 0;");
    __syncthreads();

    // Q fragments -> registers (loop-invariant)
    uint32_t qh[8][4], ql[8][4];
    {
        int qrow = wid * 16 + (grp & 1) * 8 + ri;
        uint32_t qbase = smem + SM_QH + (uint32_t)qrow * KPAD + (grp >> 1) * 16u;
#pragma unroll
        for (int ks = 0; ks < 8; ks++) {
            ldmx4(qh[ks], qbase + ks * 32u);
            ldmx4(ql[ks], qbase + ks * 32u + (SM_QL - SM_QH));
        }
    }

    float m0 = -1e30f, m1 = -1e30f, l0 = 0.0f, l1 = 0.0f;
    float oacc[16][4];
#pragma unroll
    for (int f = 0; f < 16; f++)
#pragma unroll
        for (int e = 0; e < 4; e++) oacc[f][e] = 0.0f;

    const int rowA = wid * 16 + r;
    const int rowB = rowA + 8;

    for (int t = 0; t <= qt; t++) {
        if (t > 0) {
            asm volatile("cp.async.wait_group 0;");
            __syncthreads();
        }
        loadV(t);
        asm volatile("cp.async.commit_group;");

        float sacc[8][4];
#pragma unroll
        for (int f = 0; f < 8; f++)
#pragma unroll
            for (int e = 0; e < 4; e++) sacc[f][e] = 0.0f;

#pragma unroll
        for (int ks = 0; ks < 8; ks++) {
#pragma unroll
            for (int fnp = 0; fnp < 4; fnp++) {
                int krow = fnp * 16 + (grp & 1) * 8 + ri;
                uint32_t ka = smem + SM_KH + (uint32_t)krow * KPAD + ks * 32u + (grp >> 1) * 16u;
                uint32_t bh4[4], bl4[4];
                ldmx4(bh4, ka);
                ldmx4(bl4, ka + (SM_KL - SM_KH));
                uint32_t be[2]  = {bh4[0], bh4[2]};
                uint32_t bo[2]  = {bh4[1], bh4[3]};
                uint32_t ble[2] = {bl4[0], bl4[2]};
                uint32_t blo[2] = {bl4[1], bl4[3]};
                mma16816(sacc[2 * fnp],     qh[ks], be);
                mma16816(sacc[2 * fnp],     ql[ks], be);
                mma16816(sacc[2 * fnp],     qh[ks], ble);
                mma16816(sacc[2 * fnp + 1], qh[ks], bo);
                mma16816(sacc[2 * fnp + 1], ql[ks], bo);
                mma16816(sacc[2 * fnp + 1], qh[ks], blo);
            }
        }

        if (t == qt) {
#pragma unroll
            for (int fn = 0; fn < 8; fn++) {
                int c0 = fn * 8 + cgrp * 2;
                if (c0 > rowA) sacc[fn][0] = -1e30f;
                if (c0 + 1 > rowA) sacc[fn][1] = -1e30f;
                if (c0 > rowB) sacc[fn][2] = -1e30f;
                if (c0 + 1 > rowB) sacc[fn][3] = -1e30f;
            }
        }

        float tm0 = -1e30f, tm1 = -1e30f;
#pragma unroll
        for (int fn = 0; fn < 8; fn++) {
            tm0 = fmaxf(tm0, fmaxf(sacc[fn][0], sacc[fn][1]));
            tm1 = fmaxf(tm1, fmaxf(sacc[fn][2], sacc[fn][3]));
        }
        tm0 = fmaxf(tm0, __shfl_xor_sync(0xFFFFFFFFu, tm0, 1));
        tm0 = fmaxf(tm0, __shfl_xor_sync(0xFFFFFFFFu, tm0, 2));
        tm1 = fmaxf(tm1, __shfl_xor_sync(0xFFFFFFFFu, tm1, 1));
        tm1 = fmaxf(tm1, __shfl_xor_sync(0xFFFFFFFFu, tm1, 2));

        float mn0 = fmaxf(m0, tm0), mn1 = fmaxf(m1, tm1);
        float corr0 = __expf(m0 - mn0), corr1 = __expf(m1 - mn1);
        m0 = mn0; m1 = mn1;

        float rs0 = 0.0f, rs1 = 0.0f;
#pragma unroll
        for (int fn = 0; fn < 8; fn++) {
            sacc[fn][0] = __expf(sacc[fn][0] - m0);
            sacc[fn][1] = __expf(sacc[fn][1] - m0);
            sacc[fn][2] = __expf(sacc[fn][2] - m1);
            sacc[fn][3] = __expf(sacc[fn][3] - m1);
            rs0 += sacc[fn][0] + sacc[fn][1];
            rs1 += sacc[fn][2] + sacc[fn][3];
        }
        rs0 += __shfl_xor_sync(0xFFFFFFFFu, rs0, 1);
        rs0 += __shfl_xor_sync(0xFFFFFFFFu, rs0, 2);
        rs1 += __shfl_xor_sync(0xFFFFFFFFu, rs1, 1);
        rs1 += __shfl_xor_sync(0xFFFFFFFFu, rs1, 2);
        l0 = l0 * corr0 + rs0;
        l1 = l1 * corr1 + rs1;

#pragma unroll
        for (int f = 0; f < 16; f++) {
            oacc[f][0] *= corr0; oacc[f][1] *= corr0;
            oacc[f][2] *= corr1; oacc[f][3] *= corr1;
        }

        asm volatile("cp.async.wait_group 0;");
        __syncthreads();
        if (t < qt) {
            loadK(t + 1);
            asm volatile("cp.async.commit_group;");
        }

#pragma unroll
        for (int kk = 0; kk < 4; kk++) {
            uint32_t aph[4], apl[4];
#pragma unroll
            for (int half = 0; half < 2; half++) {
                const float* sp = sacc[2 * kk + half];
                float h0 = __bfloat162float(__float2bfloat16(sp[0]));
                float h1 = __bfloat162float(__float2bfloat16(sp[1]));
                float h2 = __bfloat162float(__float2bfloat16(sp[2]));
                float h3 = __bfloat162float(__float2bfloat16(sp[3]));
                aph[half * 2 + 0] = pack_bf16(sp[0], sp[1]);
                aph[half * 2 + 1] = pack_bf16(sp[2], sp[3]);
                apl[half * 2 + 0] = pack_bf16(sp[0] - h0, sp[1] - h1);
                apl[half * 2 + 1] = pack_bf16(sp[2] - h2, sp[3] - h3);
            }
#pragma unroll
            for (int fnp = 0; fnp < 8; fnp++) {
                int vrow = fnp * 16 + (grp & 1) * 8 + ri;
                uint32_t va = smem + SM_VH + (uint32_t)vrow * VPAD + kk * 32u + (grp >> 1) * 16u;
                uint32_t bh4[4], bl4[4];
                ldmx4(bh4, va);
                ldmx4(bl4, va + (SM_VL - SM_VH));
                uint32_t be[2]  = {bh4[0], bh4[2]};
                uint32_t bo[2]  = {bh4[1], bh4[3]};
                uint32_t ble[2] = {bl4[0], bl4[2]};
                uint32_t blo[2] = {bl4[1], bl4[3]};
                mma16816(oacc[2 * fnp],     aph, be);
                mma16816(oacc[2 * fnp],     apl, be);
                mma16816(oacc[2 * fnp],     aph, ble);
                mma16816(oacc[2 * fnp + 1], aph, bo);
                mma16816(oacc[2 * fnp + 1], apl, bo);
                mma16816(oacc[2 * fnp + 1], aph, blo);
            }
        }
    }

    // epilogue: divide by l, write fp16 hi/lo (O-proj input)
    float inv0 = 1.0f / l0, inv1 = 1.0f / l1;
    const size_t gr0 = (size_t)(q0 + rowA) * D + h * HD + cgrp * 2;
    const size_t gr1 = (size_t)(q0 + rowB) * D + h * HD + cgrp * 2;
#pragma unroll
    for (int fn = 0; fn < 16; fn++) {
        float v0 = oacc[fn][0] * inv0, v1 = oacc[fn][1] * inv0;
        float v2 = oacc[fn][2] * inv1, v3 = oacc[fn][3] * inv1;
        __half2 ph, pl;
        split2h(v0, v1, ph, pl);
        *reinterpret_cast<__half2*>(O16h + gr0 + fn * 8) = ph;
        *reinterpret_cast<__half2*>(O16l + gr0 + fn * 8) = pl;
        split2h(v2, v3, ph, pl);
        *reinterpret_cast<__half2*>(O16h + gr1 + fn * 8) = ph;
        *reinterpret_cast<__half2*>(O16l + gr1 + fn * 8) = pl;
    }
}

// ---------------- launch ----------------
extern "C" void kernel_launch(void* const* d_in, const int* in_sizes, int n_in,
                              void* d_out, int out_size)
{
    const float* x    = (const float*)d_in[0];
    const float* wq   = (const float*)d_in[1];
    const float* wk   = (const float*)d_in[2];
    const float* wv   = (const float*)d_in[3];
    const float* wo   = (const float*)d_in[4];
    const float* cosb = (const float*)d_in[5];
    const float* sinb = (const float*)d_in[6];
    float* out = (float*)d_out;

    __nv_bfloat16 *xhi, *xlo, *qhi, *qlo, *khi, *klo, *vthi, *vtlo;
    __nv_bfloat16 *wqhi, *wqlo, *wkhi, *wklo;
    __half *x16h, *x16l, *a16h, *a16l, *wv16, *wo16;
    cudaGetSymbolAddress((void**)&xhi, g_xhi);   cudaGetSymbolAddress((void**)&xlo, g_xlo);
    cudaGetSymbolAddress((void**)&x16h, g_x16h); cudaGetSymbolAddress((void**)&x16l, g_x16l);
    cudaGetSymbolAddress((void**)&a16h, g_a16h); cudaGetSymbolAddress((void**)&a16l, g_a16l);
    cudaGetSymbolAddress((void**)&qhi, g_qhi);   cudaGetSymbolAddress((void**)&qlo, g_qlo);
    cudaGetSymbolAddress((void**)&khi, g_khi);   cudaGetSymbolAddress((void**)&klo, g_klo);
    cudaGetSymbolAddress((void**)&vthi, g_vthi); cudaGetSymbolAddress((void**)&vtlo, g_vtlo);
    cudaGetSymbolAddress((void**)&wqhi, g_wqhi); cudaGetSymbolAddress((void**)&wqlo, g_wqlo);
    cudaGetSymbolAddress((void**)&wkhi, g_wkhi); cudaGetSymbolAddress((void**)&wklo, g_wklo);
    cudaGetSymbolAddress((void**)&wv16, g_wv16); cudaGetSymbolAddress((void**)&wo16, g_wo16);

    const int shmem = 3 * (int)GSTAGE;        // 98304
    const int shmem16 = 3 * (int)G16STAGE;    // 73728
    cudaFuncSetAttribute(gemmqk_kernel, cudaFuncAttributeMaxDynamicSharedMemorySize, shmem);
    cudaFuncSetAttribute(gemm16_kernel, cudaFuncAttributeMaxDynamicSharedMemorySize, shmem16);
    cudaFuncSetAttribute(fattn_kernel, cudaFuncAttributeMaxDynamicSharedMemorySize, (int)SM_TOT);

    // input conversions
    xsplit_all<<<(S * D / 4 + 255) / 256, 256>>>(x, xhi, xlo, x16h, x16l, S * D / 4);
    tsplit_kernel<<<dim3(D / 32, D / 32), dim3(32, 8)>>>(wq, wqhi, wqlo, D, D);
    tsplit_kernel<<<dim3(KVD / 32, D / 32), dim3(32, 8)>>>(wk, wkhi, wklo, D, KVD);
    tsplit16_kernel<<<dim3(KVD / 32, D / 32), dim3(32, 8)>>>(wv, wv16, D, KVD);
    tsplit16_kernel<<<dim3(D / 32, D / 32), dim3(32, 8)>>>(wo, wo16, D, D);

    // Q + K projections merged (bf16 3-term, fused RoPE+scale+split)
    gemmqk_kernel<<<dim3(D / 128 + KVD / 128, S / 128), 256, shmem>>>(
        xhi, xlo, wqhi, wqlo, qhi, qlo, wkhi, wklo, khi, klo, cosb, sinb);

    // V projection (fp16 2-term, fused transpose+bf16 split)
    gemm16_kernel<<<dim3(KVD / 128, S / 128), 256, shmem16>>>(
        x16h, x16l, wv16, nullptr, vthi, vtlo, KVD, D, 2);

    // flash attention -> fp16 hi/lo
    fattn_kernel<<<dim3(S / 64, H), 128, SM_TOT>>>(qhi, qlo, khi, klo, vthi, vtlo, a16h, a16l);

    // output projection (fp16 2-term, fp32 out)
    gemm16_kernel<<<dim3(D / 128, S / 128), 256, shmem16>>>(
        a16h, a16l, wo16, out, nullptr, nullptr, D, D, 0);
}

// round 8
// speedup vs baseline: 1.1475x; 1.0278x over previous
#include <cuda_runtime.h>
#include <cuda_bf16.h>
#include <cuda_fp16.h>
#include <cstdint>

#define S 2048
#define D 4096
#define H 32
#define KVH 8
#define HD 128
#define NREP (H / KVH)
#define KVD (KVH * HD)
#define PGRID 304   // 2 CTAs/SM * 152 SMs (GB300)

// ---------------- scratch (static device arrays; no allocation) ----------------
__device__ __nv_bfloat16 g_xhi[S * D], g_xlo[S * D];
__device__ __half        g_x16h[S * D], g_x16l[S * D];
__device__ __half        g_a16h[S * D], g_a16l[S * D];
__device__ __nv_bfloat16 g_qhi[S * D], g_qlo[S * D];
__device__ __nv_bfloat16 g_khi[S * KVD], g_klo[S * KVD];
__device__ __half        g_vt16[KVD * S];                    // transposed [KVD][S], fp16
__device__ __nv_bfloat16 g_wqhi[D * D], g_wqlo[D * D];       // transposed [N,K]
__device__ __nv_bfloat16 g_wkhi[KVD * D], g_wklo[KVD * D];
__device__ __half        g_wv16[KVD * D];                    // transposed [N,K], fp16
__device__ __half        g_wo16[D * D];                      // transposed [N,K], fp16

// ---------------- helpers ----------------
__device__ __forceinline__ uint32_t s2u(const void* p) {
    uint32_t a;
    asm("{ .reg .u64 t; cvta.to.shared.u64 t, %1; cvt.u32.u64 %0, t; }" : "=r"(a) : "l"(p));
    return a;
}
__device__ __forceinline__ void cpasync16(uint32_t saddr, const void* gaddr) {
    asm volatile("cp.async.cg.shared.global [%0], [%1], 16;" :: "r"(saddr), "l"(gaddr));
}
__device__ __forceinline__ void ldmx4(uint32_t* r, uint32_t addr) {
    asm volatile("ldmatrix.sync.aligned.m8n8.x4.shared.b16 {%0,%1,%2,%3}, [%4];"
                 : "=r"(r[0]), "=r"(r[1]), "=r"(r[2]), "=r"(r[3]) : "r"(addr));
}
__device__ __forceinline__ void mma16816(float* d, const uint32_t* a, const uint32_t* b) {
    asm volatile(
        "mma.sync.aligned.m16n8k16.row.col.f32.bf16.bf16.f32 "
        "{%0,%1,%2,%3}, {%4,%5,%6,%7}, {%8,%9}, {%0,%1,%2,%3};"
        : "+f"(d[0]), "+f"(d[1]), "+f"(d[2]), "+f"(d[3])
        : "r"(a[0]), "r"(a[1]), "r"(a[2]), "r"(a[3]), "r"(b[0]), "r"(b[1]));
}
__device__ __forceinline__ void mma16816h(float* d, const uint32_t* a, const uint32_t* b) {
    asm volatile(
        "mma.sync.aligned.m16n8k16.row.col.f32.f16.f16.f32 "
        "{%0,%1,%2,%3}, {%4,%5,%6,%7}, {%8,%9}, {%0,%1,%2,%3};"
        : "+f"(d[0]), "+f"(d[1]), "+f"(d[2]), "+f"(d[3])
        : "r"(a[0]), "r"(a[1]), "r"(a[2]), "r"(a[3]), "r"(b[0]), "r"(b[1]));
}
__device__ __forceinline__ uint32_t pack_f16(float x, float y) {
    __half2 t = __floats2half2_rn(x, y);
    return *reinterpret_cast<uint32_t*>(&t);
}
__device__ __forceinline__ void split2(float v0, float v1, __nv_bfloat162& ph, __nv_bfloat162& pl) {
    __nv_bfloat16 h0 = __float2bfloat16(v0), h1 = __float2bfloat16(v1);
    ph.x = h0; ph.y = h1;
    pl.x = __float2bfloat16(v0 - __bfloat162float(h0));
    pl.y = __float2bfloat16(v1 - __bfloat162float(h1));
}
__device__ __forceinline__ void split2h(float v0, float v1, __half2& ph, __half2& pl) {
    __half h0 = __float2half_rn(v0), h1 = __float2half_rn(v1);
    ph = __halves2half2(h0, h1);
    pl = __halves2half2(__float2half_rn(v0 - __half2float(h0)),
                        __float2half_rn(v1 - __half2float(h1)));
}

// ---------------- x: fp32 -> bf16 hi/lo AND fp16 hi/lo ----------------
__global__ void xsplit_all(const float* __restrict__ in,
                           __nv_bfloat16* __restrict__ bh, __nv_bfloat16* __restrict__ bl,
                           __half* __restrict__ fh, __half* __restrict__ fl, int n4)
{
    int i = blockIdx.x * blockDim.x + threadIdx.x;
    if (i >= n4) return;
    float4 v = reinterpret_cast<const float4*>(in)[i];
    __nv_bfloat162 ph, pl;
    split2(v.x, v.y, ph, pl);
    reinterpret_cast<__nv_bfloat162*>(bh)[2 * i] = ph;
    reinterpret_cast<__nv_bfloat162*>(bl)[2 * i] = pl;
    split2(v.z, v.w, ph, pl);
    reinterpret_cast<__nv_bfloat162*>(bh)[2 * i + 1] = ph;
    reinterpret_cast<__nv_bfloat162*>(bl)[2 * i + 1] = pl;
    __half2 hh, hl;
    split2h(v.x, v.y, hh, hl);
    reinterpret_cast<__half2*>(fh)[2 * i] = hh;
    reinterpret_cast<__half2*>(fl)[2 * i] = hl;
    split2h(v.z, v.w, hh, hl);
    reinterpret_cast<__half2*>(fh)[2 * i + 1] = hh;
    reinterpret_cast<__half2*>(fl)[2 * i + 1] = hl;
}

// ---------------- transpose+split: W[K,N] fp32 -> hi/lo bf16 [N,K] ----------------
__global__ void tsplit_kernel(const float* __restrict__ w,
                              __nv_bfloat16* __restrict__ hi,
                              __nv_bfloat16* __restrict__ lo, int K, int N)
{
    __shared__ float t[32][33];
    int n0 = blockIdx.x * 32, k0 = blockIdx.y * 32;
    int tx = threadIdx.x, ty = threadIdx.y;
    for (int r = ty; r < 32; r += 8)
        t[r][tx] = w[(size_t)(k0 + r) * N + n0 + tx];
    __syncthreads();
    for (int r = ty; r < 32; r += 8) {
        float v = t[tx][r];
        __nv_bfloat16 h = __float2bfloat16(v);
        __nv_bfloat16 l = __float2bfloat16(v - __bfloat162float(h));
        size_t o = (size_t)(n0 + r) * K + k0 + tx;
        hi[o] = h; lo[o] = l;
    }
}

// ---------------- transpose: W[K,N] fp32 -> fp16 [N,K] ----------------
__global__ void tsplit16_kernel(const float* __restrict__ w,
                                __half* __restrict__ out, int K, int N)
{
    __shared__ float t[32][33];
    int n0 = blockIdx.x * 32, k0 = blockIdx.y * 32;
    int tx = threadIdx.x, ty = threadIdx.y;
    for (int r = ty; r < 32; r += 8)
        t[r][tx] = w[(size_t)(k0 + r) * N + n0 + tx];
    __syncthreads();
    for (int r = ty; r < 32; r += 8)
        out[(size_t)(n0 + r) * K + k0 + tx] = __float2half_rn(t[tx][r]);
}

// ---------------- bf16 3-term GEMM: persistent, merged Q+K projections ----------------
#define GTILE  8192u
#define GSTAGE 32768u
#define NXQ    (D / 128)                 // 32 Q column-blocks
#define NTXQK  (D / 128 + KVD / 128)     // 40
#define NTILQK (NTXQK * (S / 128))       // 640

__global__ __launch_bounds__(256, 2) void gemmqk_kernel(
    const __nv_bfloat16* __restrict__ Ahi, const __nv_bfloat16* __restrict__ Alo,
    const __nv_bfloat16* __restrict__ Bq_hi, const __nv_bfloat16* __restrict__ Bq_lo,
    __nv_bfloat16* __restrict__ Cq_hi, __nv_bfloat16* __restrict__ Cq_lo,
    const __nv_bfloat16* __restrict__ Bk_hi, const __nv_bfloat16* __restrict__ Bk_lo,
    __nv_bfloat16* __restrict__ Ck_hi, __nv_bfloat16* __restrict__ Ck_lo,
    const float* __restrict__ cosb, const float* __restrict__ sinb)
{
    extern __shared__ char dsm[];
    const uint32_t smem = s2u(dsm);

    const int tid = threadIdx.x;
    const int wid = tid >> 5;
    const int lane = tid & 31;
    const int wm = (wid & 1) * 64;
    const int wn = (wid >> 1) * 32;
    const int grp = lane >> 3;
    const int ri = lane & 7;

    for (int tile = blockIdx.x; tile < NTILQK; tile += gridDim.x) {
        const int txi = tile % NTXQK;
        const int by = (tile / NTXQK) * 128;
        const bool isQ = txi < NXQ;
        const __nv_bfloat16* Bhi = isQ ? Bq_hi : Bk_hi;
        const __nv_bfloat16* Blo = isQ ? Bq_lo : Bk_lo;
        __nv_bfloat16* Chi = isQ ? Cq_hi : Ck_hi;
        __nv_bfloat16* Clo = isQ ? Cq_lo : Ck_lo;
        const int Ndim = isQ ? D : KVD;
        const float scale = isQ ? 0.08838834764831845f : 1.0f;
        const int bx = (isQ ? txi : txi - NXQ) * 128;

        float acc[4][4][4];
#pragma unroll
        for (int i = 0; i < 4; i++)
#pragma unroll
            for (int j = 0; j < 4; j++)
#pragma unroll
                for (int e = 0; e < 4; e++) acc[i][j][e] = 0.0f;

        auto load_stage = [&](int c, int stage) {
            const uint32_t sb = smem + stage * GSTAGE;
            const int k0 = c << 5;
#pragma unroll
            for (int i = 0; i < 2; i++) {
                int idx = tid + i * 256;
                int row = idx >> 2, cc = idx & 3;
                uint32_t sc = (uint32_t)(cc ^ ((row >> 1) & 3));
                uint32_t so = (uint32_t)row * 64u + sc * 16u;
                size_t ga = (size_t)(by + row) * D + k0 + cc * 8;
                size_t gb = (size_t)(bx + row) * D + k0 + cc * 8;
                cpasync16(sb + so,              Ahi + ga);
                cpasync16(sb + GTILE + so,      Alo + ga);
                cpasync16(sb + 2 * GTILE + so,  Bhi + gb);
                cpasync16(sb + 3 * GTILE + so,  Blo + gb);
            }
        };

        load_stage(0, 0);
        asm volatile("cp.async.commit_group;");
        load_stage(1, 1);
        asm volatile("cp.async.commit_group;");

        const int nchunks = D >> 5;
        for (int c = 0; c < nchunks; c++) {
            if (c + 1 < nchunks) asm volatile("cp.async.wait_group 1;");
            else                 asm volatile("cp.async.wait_group 0;");
            __syncthreads();
            if (c + 2 < nchunks) {
                load_stage(c + 2, (c + 2) % 3);
                asm volatile("cp.async.commit_group;");
            }

            const uint32_t sb = smem + (c % 3) * GSTAGE;

#pragma unroll
            for (int k16 = 0; k16 < 2; k16++) {
                const int lchunk = k16 * 2 + (grp >> 1);
                uint32_t ah[4][4], al[4][4];
#pragma unroll
                for (int fm = 0; fm < 4; fm++) {
                    int row = wm + fm * 16 + (grp & 1) * 8 + ri;
                    uint32_t ad = sb + (uint32_t)row * 64u
                                + (uint32_t)((lchunk ^ ((row >> 1) & 3)) * 16);
                    ldmx4(ah[fm], ad);
                    ldmx4(al[fm], ad + GTILE);
                }
#pragma unroll
                for (int fnp = 0; fnp < 2; fnp++) {
                    int row = wn + fnp * 16 + (grp & 1) * 8 + ri;
                    uint32_t bd = sb + 2 * GTILE + (uint32_t)row * 64u
                                + (uint32_t)((lchunk ^ ((row >> 1) & 3)) * 16);
                    uint32_t bh4[4], bl4[4];
                    ldmx4(bh4, bd);
                    ldmx4(bl4, bd + GTILE);
                    uint32_t be[2]  = {bh4[0], bh4[2]};
                    uint32_t bo[2]  = {bh4[1], bh4[3]};
                    uint32_t ble[2] = {bl4[0], bl4[2]};
                    uint32_t blo[2] = {bl4[1], bl4[3]};
#pragma unroll
                    for (int fm = 0; fm < 4; fm++) {
                        mma16816(acc[fm][2 * fnp],     ah[fm], be);
                        mma16816(acc[fm][2 * fnp],     al[fm], be);
                        mma16816(acc[fm][2 * fnp],     ah[fm], ble);
                        mma16816(acc[fm][2 * fnp + 1], ah[fm], bo);
                        mma16816(acc[fm][2 * fnp + 1], al[fm], bo);
                        mma16816(acc[fm][2 * fnp + 1], ah[fm], blo);
                    }
                }
            }
        }

        // RoPE + scale + split epilogue
        const int erow = lane >> 2;
        const int ecol = (lane & 3) * 2;
#pragma unroll
        for (int fm = 0; fm < 4; fm++) {
#pragma unroll
            for (int fn = 0; fn < 4; fn++) {
                int col = bx + wn + fn * 8 + ecol;
                int i = (col & 127) >> 1;
#pragma unroll
                for (int half = 0; half < 2; half++) {
                    int row = by + wm + fm * 16 + erow + half * 8;
                    float cv = cosb[row * 64 + i];
                    float sv = sinb[row * 64 + i];
                    float t0 = acc[fm][fn][half * 2], t1 = acc[fm][fn][half * 2 + 1];
                    float o0 = (t0 * cv - t1 * sv) * scale;
                    float o1 = (t0 * sv + t1 * cv) * scale;
                    __nv_bfloat162 ph, pl;
                    split2(o0, o1, ph, pl);
                    size_t o = (size_t)row * Ndim + col;
                    *reinterpret_cast<__nv_bfloat162*>(Chi + o) = ph;
                    *reinterpret_cast<__nv_bfloat162*>(Clo + o) = pl;
                }
            }
        }
        __syncthreads();   // smem safe before next tile's loads
    }
}

// ---------------- fp16 2-term GEMM: persistent ----------------
// mode 0: fp32 C[row*Ndim+col]    mode 2: transpose fp16: C16[col*S+row]
#define G16STAGE 24576u

__global__ __launch_bounds__(256, 2) void gemm16_kernel(
    const __half* __restrict__ Ah16, const __half* __restrict__ Al16,
    const __half* __restrict__ Bh16,
    float* __restrict__ Cf, __half* __restrict__ C16,
    int Ndim, int Kdim, int mode, int ntx, int ntiles)
{
    extern __shared__ char dsm[];
    const uint32_t smem = s2u(dsm);

    const int tid = threadIdx.x;
    const int wid = tid >> 5;
    const int lane = tid & 31;
    const int wm = (wid & 1) * 64;
    const int wn = (wid >> 1) * 32;
    const int grp = lane >> 3;
    const int ri = lane & 7;

    for (int tile = blockIdx.x; tile < ntiles; tile += gridDim.x) {
        const int bx = (tile % ntx) * 128;
        const int by = (tile / ntx) * 128;

        float acc[4][4][4];
#pragma unroll
        for (int i = 0; i < 4; i++)
#pragma unroll
            for (int j = 0; j < 4; j++)
#pragma unroll
                for (int e = 0; e < 4; e++) acc[i][j][e] = 0.0f;

        auto load_stage = [&](int c, int stage) {
            const uint32_t sb = smem + stage * G16STAGE;
            const int k0 = c << 5;
#pragma unroll
            for (int i = 0; i < 2; i++) {
                int idx = tid + i * 256;
                int row = idx >> 2, cc = idx & 3;
                uint32_t sc = (uint32_t)(cc ^ ((row >> 1) & 3));
                uint32_t so = (uint32_t)row * 64u + sc * 16u;
                size_t ga = (size_t)(by + row) * Kdim + k0 + cc * 8;
                size_t gb = (size_t)(bx + row) * Kdim + k0 + cc * 8;
                cpasync16(sb + so,              Ah16 + ga);
                cpasync16(sb + GTILE + so,      Al16 + ga);
                cpasync16(sb + 2 * GTILE + so,  Bh16 + gb);
            }
        };

        load_stage(0, 0);
        asm volatile("cp.async.commit_group;");
        load_stage(1, 1);
        asm volatile("cp.async.commit_group;");

        const int nchunks = Kdim >> 5;
        for (int c = 0; c < nchunks; c++) {
            if (c + 1 < nchunks) asm volatile("cp.async.wait_group 1;");
            else                 asm volatile("cp.async.wait_group 0;");
            __syncthreads();
            if (c + 2 < nchunks) {
                load_stage(c + 2, (c + 2) % 3);
                asm volatile("cp.async.commit_group;");
            }

            const uint32_t sb = smem + (c % 3) * G16STAGE;

#pragma unroll
            for (int k16 = 0; k16 < 2; k16++) {
                const int lchunk = k16 * 2 + (grp >> 1);
                uint32_t ah[4][4], al[4][4];
#pragma unroll
                for (int fm = 0; fm < 4; fm++) {
                    int row = wm + fm * 16 + (grp & 1) * 8 + ri;
                    uint32_t ad = sb + (uint32_t)row * 64u
                                + (uint32_t)((lchunk ^ ((row >> 1) & 3)) * 16);
                    ldmx4(ah[fm], ad);
                    ldmx4(al[fm], ad + GTILE);
                }
#pragma unroll
                for (int fnp = 0; fnp < 2; fnp++) {
                    int row = wn + fnp * 16 + (grp & 1) * 8 + ri;
                    uint32_t bd = sb + 2 * GTILE + (uint32_t)row * 64u
                                + (uint32_t)((lchunk ^ ((row >> 1) & 3)) * 16);
                    uint32_t bh4[4];
                    ldmx4(bh4, bd);
                    uint32_t be[2] = {bh4[0], bh4[2]};
                    uint32_t bo[2] = {bh4[1], bh4[3]};
#pragma unroll
                    for (int fm = 0; fm < 4; fm++) {
                        mma16816h(acc[fm][2 * fnp],     ah[fm], be);
                        mma16816h(acc[fm][2 * fnp],     al[fm], be);
                        mma16816h(acc[fm][2 * fnp + 1], ah[fm], bo);
                        mma16816h(acc[fm][2 * fnp + 1], al[fm], bo);
                    }
                }
            }
        }

        const int erow = lane >> 2;
        const int ecol = (lane & 3) * 2;
        if (mode == 0) {
#pragma unroll
            for (int fm = 0; fm < 4; fm++) {
#pragma unroll
                for (int fn = 0; fn < 4; fn++) {
                    float* cp0 = Cf + (size_t)(by + wm + fm * 16 + erow) * Ndim + bx + wn + fn * 8 + ecol;
                    float* cp1 = cp0 + 8 * (size_t)Ndim;
                    *reinterpret_cast<float2*>(cp0) = make_float2(acc[fm][fn][0], acc[fm][fn][1]);
                    *reinterpret_cast<float2*>(cp1) = make_float2(acc[fm][fn][2], acc[fm][fn][3]);
                }
            }
        } else {
            // transpose fp16: out[col][row], row stride S
#pragma unroll
            for (int fm = 0; fm < 4; fm++) {
#pragma unroll
                for (int fn = 0; fn < 4; fn++) {
                    int col = bx + wn + fn * 8 + ecol;
#pragma unroll
                    for (int half = 0; half < 2; half++) {
                        int row = by + wm + fm * 16 + erow + half * 8;
#pragma unroll
                        for (int e = 0; e < 2; e++) {
                            float v = acc[fm][fn][half * 2 + e];
                            C16[(size_t)(col + e) * S + row] = __float2half_rn(v);
                        }
                    }
                }
            }
        }
        __syncthreads();
    }
}

// ---------------- flash attention: QK bf16 3-term, PV fp16 2-term ----------------
#define KPAD 272u
#define VPAD 144u
#define SM_QH 0u
#define SM_QL 17408u
#define SM_KH 34816u
#define SM_KL 52224u
#define SM_VH 69632u
#define SM_TOT 88064u

__global__ __launch_bounds__(128) void fattn_kernel(
    const __nv_bfloat16* __restrict__ Qh, const __nv_bfloat16* __restrict__ Ql,
    const __nv_bfloat16* __restrict__ Kh, const __nv_bfloat16* __restrict__ Kl,
    const __half* __restrict__ Vt16,
    __half* __restrict__ O16h, __half* __restrict__ O16l)
{
    extern __shared__ char dsm[];
    const uint32_t smem = s2u(dsm);
    const int tid = threadIdx.x;
    const int wid = tid >> 5, lane = tid & 31;
    const int qt = gridDim.x - 1 - blockIdx.x;
    const int h = blockIdx.y;
    const int kvh = h / NREP;
    const int q0 = qt * 64;

    const int r = lane >> 2;
    const int cgrp = lane & 3;
    const int grp = lane >> 3;
    const int ri = lane & 7;

    auto loadK = [&](int t) {
#pragma unroll
        for (int i = 0; i < 8; i++) {
            int idx = tid + i * 128;
            int row = idx >> 4, cc = idx & 15;
            size_t g = (size_t)(t * 64 + row) * KVD + kvh * HD + cc * 8;
            cpasync16(smem + SM_KH + row * KPAD + cc * 16, Kh + g);
            cpasync16(smem + SM_KL + row * KPAD + cc * 16, Kl + g);
        }
    };
    auto loadV = [&](int t) {
#pragma unroll
        for (int i = 0; i < 8; i++) {
            int idx = tid + i * 128;
            int row = idx >> 3, cc = idx & 7;
            size_t g = (size_t)(kvh * HD + row) * S + t * 64 + cc * 8;
            cpasync16(smem + SM_VH + row * VPAD + cc * 16, Vt16 + g);
        }
    };

#pragma unroll
    for (int i = 0; i < 8; i++) {
        int idx = tid + i * 128;
        int row = idx >> 4, cc = idx & 15;
        size_t g = (size_t)(q0 + row) * D + h * HD + cc * 8;
        cpasync16(smem + SM_QH + row * KPAD + cc * 16, Qh + g);
        cpasync16(smem + SM_QL + row * KPAD + cc * 16, Ql + g);
    }
    loadK(0);
    asm volatile("cp.async.commit_group;");
    asm volatile("cp.async.wait_group 0;");
    __syncthreads();

    // Q fragments -> registers (loop-invariant)
    uint32_t qh[8][4], ql[8][4];
    {
        int qrow = wid * 16 + (grp & 1) * 8 + ri;
        uint32_t qbase = smem + SM_QH + (uint32_t)qrow * KPAD + (grp >> 1) * 16u;
#pragma unroll
        for (int ks = 0; ks < 8; ks++) {
            ldmx4(qh[ks], qbase + ks * 32u);
            ldmx4(ql[ks], qbase + ks * 32u + (SM_QL - SM_QH));
        }
    }

    float m0 = -1e30f, m1 = -1e30f, l0 = 0.0f, l1 = 0.0f;
    float oacc[16][4];
#pragma unroll
    for (int f = 0; f < 16; f++)
#pragma unroll
        for (int e = 0; e < 4; e++) oacc[f][e] = 0.0f;

    const int rowA = wid * 16 + r;
    const int rowB = rowA + 8;

    for (int t = 0; t <= qt; t++) {
        if (t > 0) {
            asm volatile("cp.async.wait_group 0;");
            __syncthreads();
        }
        loadV(t);
        asm volatile("cp.async.commit_group;");

        float sacc[8][4];
#pragma unroll
        for (int f = 0; f < 8; f++)
#pragma unroll
            for (int e = 0; e < 4; e++) sacc[f][e] = 0.0f;

#pragma unroll
        for (int ks = 0; ks < 8; ks++) {
#pragma unroll
            for (int fnp = 0; fnp < 4; fnp++) {
                int krow = fnp * 16 + (grp & 1) * 8 + ri;
                uint32_t ka = smem + SM_KH + (uint32_t)krow * KPAD + ks * 32u + (grp >> 1) * 16u;
                uint32_t bh4[4], bl4[4];
                ldmx4(bh4, ka);
                ldmx4(bl4, ka + (SM_KL - SM_KH));
                uint32_t be[2]  = {bh4[0], bh4[2]};
                uint32_t bo[2]  = {bh4[1], bh4[3]};
                uint32_t ble[2] = {bl4[0], bl4[2]};
                uint32_t blo[2] = {bl4[1], bl4[3]};
                mma16816(sacc[2 * fnp],     qh[ks], be);
                mma16816(sacc[2 * fnp],     ql[ks], be);
                mma16816(sacc[2 * fnp],     qh[ks], ble);
                mma16816(sacc[2 * fnp + 1], qh[ks], bo);
                mma16816(sacc[2 * fnp + 1], ql[ks], bo);
                mma16816(sacc[2 * fnp + 1], qh[ks], blo);
            }
        }

        if (t == qt) {
#pragma unroll
            for (int fn = 0; fn < 8; fn++) {
                int c0 = fn * 8 + cgrp * 2;
                if (c0 > rowA) sacc[fn][0] = -1e30f;
                if (c0 + 1 > rowA) sacc[fn][1] = -1e30f;
                if (c0 > rowB) sacc[fn][2] = -1e30f;
                if (c0 + 1 > rowB) sacc[fn][3] = -1e30f;
            }
        }

        float tm0 = -1e30f, tm1 = -1e30f;
#pragma unroll
        for (int fn = 0; fn < 8; fn++) {
            tm0 = fmaxf(tm0, fmaxf(sacc[fn][0], sacc[fn][1]));
            tm1 = fmaxf(tm1, fmaxf(sacc[fn][2], sacc[fn][3]));
        }
        tm0 = fmaxf(tm0, __shfl_xor_sync(0xFFFFFFFFu, tm0, 1));
        tm0 = fmaxf(tm0, __shfl_xor_sync(0xFFFFFFFFu, tm0, 2));
        tm1 = fmaxf(tm1, __shfl_xor_sync(0xFFFFFFFFu, tm1, 1));
        tm1 = fmaxf(tm1, __shfl_xor_sync(0xFFFFFFFFu, tm1, 2));

        float mn0 = fmaxf(m0, tm0), mn1 = fmaxf(m1, tm1);
        float corr0 = __expf(m0 - mn0), corr1 = __expf(m1 - mn1);
        m0 = mn0; m1 = mn1;

        float rs0 = 0.0f, rs1 = 0.0f;
#pragma unroll
        for (int fn = 0; fn < 8; fn++) {
            sacc[fn][0] = __expf(sacc[fn][0] - m0);
            sacc[fn][1] = __expf(sacc[fn][1] - m0);
            sacc[fn][2] = __expf(sacc[fn][2] - m1);
            sacc[fn][3] = __expf(sacc[fn][3] - m1);
            rs0 += sacc[fn][0] + sacc[fn][1];
            rs1 += sacc[fn][2] + sacc[fn][3];
        }
        rs0 += __shfl_xor_sync(0xFFFFFFFFu, rs0, 1);
        rs0 += __shfl_xor_sync(0xFFFFFFFFu, rs0, 2);
        rs1 += __shfl_xor_sync(0xFFFFFFFFu, rs1, 1);
        rs1 += __shfl_xor_sync(0xFFFFFFFFu, rs1, 2);
        l0 = l0 * corr0 + rs0;
        l1 = l1 * corr1 + rs1;

#pragma unroll
        for (int f = 0; f < 16; f++) {
            oacc[f][0] *= corr0; oacc[f][1] *= corr0;
            oacc[f][2] *= corr1; oacc[f][3] *= corr1;
        }

        asm volatile("cp.async.wait_group 0;");
        __syncthreads();
        if (t < qt) {
            loadK(t + 1);
            asm volatile("cp.async.commit_group;");
        }

        // ---- O += P V (P fp16 hi/lo, V fp16 single) ----
#pragma unroll
        for (int kk = 0; kk < 4; kk++) {
            uint32_t aph[4], apl[4];
#pragma unroll
            for (int half = 0; half < 2; half++) {
                const float* sp = sacc[2 * kk + half];
                float h0 = __half2float(__float2half_rn(sp[0]));
                float h1 = __half2float(__float2half_rn(sp[1]));
                float h2 = __half2float(__float2half_rn(sp[2]));
                float h3 = __half2float(__float2half_rn(sp[3]));
                aph[half * 2 + 0] = pack_f16(sp[0], sp[1]);
                aph[half * 2 + 1] = pack_f16(sp[2], sp[3]);
                apl[half * 2 + 0] = pack_f16(sp[0] - h0, sp[1] - h1);
                apl[half * 2 + 1] = pack_f16(sp[2] - h2, sp[3] - h3);
            }
#pragma unroll
            for (int fnp = 0; fnp < 8; fnp++) {
                int vrow = fnp * 16 + (grp & 1) * 8 + ri;
                uint32_t va = smem + SM_VH + (uint32_t)vrow * VPAD + kk * 32u + (grp >> 1) * 16u;
                uint32_t bh4[4];
                ldmx4(bh4, va);
                uint32_t be[2] = {bh4[0], bh4[2]};
                uint32_t bo[2] = {bh4[1], bh4[3]};
                mma16816h(oacc[2 * fnp],     aph, be);
                mma16816h(oacc[2 * fnp],     apl, be);
                mma16816h(oacc[2 * fnp + 1], aph, bo);
                mma16816h(oacc[2 * fnp + 1], apl, bo);
            }
        }
    }

    // epilogue: divide by l, write fp16 hi/lo (O-proj input)
    float inv0 = 1.0f / l0, inv1 = 1.0f / l1;
    const size_t gr0 = (size_t)(q0 + rowA) * D + h * HD + cgrp * 2;
    const size_t gr1 = (size_t)(q0 + rowB) * D + h * HD + cgrp * 2;
#pragma unroll
    for (int fn = 0; fn < 16; fn++) {
        float v0 = oacc[fn][0] * inv0, v1 = oacc[fn][1] * inv0;
        float v2 = oacc[fn][2] * inv1, v3 = oacc[fn][3] * inv1;
        __half2 ph, pl;
        split2h(v0, v1, ph, pl);
        *reinterpret_cast<__half2*>(O16h + gr0 + fn * 8) = ph;
        *reinterpret_cast<__half2*>(O16l + gr0 + fn * 8) = pl;
        split2h(v2, v3, ph, pl);
        *reinterpret_cast<__half2*>(O16h + gr1 + fn * 8) = ph;
        *reinterpret_cast<__half2*>(O16l + gr1 + fn * 8) = pl;
    }
}

// ---------------- launch ----------------
extern "C" void kernel_launch(void* const* d_in, const int* in_sizes, int n_in,
                              void* d_out, int out_size)
{
    const float* x    = (const float*)d_in[0];
    const float* wq   = (const float*)d_in[1];
    const float* wk   = (const float*)d_in[2];
    const float* wv   = (const float*)d_in[3];
    const float* wo   = (const float*)d_in[4];
    const float* cosb = (const float*)d_in[5];
    const float* sinb = (const float*)d_in[6];
    float* out = (float*)d_out;

    __nv_bfloat16 *xhi, *xlo, *qhi, *qlo, *khi, *klo;
    __nv_bfloat16 *wqhi, *wqlo, *wkhi, *wklo;
    __half *x16h, *x16l, *a16h, *a16l, *vt16, *wv16, *wo16;
    cudaGetSymbolAddress((void**)&xhi, g_xhi);   cudaGetSymbolAddress((void**)&xlo, g_xlo);
    cudaGetSymbolAddress((void**)&x16h, g_x16h); cudaGetSymbolAddress((void**)&x16l, g_x16l);
    cudaGetSymbolAddress((void**)&a16h, g_a16h); cudaGetSymbolAddress((void**)&a16l, g_a16l);
    cudaGetSymbolAddress((void**)&qhi, g_qhi);   cudaGetSymbolAddress((void**)&qlo, g_qlo);
    cudaGetSymbolAddress((void**)&khi, g_khi);   cudaGetSymbolAddress((void**)&klo, g_klo);
    cudaGetSymbolAddress((void**)&vt16, g_vt16);
    cudaGetSymbolAddress((void**)&wqhi, g_wqhi); cudaGetSymbolAddress((void**)&wqlo, g_wqlo);
    cudaGetSymbolAddress((void**)&wkhi, g_wkhi); cudaGetSymbolAddress((void**)&wklo, g_wklo);
    cudaGetSymbolAddress((void**)&wv16, g_wv16); cudaGetSymbolAddress((void**)&wo16, g_wo16);

    const int shmem = 3 * (int)GSTAGE;        // 98304
    const int shmem16 = 3 * (int)G16STAGE;    // 73728
    cudaFuncSetAttribute(gemmqk_kernel, cudaFuncAttributeMaxDynamicSharedMemorySize, shmem);
    cudaFuncSetAttribute(gemm16_kernel, cudaFuncAttributeMaxDynamicSharedMemorySize, shmem16);
    cudaFuncSetAttribute(fattn_kernel, cudaFuncAttributeMaxDynamicSharedMemorySize, (int)SM_TOT);

    // input conversions
    xsplit_all<<<(S * D / 4 + 255) / 256, 256>>>(x, xhi, xlo, x16h, x16l, S * D / 4);
    tsplit_kernel<<<dim3(D / 32, D / 32), dim3(32, 8)>>>(wq, wqhi, wqlo, D, D);
    tsplit_kernel<<<dim3(KVD / 32, D / 32), dim3(32, 8)>>>(wk, wkhi, wklo, D, KVD);
    tsplit16_kernel<<<dim3(KVD / 32, D / 32), dim3(32, 8)>>>(wv, wv16, D, KVD);
    tsplit16_kernel<<<dim3(D / 32, D / 32), dim3(32, 8)>>>(wo, wo16, D, D);

    // Q + K projections merged, persistent (bf16 3-term, fused RoPE+scale+split)
    gemmqk_kernel<<<PGRID, 256, shmem>>>(
        xhi, xlo, wqhi, wqlo, qhi, qlo, wkhi, wklo, khi, klo, cosb, sinb);

    // V projection (fp16 2-term, fused transpose to fp16 [KVD][S])
    gemm16_kernel<<<KVD / 128 * (S / 128), 256, shmem16>>>(
        x16h, x16l, wv16, nullptr, vt16, KVD, D, 2, KVD / 128, KVD / 128 * (S / 128));

    // flash attention -> fp16 hi/lo
    fattn_kernel<<<dim3(S / 64, H), 128, SM_TOT>>>(qhi, qlo, khi, klo, vt16, a16h, a16l);

    // output projection (fp16 2-term, fp32 out), persistent
    gemm16_kernel<<<PGRID, 256, shmem16>>>(
        a16h, a16l, wo16, out, nullptr, D, D, 0, D / 128, (D / 128) * (S / 128));
}

// round 9
// speedup vs baseline: 1.3646x; 1.1892x over previous
#include <cuda_runtime.h>
#include <cuda_bf16.h>
#include <cuda_fp16.h>
#include <cstdint>

#define S 2048
#define D 4096
#define H 32
#define KVH 8
#define HD 128
#define NREP (H / KVH)
#define KVD (KVH * HD)
#define PGRID 304

// ---------------- scratch (static device arrays; no allocation) ----------------
__device__ __nv_bfloat16 g_xhi[S * D], g_xlo[S * D];
__device__ __half        g_x16[S * D];
__device__ __half        g_a16[S * D];
__device__ __nv_bfloat16 g_qhi[S * D], g_qlo[S * D];
__device__ __nv_bfloat16 g_khi[S * KVD], g_klo[S * KVD];
__device__ __half        g_vt16[KVD * S];                    // transposed [KVD][S], fp16
__device__ __nv_bfloat16 g_wqhi[D * D], g_wqlo[D * D];       // transposed [N,K]
__device__ __nv_bfloat16 g_wkhi[KVD * D], g_wklo[KVD * D];
__device__ __half        g_wv16[KVD * D];                    // transposed [N,K], fp16
__device__ __half        g_wo16[D * D];                      // transposed [N,K], fp16

// ---------------- helpers ----------------
__device__ __forceinline__ uint32_t s2u(const void* p) {
    uint32_t a;
    asm("{ .reg .u64 t; cvta.to.shared.u64 t, %1; cvt.u32.u64 %0, t; }" : "=r"(a) : "l"(p));
    return a;
}
__device__ __forceinline__ void cpasync16(uint32_t saddr, const void* gaddr) {
    asm volatile("cp.async.cg.shared.global [%0], [%1], 16;" :: "r"(saddr), "l"(gaddr));
}
__device__ __forceinline__ void ldmx4(uint32_t* r, uint32_t addr) {
    asm volatile("ldmatrix.sync.aligned.m8n8.x4.shared.b16 {%0,%1,%2,%3}, [%4];"
                 : "=r"(r[0]), "=r"(r[1]), "=r"(r[2]), "=r"(r[3]) : "r"(addr));
}
__device__ __forceinline__ void mma16816(float* d, const uint32_t* a, const uint32_t* b) {
    asm volatile(
        "mma.sync.aligned.m16n8k16.row.col.f32.bf16.bf16.f32 "
        "{%0,%1,%2,%3}, {%4,%5,%6,%7}, {%8,%9}, {%0,%1,%2,%3};"
        : "+f"(d[0]), "+f"(d[1]), "+f"(d[2]), "+f"(d[3])
        : "r"(a[0]), "r"(a[1]), "r"(a[2]), "r"(a[3]), "r"(b[0]), "r"(b[1]));
}
__device__ __forceinline__ void mma16816h(float* d, const uint32_t* a, const uint32_t* b) {
    asm volatile(
        "mma.sync.aligned.m16n8k16.row.col.f32.f16.f16.f32 "
        "{%0,%1,%2,%3}, {%4,%5,%6,%7}, {%8,%9}, {%0,%1,%2,%3};"
        : "+f"(d[0]), "+f"(d[1]), "+f"(d[2]), "+f"(d[3])
        : "r"(a[0]), "r"(a[1]), "r"(a[2]), "r"(a[3]), "r"(b[0]), "r"(b[1]));
}
__device__ __forceinline__ uint32_t pack_f16(float x, float y) {
    __half2 t = __floats2half2_rn(x, y);
    return *reinterpret_cast<uint32_t*>(&t);
}
__device__ __forceinline__ void split2(float v0, float v1, __nv_bfloat162& ph, __nv_bfloat162& pl) {
    __nv_bfloat16 h0 = __float2bfloat16(v0), h1 = __float2bfloat16(v1);
    ph.x = h0; ph.y = h1;
    pl.x = __float2bfloat16(v0 - __bfloat162float(h0));
    pl.y = __float2bfloat16(v1 - __bfloat162float(h1));
}

// ---------------- x: fp32 -> bf16 hi/lo + fp16 single ----------------
__global__ void xsplit_all(const float* __restrict__ in,
                           __nv_bfloat16* __restrict__ bh, __nv_bfloat16* __restrict__ bl,
                           __half* __restrict__ fh, int n4)
{
    int i = blockIdx.x * blockDim.x + threadIdx.x;
    if (i >= n4) return;
    float4 v = reinterpret_cast<const float4*>(in)[i];
    __nv_bfloat162 ph, pl;
    split2(v.x, v.y, ph, pl);
    reinterpret_cast<__nv_bfloat162*>(bh)[2 * i] = ph;
    reinterpret_cast<__nv_bfloat162*>(bl)[2 * i] = pl;
    split2(v.z, v.w, ph, pl);
    reinterpret_cast<__nv_bfloat162*>(bh)[2 * i + 1] = ph;
    reinterpret_cast<__nv_bfloat162*>(bl)[2 * i + 1] = pl;
    reinterpret_cast<__half2*>(fh)[2 * i]     = __floats2half2_rn(v.x, v.y);
    reinterpret_cast<__half2*>(fh)[2 * i + 1] = __floats2half2_rn(v.z, v.w);
}

// ---------------- transpose+split: W[K,N] fp32 -> hi/lo bf16 [N,K] ----------------
__global__ void tsplit_kernel(const float* __restrict__ w,
                              __nv_bfloat16* __restrict__ hi,
                              __nv_bfloat16* __restrict__ lo, int K, int N)
{
    __shared__ float t[32][33];
    int n0 = blockIdx.x * 32, k0 = blockIdx.y * 32;
    int tx = threadIdx.x, ty = threadIdx.y;
    for (int r = ty; r < 32; r += 8)
        t[r][tx] = w[(size_t)(k0 + r) * N + n0 + tx];
    __syncthreads();
    for (int r = ty; r < 32; r += 8) {
        float v = t[tx][r];
        __nv_bfloat16 h = __float2bfloat16(v);
        __nv_bfloat16 l = __float2bfloat16(v - __bfloat162float(h));
        size_t o = (size_t)(n0 + r) * K + k0 + tx;
        hi[o] = h; lo[o] = l;
    }
}

// ---------------- transpose: W[K,N] fp32 -> fp16 [N,K] ----------------
__global__ void tsplit16_kernel(const float* __restrict__ w,
                                __half* __restrict__ out, int K, int N)
{
    __shared__ float t[32][33];
    int n0 = blockIdx.x * 32, k0 = blockIdx.y * 32;
    int tx = threadIdx.x, ty = threadIdx.y;
    for (int r = ty; r < 32; r += 8)
        t[r][tx] = w[(size_t)(k0 + r) * N + n0 + tx];
    __syncthreads();
    for (int r = ty; r < 32; r += 8)
        out[(size_t)(n0 + r) * K + k0 + tx] = __float2half_rn(t[tx][r]);
}

// ---------------- bf16 3-term GEMM: persistent, merged Q+K projections ----------------
#define GTILE  8192u
#define GSTAGE 32768u
#define NXQ    (D / 128)
#define NTXQK  (D / 128 + KVD / 128)
#define NTILQK (NTXQK * (S / 128))

__global__ __launch_bounds__(256, 2) void gemmqk_kernel(
    const __nv_bfloat16* __restrict__ Ahi, const __nv_bfloat16* __restrict__ Alo,
    const __nv_bfloat16* __restrict__ Bq_hi, const __nv_bfloat16* __restrict__ Bq_lo,
    __nv_bfloat16* __restrict__ Cq_hi, __nv_bfloat16* __restrict__ Cq_lo,
    const __nv_bfloat16* __restrict__ Bk_hi, const __nv_bfloat16* __restrict__ Bk_lo,
    __nv_bfloat16* __restrict__ Ck_hi, __nv_bfloat16* __restrict__ Ck_lo,
    const float* __restrict__ cosb, const float* __restrict__ sinb)
{
    extern __shared__ char dsm[];
    const uint32_t smem = s2u(dsm);

    const int tid = threadIdx.x;
    const int wid = tid >> 5;
    const int lane = tid & 31;
    const int wm = (wid & 1) * 64;
    const int wn = (wid >> 1) * 32;
    const int grp = lane >> 3;
    const int ri = lane & 7;

    for (int tile = blockIdx.x; tile < NTILQK; tile += gridDim.x) {
        const int txi = tile % NTXQK;
        const int by = (tile / NTXQK) * 128;
        const bool isQ = txi < NXQ;
        const __nv_bfloat16* Bhi = isQ ? Bq_hi : Bk_hi;
        const __nv_bfloat16* Blo = isQ ? Bq_lo : Bk_lo;
        __nv_bfloat16* Chi = isQ ? Cq_hi : Ck_hi;
        __nv_bfloat16* Clo = isQ ? Cq_lo : Ck_lo;
        const int Ndim = isQ ? D : KVD;
        const float scale = isQ ? 0.08838834764831845f : 1.0f;
        const int bx = (isQ ? txi : txi - NXQ) * 128;

        float acc[4][4][4];
#pragma unroll
        for (int i = 0; i < 4; i++)
#pragma unroll
            for (int j = 0; j < 4; j++)
#pragma unroll
                for (int e = 0; e < 4; e++) acc[i][j][e] = 0.0f;

        auto load_stage = [&](int c, int stage) {
            const uint32_t sb = smem + stage * GSTAGE;
            const int k0 = c << 5;
#pragma unroll
            for (int i = 0; i < 2; i++) {
                int idx = tid + i * 256;
                int row = idx >> 2, cc = idx & 3;
                uint32_t sc = (uint32_t)(cc ^ ((row >> 1) & 3));
                uint32_t so = (uint32_t)row * 64u + sc * 16u;
                size_t ga = (size_t)(by + row) * D + k0 + cc * 8;
                size_t gb = (size_t)(bx + row) * D + k0 + cc * 8;
                cpasync16(sb + so,              Ahi + ga);
                cpasync16(sb + GTILE + so,      Alo + ga);
                cpasync16(sb + 2 * GTILE + so,  Bhi + gb);
                cpasync16(sb + 3 * GTILE + so,  Blo + gb);
            }
        };

        load_stage(0, 0);
        asm volatile("cp.async.commit_group;");
        load_stage(1, 1);
        asm volatile("cp.async.commit_group;");

        const int nchunks = D >> 5;
        for (int c = 0; c < nchunks; c++) {
            if (c + 1 < nchunks) asm volatile("cp.async.wait_group 1;");
            else                 asm volatile("cp.async.wait_group 0;");
            __syncthreads();
            if (c + 2 < nchunks) {
                load_stage(c + 2, (c + 2) % 3);
                asm volatile("cp.async.commit_group;");
            }

            const uint32_t sb = smem + (c % 3) * GSTAGE;

#pragma unroll
            for (int k16 = 0; k16 < 2; k16++) {
                const int lchunk = k16 * 2 + (grp >> 1);
                uint32_t ah[4][4], al[4][4];
#pragma unroll
                for (int fm = 0; fm < 4; fm++) {
                    int row = wm + fm * 16 + (grp & 1) * 8 + ri;
                    uint32_t ad = sb + (uint32_t)row * 64u
                                + (uint32_t)((lchunk ^ ((row >> 1) & 3)) * 16);
                    ldmx4(ah[fm], ad);
                    ldmx4(al[fm], ad + GTILE);
                }
#pragma unroll
                for (int fnp = 0; fnp < 2; fnp++) {
                    int row = wn + fnp * 16 + (grp & 1) * 8 + ri;
                    uint32_t bd = sb + 2 * GTILE + (uint32_t)row * 64u
                                + (uint32_t)((lchunk ^ ((row >> 1) & 3)) * 16);
                    uint32_t bh4[4], bl4[4];
                    ldmx4(bh4, bd);
                    ldmx4(bl4, bd + GTILE);
                    uint32_t be[2]  = {bh4[0], bh4[2]};
                    uint32_t bo[2]  = {bh4[1], bh4[3]};
                    uint32_t ble[2] = {bl4[0], bl4[2]};
                    uint32_t blo[2] = {bl4[1], bl4[3]};
#pragma unroll
                    for (int fm = 0; fm < 4; fm++) {
                        mma16816(acc[fm][2 * fnp],     ah[fm], be);
                        mma16816(acc[fm][2 * fnp],     al[fm], be);
                        mma16816(acc[fm][2 * fnp],     ah[fm], ble);
                        mma16816(acc[fm][2 * fnp + 1], ah[fm], bo);
                        mma16816(acc[fm][2 * fnp + 1], al[fm], bo);
                        mma16816(acc[fm][2 * fnp + 1], ah[fm], blo);
                    }
                }
            }
        }

        // RoPE + scale + split epilogue
        const int erow = lane >> 2;
        const int ecol = (lane & 3) * 2;
#pragma unroll
        for (int fm = 0; fm < 4; fm++) {
#pragma unroll
            for (int fn = 0; fn < 4; fn++) {
                int col = bx + wn + fn * 8 + ecol;
                int i = (col & 127) >> 1;
#pragma unroll
                for (int half = 0; half < 2; half++) {
                    int row = by + wm + fm * 16 + erow + half * 8;
                    float cv = cosb[row * 64 + i];
                    float sv = sinb[row * 64 + i];
                    float t0 = acc[fm][fn][half * 2], t1 = acc[fm][fn][half * 2 + 1];
                    float o0 = (t0 * cv - t1 * sv) * scale;
                    float o1 = (t0 * sv + t1 * cv) * scale;
                    __nv_bfloat162 ph, pl;
                    split2(o0, o1, ph, pl);
                    size_t o = (size_t)row * Ndim + col;
                    *reinterpret_cast<__nv_bfloat162*>(Chi + o) = ph;
                    *reinterpret_cast<__nv_bfloat162*>(Clo + o) = pl;
                }
            }
        }
        __syncthreads();
    }
}

// ---------------- fp16 1-term GEMM: persistent ----------------
// mode 0: fp32 C[row*Ndim+col]    mode 2: transpose fp16: C16[col*S+row]
#define G16STAGE 16384u   // 2 tiles (A, B)

__global__ __launch_bounds__(256, 2) void gemm16_kernel(
    const __half* __restrict__ A16, const __half* __restrict__ B16,
    float* __restrict__ Cf, __half* __restrict__ C16,
    int Ndim, int Kdim, int mode, int ntx, int ntiles)
{
    extern __shared__ char dsm[];
    const uint32_t smem = s2u(dsm);

    const int tid = threadIdx.x;
    const int wid = tid >> 5;
    const int lane = tid & 31;
    const int wm = (wid & 1) * 64;
    const int wn = (wid >> 1) * 32;
    const int grp = lane >> 3;
    const int ri = lane & 7;

    for (int tile = blockIdx.x; tile < ntiles; tile += gridDim.x) {
        const int bx = (tile % ntx) * 128;
        const int by = (tile / ntx) * 128;

        float acc[4][4][4];
#pragma unroll
        for (int i = 0; i < 4; i++)
#pragma unroll
            for (int j = 0; j < 4; j++)
#pragma unroll
                for (int e = 0; e < 4; e++) acc[i][j][e] = 0.0f;

        auto load_stage = [&](int c, int stage) {
            const uint32_t sb = smem + stage * G16STAGE;
            const int k0 = c << 5;
#pragma unroll
            for (int i = 0; i < 2; i++) {
                int idx = tid + i * 256;
                int row = idx >> 2, cc = idx & 3;
                uint32_t sc = (uint32_t)(cc ^ ((row >> 1) & 3));
                uint32_t so = (uint32_t)row * 64u + sc * 16u;
                cpasync16(sb + so,         A16 + (size_t)(by + row) * Kdim + k0 + cc * 8);
                cpasync16(sb + GTILE + so, B16 + (size_t)(bx + row) * Kdim + k0 + cc * 8);
            }
        };

        load_stage(0, 0);
        asm volatile("cp.async.commit_group;");
        load_stage(1, 1);
        asm volatile("cp.async.commit_group;");

        const int nchunks = Kdim >> 5;
        for (int c = 0; c < nchunks; c++) {
            if (c + 1 < nchunks) asm volatile("cp.async.wait_group 1;");
            else                 asm volatile("cp.async.wait_group 0;");
            __syncthreads();
            if (c + 2 < nchunks) {
                load_stage(c + 2, (c + 2) % 3);
                asm volatile("cp.async.commit_group;");
            }

            const uint32_t sb = smem + (c % 3) * G16STAGE;

#pragma unroll
            for (int k16 = 0; k16 < 2; k16++) {
                const int lchunk = k16 * 2 + (grp >> 1);
                uint32_t ah[4][4];
#pragma unroll
                for (int fm = 0; fm < 4; fm++) {
                    int row = wm + fm * 16 + (grp & 1) * 8 + ri;
                    uint32_t ad = sb + (uint32_t)row * 64u
                                + (uint32_t)((lchunk ^ ((row >> 1) & 3)) * 16);
                    ldmx4(ah[fm], ad);
                }
#pragma unroll
                for (int fnp = 0; fnp < 2; fnp++) {
                    int row = wn + fnp * 16 + (grp & 1) * 8 + ri;
                    uint32_t bd = sb + GTILE + (uint32_t)row * 64u
                                + (uint32_t)((lchunk ^ ((row >> 1) & 3)) * 16);
                    uint32_t bh4[4];
                    ldmx4(bh4, bd);
                    uint32_t be[2] = {bh4[0], bh4[2]};
                    uint32_t bo[2] = {bh4[1], bh4[3]};
#pragma unroll
                    for (int fm = 0; fm < 4; fm++) {
                        mma16816h(acc[fm][2 * fnp],     ah[fm], be);
                        mma16816h(acc[fm][2 * fnp + 1], ah[fm], bo);
                    }
                }
            }
        }

        const int erow = lane >> 2;
        const int ecol = (lane & 3) * 2;
        if (mode == 0) {
#pragma unroll
            for (int fm = 0; fm < 4; fm++) {
#pragma unroll
                for (int fn = 0; fn < 4; fn++) {
                    float* cp0 = Cf + (size_t)(by + wm + fm * 16 + erow) * Ndim + bx + wn + fn * 8 + ecol;
                    float* cp1 = cp0 + 8 * (size_t)Ndim;
                    *reinterpret_cast<float2*>(cp0) = make_float2(acc[fm][fn][0], acc[fm][fn][1]);
                    *reinterpret_cast<float2*>(cp1) = make_float2(acc[fm][fn][2], acc[fm][fn][3]);
                }
            }
        } else {
#pragma unroll
            for (int fm = 0; fm < 4; fm++) {
#pragma unroll
                for (int fn = 0; fn < 4; fn++) {
                    int col = bx + wn + fn * 8 + ecol;
#pragma unroll
                    for (int half = 0; half < 2; half++) {
                        int row = by + wm + fm * 16 + erow + half * 8;
#pragma unroll
                        for (int e = 0; e < 2; e++) {
                            float v = acc[fm][fn][half * 2 + e];
                            C16[(size_t)(col + e) * S + row] = __float2half_rn(v);
                        }
                    }
                }
            }
        }
        __syncthreads();
    }
}

// ---------------- flash attention: QK bf16 3-term, PV fp16 1-term ----------------
#define KPAD 272u
#define VPAD 144u
#define SM_QH 0u
#define SM_QL 17408u
#define SM_KH 34816u
#define SM_KL 52224u
#define SM_VH 69632u
#define SM_TOT 88064u

__global__ __launch_bounds__(128) void fattn_kernel(
    const __nv_bfloat16* __restrict__ Qh, const __nv_bfloat16* __restrict__ Ql,
    const __nv_bfloat16* __restrict__ Kh, const __nv_bfloat16* __restrict__ Kl,
    const __half* __restrict__ Vt16, __half* __restrict__ O16)
{
    extern __shared__ char dsm[];
    const uint32_t smem = s2u(dsm);
    const int tid = threadIdx.x;
    const int wid = tid >> 5, lane = tid & 31;
    const int qt = gridDim.x - 1 - blockIdx.x;
    const int h = blockIdx.y;
    const int kvh = h / NREP;
    const int q0 = qt * 64;

    const int r = lane >> 2;
    const int cgrp = lane & 3;
    const int grp = lane >> 3;
    const int ri = lane & 7;

    auto loadK = [&](int t) {
#pragma unroll
        for (int i = 0; i < 8; i++) {
            int idx = tid + i * 128;
            int row = idx >> 4, cc = idx & 15;
            size_t g = (size_t)(t * 64 + row) * KVD + kvh * HD + cc * 8;
            cpasync16(smem + SM_KH + row * KPAD + cc * 16, Kh + g);
            cpasync16(smem + SM_KL + row * KPAD + cc * 16, Kl + g);
        }
    };
    auto loadV = [&](int t) {
#pragma unroll
        for (int i = 0; i < 8; i++) {
            int idx = tid + i * 128;
            int row = idx >> 3, cc = idx & 7;
            size_t g = (size_t)(kvh * HD + row) * S + t * 64 + cc * 8;
            cpasync16(smem + SM_VH + row * VPAD + cc * 16, Vt16 + g);
        }
    };

#pragma unroll
    for (int i = 0; i < 8; i++) {
        int idx = tid + i * 128;
        int row = idx >> 4, cc = idx & 15;
        size_t g = (size_t)(q0 + row) * D + h * HD + cc * 8;
        cpasync16(smem + SM_QH + row * KPAD + cc * 16, Qh + g);
        cpasync16(smem + SM_QL + row * KPAD + cc * 16, Ql + g);
    }
    loadK(0);
    asm volatile("cp.async.commit_group;");
    asm volatile("cp.async.wait_group 0;");
    __syncthreads();

    uint32_t qh[8][4], ql[8][4];
    {
        int qrow = wid * 16 + (grp & 1) * 8 + ri;
        uint32_t qbase = smem + SM_QH + (uint32_t)qrow * KPAD + (grp >> 1) * 16u;
#pragma unroll
        for (int ks = 0; ks < 8; ks++) {
            ldmx4(qh[ks], qbase + ks * 32u);
            ldmx4(ql[ks], qbase + ks * 32u + (SM_QL - SM_QH));
        }
    }

    float m0 = -1e30f, m1 = -1e30f, l0 = 0.0f, l1 = 0.0f;
    float oacc[16][4];
#pragma unroll
    for (int f = 0; f < 16; f++)
#pragma unroll
        for (int e = 0; e < 4; e++) oacc[f][e] = 0.0f;

    const int rowA = wid * 16 + r;
    const int rowB = rowA + 8;

    for (int t = 0; t <= qt; t++) {
        if (t > 0) {
            asm volatile("cp.async.wait_group 0;");
            __syncthreads();
        }
        loadV(t);
        asm volatile("cp.async.commit_group;");

        float sacc[8][4];
#pragma unroll
        for (int f = 0; f < 8; f++)
#pragma unroll
            for (int e = 0; e < 4; e++) sacc[f][e] = 0.0f;

#pragma unroll
        for (int ks = 0; ks < 8; ks++) {
#pragma unroll
            for (int fnp = 0; fnp < 4; fnp++) {
                int krow = fnp * 16 + (grp & 1) * 8 + ri;
                uint32_t ka = smem + SM_KH + (uint32_t)krow * KPAD + ks * 32u + (grp >> 1) * 16u;
                uint32_t bh4[4], bl4[4];
                ldmx4(bh4, ka);
                ldmx4(bl4, ka + (SM_KL - SM_KH));
                uint32_t be[2]  = {bh4[0], bh4[2]};
                uint32_t bo[2]  = {bh4[1], bh4[3]};
                uint32_t ble[2] = {bl4[0], bl4[2]};
                uint32_t blo[2] = {bl4[1], bl4[3]};
                mma16816(sacc[2 * fnp],     qh[ks], be);
                mma16816(sacc[2 * fnp],     ql[ks], be);
                mma16816(sacc[2 * fnp],     qh[ks], ble);
                mma16816(sacc[2 * fnp + 1], qh[ks], bo);
                mma16816(sacc[2 * fnp + 1], ql[ks], bo);
                mma16816(sacc[2 * fnp + 1], qh[ks], blo);
            }
        }

        if (t == qt) {
#pragma unroll
            for (int fn = 0; fn < 8; fn++) {
                int c0 = fn * 8 + cgrp * 2;
                if (c0 > rowA) sacc[fn][0] = -1e30f;
                if (c0 + 1 > rowA) sacc[fn][1] = -1e30f;
                if (c0 > rowB) sacc[fn][2] = -1e30f;
                if (c0 + 1 > rowB) sacc[fn][3] = -1e30f;
            }
        }

        float tm0 = -1e30f, tm1 = -1e30f;
#pragma unroll
        for (int fn = 0; fn < 8; fn++) {
            tm0 = fmaxf(tm0, fmaxf(sacc[fn][0], sacc[fn][1]));
            tm1 = fmaxf(tm1, fmaxf(sacc[fn][2], sacc[fn][3]));
        }
        tm0 = fmaxf(tm0, __shfl_xor_sync(0xFFFFFFFFu, tm0, 1));
        tm0 = fmaxf(tm0, __shfl_xor_sync(0xFFFFFFFFu, tm0, 2));
        tm1 = fmaxf(tm1, __shfl_xor_sync(0xFFFFFFFFu, tm1, 1));
        tm1 = fmaxf(tm1, __shfl_xor_sync(0xFFFFFFFFu, tm1, 2));

        float mn0 = fmaxf(m0, tm0), mn1 = fmaxf(m1, tm1);
        float corr0 = __expf(m0 - mn0), corr1 = __expf(m1 - mn1);
        m0 = mn0; m1 = mn1;

        float rs0 = 0.0f, rs1 = 0.0f;
#pragma unroll
        for (int fn = 0; fn < 8; fn++) {
            sacc[fn][0] = __expf(sacc[fn][0] - m0);
            sacc[fn][1] = __expf(sacc[fn][1] - m0);
            sacc[fn][2] = __expf(sacc[fn][2] - m1);
            sacc[fn][3] = __expf(sacc[fn][3] - m1);
            rs0 += sacc[fn][0] + sacc[fn][1];
            rs1 += sacc[fn][2] + sacc[fn][3];
        }
        rs0 += __shfl_xor_sync(0xFFFFFFFFu, rs0, 1);
        rs0 += __shfl_xor_sync(0xFFFFFFFFu, rs0, 2);
        rs1 += __shfl_xor_sync(0xFFFFFFFFu, rs1, 1);
        rs1 += __shfl_xor_sync(0xFFFFFFFFu, rs1, 2);
        l0 = l0 * corr0 + rs0;
        l1 = l1 * corr1 + rs1;

#pragma unroll
        for (int f = 0; f < 16; f++) {
            oacc[f][0] *= corr0; oacc[f][1] *= corr0;
            oacc[f][2] *= corr1; oacc[f][3] *= corr1;
        }

        asm volatile("cp.async.wait_group 0;");
        __syncthreads();
        if (t < qt) {
            loadK(t + 1);
            asm volatile("cp.async.commit_group;");
        }

        // ---- O += P V (P single fp16, V single fp16) ----
#pragma unroll
        for (int kk = 0; kk < 4; kk++) {
            uint32_t aph[4];
#pragma unroll
            for (int half = 0; half < 2; half++) {
                const float* sp = sacc[2 * kk + half];
                aph[half * 2 + 0] = pack_f16(sp[0], sp[1]);
                aph[half * 2 + 1] = pack_f16(sp[2], sp[3]);
            }
#pragma unroll
            for (int fnp = 0; fnp < 8; fnp++) {
                int vrow = fnp * 16 + (grp & 1) * 8 + ri;
                uint32_t va = smem + SM_VH + (uint32_t)vrow * VPAD + kk * 32u + (grp >> 1) * 16u;
                uint32_t bh4[4];
                ldmx4(bh4, va);
                uint32_t be[2] = {bh4[0], bh4[2]};
                uint32_t bo[2] = {bh4[1], bh4[3]};
                mma16816h(oacc[2 * fnp],     aph, be);
                mma16816h(oacc[2 * fnp + 1], aph, bo);
            }
        }
    }

    // epilogue: divide by l, write fp16 single (O-proj input)
    float inv0 = 1.0f / l0, inv1 = 1.0f / l1;
    const size_t gr0 = (size_t)(q0 + rowA) * D + h * HD + cgrp * 2;
    const size_t gr1 = (size_t)(q0 + rowB) * D + h * HD + cgrp * 2;
#pragma unroll
    for (int fn = 0; fn < 16; fn++) {
        *reinterpret_cast<__half2*>(O16 + gr0 + fn * 8) =
            __floats2half2_rn(oacc[fn][0] * inv0, oacc[fn][1] * inv0);
        *reinterpret_cast<__half2*>(O16 + gr1 + fn * 8) =
            __floats2half2_rn(oacc[fn][2] * inv1, oacc[fn][3] * inv1);
    }
}

// ---------------- launch ----------------
extern "C" void kernel_launch(void* const* d_in, const int* in_sizes, int n_in,
                              void* d_out, int out_size)
{
    const float* x    = (const float*)d_in[0];
    const float* wq   = (const float*)d_in[1];
    const float* wk   = (const float*)d_in[2];
    const float* wv   = (const float*)d_in[3];
    const float* wo   = (const float*)d_in[4];
    const float* cosb = (const float*)d_in[5];
    const float* sinb = (const float*)d_in[6];
    float* out = (float*)d_out;

    __nv_bfloat16 *xhi, *xlo, *qhi, *qlo, *khi, *klo;
    __nv_bfloat16 *wqhi, *wqlo, *wkhi, *wklo;
    __half *x16, *a16, *vt16, *wv16, *wo16;
    cudaGetSymbolAddress((void**)&xhi, g_xhi);   cudaGetSymbolAddress((void**)&xlo, g_xlo);
    cudaGetSymbolAddress((void**)&x16, g_x16);   cudaGetSymbolAddress((void**)&a16, g_a16);
    cudaGetSymbolAddress((void**)&qhi, g_qhi);   cudaGetSymbolAddress((void**)&qlo, g_qlo);
    cudaGetSymbolAddress((void**)&khi, g_khi);   cudaGetSymbolAddress((void**)&klo, g_klo);
    cudaGetSymbolAddress((void**)&vt16, g_vt16);
    cudaGetSymbolAddress((void**)&wqhi, g_wqhi); cudaGetSymbolAddress((void**)&wqlo, g_wqlo);
    cudaGetSymbolAddress((void**)&wkhi, g_wkhi); cudaGetSymbolAddress((void**)&wklo, g_wklo);
    cudaGetSymbolAddress((void**)&wv16, g_wv16); cudaGetSymbolAddress((void**)&wo16, g_wo16);

    const int shmem = 3 * (int)GSTAGE;        // 98304
    const int shmem16 = 3 * (int)G16STAGE;    // 49152
    cudaFuncSetAttribute(gemmqk_kernel, cudaFuncAttributeMaxDynamicSharedMemorySize, shmem);
    cudaFuncSetAttribute(gemm16_kernel, cudaFuncAttributeMaxDynamicSharedMemorySize, shmem16);
    cudaFuncSetAttribute(fattn_kernel, cudaFuncAttributeMaxDynamicSharedMemorySize, (int)SM_TOT);

    // input conversions
    xsplit_all<<<(S * D / 4 + 255) / 256, 256>>>(x, xhi, xlo, x16, S * D / 4);
    tsplit_kernel<<<dim3(D / 32, D / 32), dim3(32, 8)>>>(wq, wqhi, wqlo, D, D);
    tsplit_kernel<<<dim3(KVD / 32, D / 32), dim3(32, 8)>>>(wk, wkhi, wklo, D, KVD);
    tsplit16_kernel<<<dim3(KVD / 32, D / 32), dim3(32, 8)>>>(wv, wv16, D, KVD);
    tsplit16_kernel<<<dim3(D / 32, D / 32), dim3(32, 8)>>>(wo, wo16, D, D);

    // Q + K projections merged, persistent (bf16 3-term, fused RoPE+scale+split)
    gemmqk_kernel<<<PGRID, 256, shmem>>>(
        xhi, xlo, wqhi, wqlo, qhi, qlo, wkhi, wklo, khi, klo, cosb, sinb);

    // V projection (fp16 1-term, fused transpose to fp16 [KVD][S])
    gemm16_kernel<<<KVD / 128 * (S / 128), 256, shmem16>>>(
        x16, wv16, nullptr, vt16, KVD, D, 2, KVD / 128, KVD / 128 * (S / 128));

    // flash attention -> fp16 single
    fattn_kernel<<<dim3(S / 64, H), 128, SM_TOT>>>(qhi, qlo, khi, klo, vt16, a16);

    // output projection (fp16 1-term, fp32 out), persistent
    gemm16_kernel<<<PGRID, 256, shmem16>>>(
        a16, wo16, out, nullptr, D, D, 0, D / 128, (D / 128) * (S / 128));
}

// round 10
// speedup vs baseline: 1.3752x; 1.0078x over previous
#include <cuda_runtime.h>
#include <cuda_bf16.h>
#include <cuda_fp16.h>
#include <cstdint>

#define S 2048
#define D 4096
#define H 32
#define KVH 8
#define HD 128
#define NREP (H / KVH)
#define KVD (KVH * HD)
#define PGRID 304

// ---------------- scratch (static device arrays; no allocation) ----------------
__device__ __nv_bfloat16 g_xhi[S * D], g_xlo[S * D];
__device__ __half        g_x16h[S * D], g_x16l[S * D];
__device__ __half        g_a16[S * D];
__device__ __nv_bfloat16 g_qhi[S * D], g_qlo[S * D];
__device__ __nv_bfloat16 g_khi[S * KVD], g_klo[S * KVD];
__device__ __half        g_vt16[KVD * S];                    // transposed [KVD][S], fp16
__device__ __half        g_wq16[D * D];                      // transposed [N,K], fp16
__device__ __nv_bfloat16 g_wkhi[KVD * D], g_wklo[KVD * D];   // transposed [N,K]
__device__ __half        g_wv16[KVD * D];
__device__ __half        g_wo16[D * D];

// ---------------- helpers ----------------
__device__ __forceinline__ uint32_t s2u(const void* p) {
    uint32_t a;
    asm("{ .reg .u64 t; cvta.to.shared.u64 t, %1; cvt.u32.u64 %0, t; }" : "=r"(a) : "l"(p));
    return a;
}
__device__ __forceinline__ void cpasync16(uint32_t saddr, const void* gaddr) {
    asm volatile("cp.async.cg.shared.global [%0], [%1], 16;" :: "r"(saddr), "l"(gaddr));
}
__device__ __forceinline__ void ldmx4(uint32_t* r, uint32_t addr) {
    asm volatile("ldmatrix.sync.aligned.m8n8.x4.shared.b16 {%0,%1,%2,%3}, [%4];"
                 : "=r"(r[0]), "=r"(r[1]), "=r"(r[2]), "=r"(r[3]) : "r"(addr));
}
__device__ __forceinline__ void mma16816(float* d, const uint32_t* a, const uint32_t* b) {
    asm volatile(
        "mma.sync.aligned.m16n8k16.row.col.f32.bf16.bf16.f32 "
        "{%0,%1,%2,%3}, {%4,%5,%6,%7}, {%8,%9}, {%0,%1,%2,%3};"
        : "+f"(d[0]), "+f"(d[1]), "+f"(d[2]), "+f"(d[3])
        : "r"(a[0]), "r"(a[1]), "r"(a[2]), "r"(a[3]), "r"(b[0]), "r"(b[1]));
}
__device__ __forceinline__ void mma16816h(float* d, const uint32_t* a, const uint32_t* b) {
    asm volatile(
        "mma.sync.aligned.m16n8k16.row.col.f32.f16.f16.f32 "
        "{%0,%1,%2,%3}, {%4,%5,%6,%7}, {%8,%9}, {%0,%1,%2,%3};"
        : "+f"(d[0]), "+f"(d[1]), "+f"(d[2]), "+f"(d[3])
        : "r"(a[0]), "r"(a[1]), "r"(a[2]), "r"(a[3]), "r"(b[0]), "r"(b[1]));
}
__device__ __forceinline__ uint32_t pack_f16(float x, float y) {
    __half2 t = __floats2half2_rn(x, y);
    return *reinterpret_cast<uint32_t*>(&t);
}
__device__ __forceinline__ void split2(float v0, float v1, __nv_bfloat162& ph, __nv_bfloat162& pl) {
    __nv_bfloat16 h0 = __float2bfloat16(v0), h1 = __float2bfloat16(v1);
    ph.x = h0; ph.y = h1;
    pl.x = __float2bfloat16(v0 - __bfloat162float(h0));
    pl.y = __float2bfloat16(v1 - __bfloat162float(h1));
}
__device__ __forceinline__ void split2h(float v0, float v1, __half2& ph, __half2& pl) {
    __half h0 = __float2half_rn(v0), h1 = __float2half_rn(v1);
    ph = __halves2half2(h0, h1);
    pl = __halves2half2(__float2half_rn(v0 - __half2float(h0)),
                        __float2half_rn(v1 - __half2float(h1)));
}

// ---------------- x: fp32 -> bf16 hi/lo + fp16 hi/lo ----------------
__global__ void xsplit_all(const float* __restrict__ in,
                           __nv_bfloat16* __restrict__ bh, __nv_bfloat16* __restrict__ bl,
                           __half* __restrict__ fh, __half* __restrict__ fl, int n4)
{
    int i = blockIdx.x * blockDim.x + threadIdx.x;
    if (i >= n4) return;
    float4 v = reinterpret_cast<const float4*>(in)[i];
    __nv_bfloat162 ph, pl;
    split2(v.x, v.y, ph, pl);
    reinterpret_cast<__nv_bfloat162*>(bh)[2 * i] = ph;
    reinterpret_cast<__nv_bfloat162*>(bl)[2 * i] = pl;
    split2(v.z, v.w, ph, pl);
    reinterpret_cast<__nv_bfloat162*>(bh)[2 * i + 1] = ph;
    reinterpret_cast<__nv_bfloat162*>(bl)[2 * i + 1] = pl;
    __half2 hh, hl;
    split2h(v.x, v.y, hh, hl);
    reinterpret_cast<__half2*>(fh)[2 * i] = hh;
    reinterpret_cast<__half2*>(fl)[2 * i] = hl;
    split2h(v.z, v.w, hh, hl);
    reinterpret_cast<__half2*>(fh)[2 * i + 1] = hh;
    reinterpret_cast<__half2*>(fl)[2 * i + 1] = hl;
}

// ---------------- transpose+split: W[K,N] fp32 -> hi/lo bf16 [N,K] ----------------
__global__ void tsplit_kernel(const float* __restrict__ w,
                              __nv_bfloat16* __restrict__ hi,
                              __nv_bfloat16* __restrict__ lo, int K, int N)
{
    __shared__ float t[32][33];
    int n0 = blockIdx.x * 32, k0 = blockIdx.y * 32;
    int tx = threadIdx.x, ty = threadIdx.y;
    for (int r = ty; r < 32; r += 8)
        t[r][tx] = w[(size_t)(k0 + r) * N + n0 + tx];
    __syncthreads();
    for (int r = ty; r < 32; r += 8) {
        float v = t[tx][r];
        __nv_bfloat16 h = __float2bfloat16(v);
        __nv_bfloat16 l = __float2bfloat16(v - __bfloat162float(h));
        size_t o = (size_t)(n0 + r) * K + k0 + tx;
        hi[o] = h; lo[o] = l;
    }
}

// ---------------- transpose: W[K,N] fp32 -> fp16 [N,K] ----------------
__global__ void tsplit16_kernel(const float* __restrict__ w,
                                __half* __restrict__ out, int K, int N)
{
    __shared__ float t[32][33];
    int n0 = blockIdx.x * 32, k0 = blockIdx.y * 32;
    int tx = threadIdx.x, ty = threadIdx.y;
    for (int r = ty; r < 32; r += 8)
        t[r][tx] = w[(size_t)(k0 + r) * N + n0 + tx];
    __syncthreads();
    for (int r = ty; r < 32; r += 8)
        out[(size_t)(n0 + r) * K + k0 + tx] = __float2half_rn(t[tx][r]);
}

#define GTILE  8192u

// ---------------- bf16 3-term GEMM: K projection, RoPE+split epilogue ----------------
#define GSTAGE 32768u

__global__ __launch_bounds__(256, 2) void gemmk_kernel(
    const __nv_bfloat16* __restrict__ Ahi, const __nv_bfloat16* __restrict__ Alo,
    const __nv_bfloat16* __restrict__ Bhi, const __nv_bfloat16* __restrict__ Blo,
    __nv_bfloat16* __restrict__ Chi, __nv_bfloat16* __restrict__ Clo,
    const float* __restrict__ cosb, const float* __restrict__ sinb)
{
    extern __shared__ char dsm[];
    const uint32_t smem = s2u(dsm);

    const int tid = threadIdx.x;
    const int wid = tid >> 5;
    const int lane = tid & 31;
    const int by = blockIdx.y * 128;
    const int bx = blockIdx.x * 128;
    const int wm = (wid & 1) * 64;
    const int wn = (wid >> 1) * 32;
    const int grp = lane >> 3;
    const int ri = lane & 7;

    float acc[4][4][4];
#pragma unroll
    for (int i = 0; i < 4; i++)
#pragma unroll
        for (int j = 0; j < 4; j++)
#pragma unroll
            for (int e = 0; e < 4; e++) acc[i][j][e] = 0.0f;

    auto load_stage = [&](int c, int stage) {
        const uint32_t sb = smem + stage * GSTAGE;
        const int k0 = c << 5;
#pragma unroll
        for (int i = 0; i < 2; i++) {
            int idx = tid + i * 256;
            int row = idx >> 2, cc = idx & 3;
            uint32_t sc = (uint32_t)(cc ^ ((row >> 1) & 3));
            uint32_t so = (uint32_t)row * 64u + sc * 16u;
            size_t ga = (size_t)(by + row) * D + k0 + cc * 8;
            size_t gb = (size_t)(bx + row) * D + k0 + cc * 8;
            cpasync16(sb + so,              Ahi + ga);
            cpasync16(sb + GTILE + so,      Alo + ga);
            cpasync16(sb + 2 * GTILE + so,  Bhi + gb);
            cpasync16(sb + 3 * GTILE + so,  Blo + gb);
        }
    };

    load_stage(0, 0);
    asm volatile("cp.async.commit_group;");
    load_stage(1, 1);
    asm volatile("cp.async.commit_group;");

    const int nchunks = D >> 5;
    for (int c = 0; c < nchunks; c++) {
        if (c + 1 < nchunks) asm volatile("cp.async.wait_group 1;");
        else                 asm volatile("cp.async.wait_group 0;");
        __syncthreads();
        if (c + 2 < nchunks) {
            load_stage(c + 2, (c + 2) % 3);
            asm volatile("cp.async.commit_group;");
        }

        const uint32_t sb = smem + (c % 3) * GSTAGE;

#pragma unroll
        for (int k16 = 0; k16 < 2; k16++) {
            const int lchunk = k16 * 2 + (grp >> 1);
            uint32_t ah[4][4], al[4][4];
#pragma unroll
            for (int fm = 0; fm < 4; fm++) {
                int row = wm + fm * 16 + (grp & 1) * 8 + ri;
                uint32_t ad = sb + (uint32_t)row * 64u
                            + (uint32_t)((lchunk ^ ((row >> 1) & 3)) * 16);
                ldmx4(ah[fm], ad);
                ldmx4(al[fm], ad + GTILE);
            }
#pragma unroll
            for (int fnp = 0; fnp < 2; fnp++) {
                int row = wn + fnp * 16 + (grp & 1) * 8 + ri;
                uint32_t bd = sb + 2 * GTILE + (uint32_t)row * 64u
                            + (uint32_t)((lchunk ^ ((row >> 1) & 3)) * 16);
                uint32_t bh4[4], bl4[4];
                ldmx4(bh4, bd);
                ldmx4(bl4, bd + GTILE);
                uint32_t be[2]  = {bh4[0], bh4[2]};
                uint32_t bo[2]  = {bh4[1], bh4[3]};
                uint32_t ble[2] = {bl4[0], bl4[2]};
                uint32_t blo[2] = {bl4[1], bl4[3]};
#pragma unroll
                for (int fm = 0; fm < 4; fm++) {
                    mma16816(acc[fm][2 * fnp],     ah[fm], be);
                    mma16816(acc[fm][2 * fnp],     al[fm], be);
                    mma16816(acc[fm][2 * fnp],     ah[fm], ble);
                    mma16816(acc[fm][2 * fnp + 1], ah[fm], bo);
                    mma16816(acc[fm][2 * fnp + 1], al[fm], bo);
                    mma16816(acc[fm][2 * fnp + 1], ah[fm], blo);
                }
            }
        }
    }

    // RoPE + split epilogue (scale = 1)
    const int erow = lane >> 2;
    const int ecol = (lane & 3) * 2;
#pragma unroll
    for (int fm = 0; fm < 4; fm++) {
#pragma unroll
        for (int fn = 0; fn < 4; fn++) {
            int col = bx + wn + fn * 8 + ecol;
            int i = (col & 127) >> 1;
#pragma unroll
            for (int half = 0; half < 2; half++) {
                int row = by + wm + fm * 16 + erow + half * 8;
                float cv = cosb[row * 64 + i];
                float sv = sinb[row * 64 + i];
                float t0 = acc[fm][fn][half * 2], t1 = acc[fm][fn][half * 2 + 1];
                float o0 = t0 * cv - t1 * sv;
                float o1 = t0 * sv + t1 * cv;
                __nv_bfloat162 ph, pl;
                split2(o0, o1, ph, pl);
                size_t o = (size_t)row * KVD + col;
                *reinterpret_cast<__nv_bfloat162*>(Chi + o) = ph;
                *reinterpret_cast<__nv_bfloat162*>(Clo + o) = pl;
            }
        }
    }
}

// ---------------- fp16 GEMM: persistent; optional A-lo (2-term) ----------------
// mode 0: fp32 C      mode 1: RoPE+scale+bf16split      mode 2: transpose fp16
#define G16STAGE 24576u   // 3 tiles (A-hi, A-lo, B)

__global__ __launch_bounds__(256, 2) void gemm16_kernel(
    const __half* __restrict__ A16, const __half* __restrict__ Al16,
    const __half* __restrict__ B16,
    float* __restrict__ Cf, __half* __restrict__ C16,
    __nv_bfloat16* __restrict__ Chi, __nv_bfloat16* __restrict__ Clo,
    int Ndim, int Kdim, int mode, int ntx, int ntiles,
    const float* __restrict__ cosb, const float* __restrict__ sinb, float scale)
{
    extern __shared__ char dsm[];
    const uint32_t smem = s2u(dsm);

    const int tid = threadIdx.x;
    const int wid = tid >> 5;
    const int lane = tid & 31;
    const int wm = (wid & 1) * 64;
    const int wn = (wid >> 1) * 32;
    const int grp = lane >> 3;
    const int ri = lane & 7;
    const bool two_term = (Al16 != nullptr);

    for (int tile = blockIdx.x; tile < ntiles; tile += gridDim.x) {
        const int bx = (tile % ntx) * 128;
        const int by = (tile / ntx) * 128;

        float acc[4][4][4];
#pragma unroll
        for (int i = 0; i < 4; i++)
#pragma unroll
            for (int j = 0; j < 4; j++)
#pragma unroll
                for (int e = 0; e < 4; e++) acc[i][j][e] = 0.0f;

        auto load_stage = [&](int c, int stage) {
            const uint32_t sb = smem + stage * G16STAGE;
            const int k0 = c << 5;
#pragma unroll
            for (int i = 0; i < 2; i++) {
                int idx = tid + i * 256;
                int row = idx >> 2, cc = idx & 3;
                uint32_t sc = (uint32_t)(cc ^ ((row >> 1) & 3));
                uint32_t so = (uint32_t)row * 64u + sc * 16u;
                size_t ga = (size_t)(by + row) * Kdim + k0 + cc * 8;
                cpasync16(sb + so, A16 + ga);
                if (two_term) cpasync16(sb + GTILE + so, Al16 + ga);
                cpasync16(sb + 2 * GTILE + so, B16 + (size_t)(bx + row) * Kdim + k0 + cc * 8);
            }
        };

        load_stage(0, 0);
        asm volatile("cp.async.commit_group;");
        load_stage(1, 1);
        asm volatile("cp.async.commit_group;");

        const int nchunks = Kdim >> 5;
        for (int c = 0; c < nchunks; c++) {
            if (c + 1 < nchunks) asm volatile("cp.async.wait_group 1;");
            else                 asm volatile("cp.async.wait_group 0;");
            __syncthreads();
            if (c + 2 < nchunks) {
                load_stage(c + 2, (c + 2) % 3);
                asm volatile("cp.async.commit_group;");
            }

            const uint32_t sb = smem + (c % 3) * G16STAGE;

#pragma unroll
            for (int k16 = 0; k16 < 2; k16++) {
                const int lchunk = k16 * 2 + (grp >> 1);
                uint32_t ah[4][4], al[4][4];
#pragma unroll
                for (int fm = 0; fm < 4; fm++) {
                    int row = wm + fm * 16 + (grp & 1) * 8 + ri;
                    uint32_t ad = sb + (uint32_t)row * 64u
                                + (uint32_t)((lchunk ^ ((row >> 1) & 3)) * 16);
                    ldmx4(ah[fm], ad);
                    if (two_term) ldmx4(al[fm], ad + GTILE);
                }
#pragma unroll
                for (int fnp = 0; fnp < 2; fnp++) {
                    int row = wn + fnp * 16 + (grp & 1) * 8 + ri;
                    uint32_t bd = sb + 2 * GTILE + (uint32_t)row * 64u
                                + (uint32_t)((lchunk ^ ((row >> 1) & 3)) * 16);
                    uint32_t bh4[4];
                    ldmx4(bh4, bd);
                    uint32_t be[2] = {bh4[0], bh4[2]};
                    uint32_t bo[2] = {bh4[1], bh4[3]};
#pragma unroll
                    for (int fm = 0; fm < 4; fm++) {
                        mma16816h(acc[fm][2 * fnp],     ah[fm], be);
                        mma16816h(acc[fm][2 * fnp + 1], ah[fm], bo);
                        if (two_term) {
                            mma16816h(acc[fm][2 * fnp],     al[fm], be);
                            mma16816h(acc[fm][2 * fnp + 1], al[fm], bo);
                        }
                    }
                }
            }
        }

        const int erow = lane >> 2;
        const int ecol = (lane & 3) * 2;
        if (mode == 0) {
#pragma unroll
            for (int fm = 0; fm < 4; fm++) {
#pragma unroll
                for (int fn = 0; fn < 4; fn++) {
                    float* cp0 = Cf + (size_t)(by + wm + fm * 16 + erow) * Ndim + bx + wn + fn * 8 + ecol;
                    float* cp1 = cp0 + 8 * (size_t)Ndim;
                    *reinterpret_cast<float2*>(cp0) = make_float2(acc[fm][fn][0], acc[fm][fn][1]);
                    *reinterpret_cast<float2*>(cp1) = make_float2(acc[fm][fn][2], acc[fm][fn][3]);
                }
            }
        } else if (mode == 1) {
            // RoPE + scale + bf16 split
#pragma unroll
            for (int fm = 0; fm < 4; fm++) {
#pragma unroll
                for (int fn = 0; fn < 4; fn++) {
                    int col = bx + wn + fn * 8 + ecol;
                    int i = (col & 127) >> 1;
#pragma unroll
                    for (int half = 0; half < 2; half++) {
                        int row = by + wm + fm * 16 + erow + half * 8;
                        float cv = cosb[row * 64 + i];
                        float sv = sinb[row * 64 + i];
                        float t0 = acc[fm][fn][half * 2], t1 = acc[fm][fn][half * 2 + 1];
                        float o0 = (t0 * cv - t1 * sv) * scale;
                        float o1 = (t0 * sv + t1 * cv) * scale;
                        __nv_bfloat162 ph, pl;
                        split2(o0, o1, ph, pl);
                        size_t o = (size_t)row * Ndim + col;
                        *reinterpret_cast<__nv_bfloat162*>(Chi + o) = ph;
                        *reinterpret_cast<__nv_bfloat162*>(Clo + o) = pl;
                    }
                }
            }
        } else {
            // transpose fp16: out[col][row], row stride S
#pragma unroll
            for (int fm = 0; fm < 4; fm++) {
#pragma unroll
                for (int fn = 0; fn < 4; fn++) {
                    int col = bx + wn + fn * 8 + ecol;
#pragma unroll
                    for (int half = 0; half < 2; half++) {
                        int row = by + wm + fm * 16 + erow + half * 8;
#pragma unroll
                        for (int e = 0; e < 2; e++) {
                            float v = acc[fm][fn][half * 2 + e];
                            C16[(size_t)(col + e) * S + row] = __float2half_rn(v);
                        }
                    }
                }
            }
        }
        __syncthreads();
    }
}

// ---------------- flash attention: QK bf16 3-term (log2 domain), PV fp16 1-term ----------------
#define KPAD 272u
#define VPAD 144u
#define SM_QH 0u
#define SM_QL 17408u
#define SM_KH 34816u
#define SM_KL 52224u
#define SM_VH 69632u
#define SM_TOT 88064u

__global__ __launch_bounds__(128) void fattn_kernel(
    const __nv_bfloat16* __restrict__ Qh, const __nv_bfloat16* __restrict__ Ql,
    const __nv_bfloat16* __restrict__ Kh, const __nv_bfloat16* __restrict__ Kl,
    const __half* __restrict__ Vt16, __half* __restrict__ O16)
{
    extern __shared__ char dsm[];
    const uint32_t smem = s2u(dsm);
    const int tid = threadIdx.x;
    const int wid = tid >> 5, lane = tid & 31;
    const int qt = gridDim.x - 1 - blockIdx.x;
    const int h = blockIdx.y;
    const int kvh = h / NREP;
    const int q0 = qt * 64;

    const int r = lane >> 2;
    const int cgrp = lane & 3;
    const int grp = lane >> 3;
    const int ri = lane & 7;

    auto loadK = [&](int t) {
#pragma unroll
        for (int i = 0; i < 8; i++) {
            int idx = tid + i * 128;
            int row = idx >> 4, cc = idx & 15;
            size_t g = (size_t)(t * 64 + row) * KVD + kvh * HD + cc * 8;
            cpasync16(smem + SM_KH + row * KPAD + cc * 16, Kh + g);
            cpasync16(smem + SM_KL + row * KPAD + cc * 16, Kl + g);
        }
    };
    auto loadV = [&](int t) {
#pragma unroll
        for (int i = 0; i < 8; i++) {
            int idx = tid + i * 128;
            int row = idx >> 3, cc = idx & 7;
            size_t g = (size_t)(kvh * HD + row) * S + t * 64 + cc * 8;
            cpasync16(smem + SM_VH + row * VPAD + cc * 16, Vt16 + g);
        }
    };

#pragma unroll
    for (int i = 0; i < 8; i++) {
        int idx = tid + i * 128;
        int row = idx >> 4, cc = idx & 15;
        size_t g = (size_t)(q0 + row) * D + h * HD + cc * 8;
        cpasync16(smem + SM_QH + row * KPAD + cc * 16, Qh + g);
        cpasync16(smem + SM_QL + row * KPAD + cc * 16, Ql + g);
    }
    loadK(0);
    asm volatile("cp.async.commit_group;");
    asm volatile("cp.async.wait_group 0;");
    __syncthreads();

    uint32_t qh[8][4], ql[8][4];
    {
        int qrow = wid * 16 + (grp & 1) * 8 + ri;
        uint32_t qbase = smem + SM_QH + (uint32_t)qrow * KPAD + (grp >> 1) * 16u;
#pragma unroll
        for (int ks = 0; ks < 8; ks++) {
            ldmx4(qh[ks], qbase + ks * 32u);
            ldmx4(ql[ks], qbase + ks * 32u + (SM_QL - SM_QH));
        }
    }

    float m0 = -1e30f, m1 = -1e30f, l0 = 0.0f, l1 = 0.0f;
    float oacc[16][4];
#pragma unroll
    for (int f = 0; f < 16; f++)
#pragma unroll
        for (int e = 0; e < 4; e++) oacc[f][e] = 0.0f;

    const int rowA = wid * 16 + r;
    const int rowB = rowA + 8;

    for (int t = 0; t <= qt; t++) {
        if (t > 0) {
            asm volatile("cp.async.wait_group 0;");
            __syncthreads();
        }
        loadV(t);
        asm volatile("cp.async.commit_group;");

        float sacc[8][4];
#pragma unroll
        for (int f = 0; f < 8; f++)
#pragma unroll
            for (int e = 0; e < 4; e++) sacc[f][e] = 0.0f;

#pragma unroll
        for (int ks = 0; ks < 8; ks++) {
#pragma unroll
            for (int fnp = 0; fnp < 4; fnp++) {
                int krow = fnp * 16 + (grp & 1) * 8 + ri;
                uint32_t ka = smem + SM_KH + (uint32_t)krow * KPAD + ks * 32u + (grp >> 1) * 16u;
                uint32_t bh4[4], bl4[4];
                ldmx4(bh4, ka);
                ldmx4(bl4, ka + (SM_KL - SM_KH));
                uint32_t be[2]  = {bh4[0], bh4[2]};
                uint32_t bo[2]  = {bh4[1], bh4[3]};
                uint32_t ble[2] = {bl4[0], bl4[2]};
                uint32_t blo[2] = {bl4[1], bl4[3]};
                mma16816(sacc[2 * fnp],     qh[ks], be);
                mma16816(sacc[2 * fnp],     ql[ks], be);
                mma16816(sacc[2 * fnp],     qh[ks], ble);
                mma16816(sacc[2 * fnp + 1], qh[ks], bo);
                mma16816(sacc[2 * fnp + 1], ql[ks], bo);
                mma16816(sacc[2 * fnp + 1], qh[ks], blo);
            }
        }

        if (t == qt) {
#pragma unroll
            for (int fn = 0; fn < 8; fn++) {
                int c0 = fn * 8 + cgrp * 2;
                if (c0 > rowA) sacc[fn][0] = -1e30f;
                if (c0 + 1 > rowA) sacc[fn][1] = -1e30f;
                if (c0 > rowB) sacc[fn][2] = -1e30f;
                if (c0 + 1 > rowB) sacc[fn][3] = -1e30f;
            }
        }

        float tm0 = -1e30f, tm1 = -1e30f;
#pragma unroll
        for (int fn = 0; fn < 8; fn++) {
            tm0 = fmaxf(tm0, fmaxf(sacc[fn][0], sacc[fn][1]));
            tm1 = fmaxf(tm1, fmaxf(sacc[fn][2], sacc[fn][3]));
        }
        tm0 = fmaxf(tm0, __shfl_xor_sync(0xFFFFFFFFu, tm0, 1));
        tm0 = fmaxf(tm0, __shfl_xor_sync(0xFFFFFFFFu, tm0, 2));
        tm1 = fmaxf(tm1, __shfl_xor_sync(0xFFFFFFFFu, tm1, 1));
        tm1 = fmaxf(tm1, __shfl_xor_sync(0xFFFFFFFFu, tm1, 2));

        float mn0 = fmaxf(m0, tm0), mn1 = fmaxf(m1, tm1);
        float corr0 = exp2f(m0 - mn0), corr1 = exp2f(m1 - mn1);
        m0 = mn0; m1 = mn1;

        float rs0 = 0.0f, rs1 = 0.0f;
#pragma unroll
        for (int fn = 0; fn < 8; fn++) {
            sacc[fn][0] = exp2f(sacc[fn][0] - m0);
            sacc[fn][1] = exp2f(sacc[fn][1] - m0);
            sacc[fn][2] = exp2f(sacc[fn][2] - m1);
            sacc[fn][3] = exp2f(sacc[fn][3] - m1);
            rs0 += sacc[fn][0] + sacc[fn][1];
            rs1 += sacc[fn][2] + sacc[fn][3];
        }
        rs0 += __shfl_xor_sync(0xFFFFFFFFu, rs0, 1);
        rs0 += __shfl_xor_sync(0xFFFFFFFFu, rs0, 2);
        rs1 += __shfl_xor_sync(0xFFFFFFFFu, rs1, 1);
        rs1 += __shfl_xor_sync(0xFFFFFFFFu, rs1, 2);
        l0 = l0 * corr0 + rs0;
        l1 = l1 * corr1 + rs1;

#pragma unroll
        for (int f = 0; f < 16; f++) {
            oacc[f][0] *= corr0; oacc[f][1] *= corr0;
            oacc[f][2] *= corr1; oacc[f][3] *= corr1;
        }

        asm volatile("cp.async.wait_group 0;");
        __syncthreads();
        if (t < qt) {
            loadK(t + 1);
            asm volatile("cp.async.commit_group;");
        }

        // ---- O += P V (P single fp16, V single fp16) ----
#pragma unroll
        for (int kk = 0; kk < 4; kk++) {
            uint32_t aph[4];
#pragma unroll
            for (int half = 0; half < 2; half++) {
                const float* sp = sacc[2 * kk + half];
                aph[half * 2 + 0] = pack_f16(sp[0], sp[1]);
                aph[half * 2 + 1] = pack_f16(sp[2], sp[3]);
            }
#pragma unroll
            for (int fnp = 0; fnp < 8; fnp++) {
                int vrow = fnp * 16 + (grp & 1) * 8 + ri;
                uint32_t va = smem + SM_VH + (uint32_t)vrow * VPAD + kk * 32u + (grp >> 1) * 16u;
                uint32_t bh4[4];
                ldmx4(bh4, va);
                uint32_t be[2] = {bh4[0], bh4[2]};
                uint32_t bo[2] = {bh4[1], bh4[3]};
                mma16816h(oacc[2 * fnp],     aph, be);
                mma16816h(oacc[2 * fnp + 1], aph, bo);
            }
        }
    }

    float inv0 = 1.0f / l0, inv1 = 1.0f / l1;
    const size_t gr0 = (size_t)(q0 + rowA) * D + h * HD + cgrp * 2;
    const size_t gr1 = (size_t)(q0 + rowB) * D + h * HD + cgrp * 2;
#pragma unroll
    for (int fn = 0; fn < 16; fn++) {
        *reinterpret_cast<__half2*>(O16 + gr0 + fn * 8) =
            __floats2half2_rn(oacc[fn][0] * inv0, oacc[fn][1] * inv0);
        *reinterpret_cast<__half2*>(O16 + gr1 + fn * 8) =
            __floats2half2_rn(oacc[fn][2] * inv1, oacc[fn][3] * inv1);
    }
}

// ---------------- launch ----------------
extern "C" void kernel_launch(void* const* d_in, const int* in_sizes, int n_in,
                              void* d_out, int out_size)
{
    const float* x    = (const float*)d_in[0];
    const float* wq   = (const float*)d_in[1];
    const float* wk   = (const float*)d_in[2];
    const float* wv   = (const float*)d_in[3];
    const float* wo   = (const float*)d_in[4];
    const float* cosb = (const float*)d_in[5];
    const float* sinb = (const float*)d_in[6];
    float* out = (float*)d_out;

    __nv_bfloat16 *xhi, *xlo, *qhi, *qlo, *khi, *klo, *wkhi, *wklo;
    __half *x16h, *x16l, *a16, *vt16, *wq16, *wv16, *wo16;
    cudaGetSymbolAddress((void**)&xhi, g_xhi);   cudaGetSymbolAddress((void**)&xlo, g_xlo);
    cudaGetSymbolAddress((void**)&x16h, g_x16h); cudaGetSymbolAddress((void**)&x16l, g_x16l);
    cudaGetSymbolAddress((void**)&a16, g_a16);
    cudaGetSymbolAddress((void**)&qhi, g_qhi);   cudaGetSymbolAddress((void**)&qlo, g_qlo);
    cudaGetSymbolAddress((void**)&khi, g_khi);   cudaGetSymbolAddress((void**)&klo, g_klo);
    cudaGetSymbolAddress((void**)&vt16, g_vt16);
    cudaGetSymbolAddress((void**)&wq16, g_wq16);
    cudaGetSymbolAddress((void**)&wkhi, g_wkhi); cudaGetSymbolAddress((void**)&wklo, g_wklo);
    cudaGetSymbolAddress((void**)&wv16, g_wv16); cudaGetSymbolAddress((void**)&wo16, g_wo16);

    const int shmem = 3 * (int)GSTAGE;        // 98304
    const int shmem16 = 3 * (int)G16STAGE;    // 73728
    cudaFuncSetAttribute(gemmk_kernel, cudaFuncAttributeMaxDynamicSharedMemorySize, shmem);
    cudaFuncSetAttribute(gemm16_kernel, cudaFuncAttributeMaxDynamicSharedMemorySize, shmem16);
    cudaFuncSetAttribute(fattn_kernel, cudaFuncAttributeMaxDynamicSharedMemorySize, (int)SM_TOT);

    // scores computed in log2 domain: fold log2(e) into Q scale
    const float qscale = 0.08838834764831845f * 1.4426950408889634f;

    // input conversions
    xsplit_all<<<(S * D / 4 + 255) / 256, 256>>>(x, xhi, xlo, x16h, x16l, S * D / 4);
    tsplit16_kernel<<<dim3(D / 32, D / 32), dim3(32, 8)>>>(wq, wq16, D, D);
    tsplit_kernel<<<dim3(KVD / 32, D / 32), dim3(32, 8)>>>(wk, wkhi, wklo, D, KVD);
    tsplit16_kernel<<<dim3(KVD / 32, D / 32), dim3(32, 8)>>>(wv, wv16, D, KVD);
    tsplit16_kernel<<<dim3(D / 32, D / 32), dim3(32, 8)>>>(wo, wo16, D, D);

    // Q projection: fp16 2-term, fused RoPE + qscale + bf16 split (persistent)
    gemm16_kernel<<<PGRID, 256, shmem16>>>(
        x16h, x16l, wq16, nullptr, nullptr, qhi, qlo,
        D, D, 1, D / 128, (D / 128) * (S / 128), cosb, sinb, qscale);

    // K projection: bf16 3-term, fused RoPE + bf16 split
    gemmk_kernel<<<dim3(KVD / 128, S / 128), 256, shmem>>>(
        xhi, xlo, wkhi, wklo, khi, klo, cosb, sinb);

    // V projection: fp16 1-term, fused transpose to fp16 [KVD][S]
    gemm16_kernel<<<KVD / 128 * (S / 128), 256, shmem16>>>(
        x16h, nullptr, wv16, nullptr, vt16, nullptr, nullptr,
        KVD, D, 2, KVD / 128, KVD / 128 * (S / 128), nullptr, nullptr, 1.0f);

    // flash attention (log2-domain softmax) -> fp16
    fattn_kernel<<<dim3(S / 64, H), 128, SM_TOT>>>(qhi, qlo, khi, klo, vt16, a16);

    // output projection: fp16 1-term, fp32 out (persistent)
    gemm16_kernel<<<PGRID, 256, shmem16>>>(
        a16, nullptr, wo16, out, nullptr, nullptr, nullptr,
        D, D, 0, D / 128, (D / 128) * (S / 128), nullptr, nullptr, 1.0f);
}

// round 11
// speedup vs baseline: 1.4650x; 1.0653x over previous
#include <cuda_runtime.h>
#include <cuda_bf16.h>
#include <cuda_fp16.h>
#include <cstdint>

#define S 2048
#define D 4096
#define H 32
#define KVH 8
#define HD 128
#define NREP (H / KVH)
#define KVD (KVH * KVH * 16)  // 1024
#undef KVD
#define KVD (KVH * HD)
#define PGRID 304

// ---------------- scratch (static device arrays; no allocation) ----------------
__device__ __nv_bfloat16 g_xhi[S * D], g_xlo[S * D];
__device__ __half        g_x16h[S * D], g_x16l[S * D];
__device__ __half        g_a16[S * D];
__device__ __nv_bfloat16 g_qhi[S * D], g_qlo[S * D];
__device__ __nv_bfloat16 g_khi[S * KVD], g_klo[S * KVD];
__device__ __half        g_vt16[KVD * S];
__device__ __half        g_wq16[D * D];
__device__ __nv_bfloat16 g_wkhi[KVD * D], g_wklo[KVD * D];
__device__ __half        g_wv16[KVD * D];
__device__ __half        g_wo16[D * D];
__device__ int           g_ctr;

// ---------------- helpers ----------------
__device__ __forceinline__ uint32_t s2u(const void* p) {
    uint32_t a;
    asm("{ .reg .u64 t; cvta.to.shared.u64 t, %1; cvt.u32.u64 %0, t; }" : "=r"(a) : "l"(p));
    return a;
}
__device__ __forceinline__ void cpasync16(uint32_t saddr, const void* gaddr) {
    asm volatile("cp.async.cg.shared.global [%0], [%1], 16;" :: "r"(saddr), "l"(gaddr));
}
__device__ __forceinline__ void ldmx4(uint32_t* r, uint32_t addr) {
    asm volatile("ldmatrix.sync.aligned.m8n8.x4.shared.b16 {%0,%1,%2,%3}, [%4];"
                 : "=r"(r[0]), "=r"(r[1]), "=r"(r[2]), "=r"(r[3]) : "r"(addr));
}
__device__ __forceinline__ void mma16816(float* d, const uint32_t* a, const uint32_t* b) {
    asm volatile(
        "mma.sync.aligned.m16n8k16.row.col.f32.bf16.bf16.f32 "
        "{%0,%1,%2,%3}, {%4,%5,%6,%7}, {%8,%9}, {%0,%1,%2,%3};"
        : "+f"(d[0]), "+f"(d[1]), "+f"(d[2]), "+f"(d[3])
        : "r"(a[0]), "r"(a[1]), "r"(a[2]), "r"(a[3]), "r"(b[0]), "r"(b[1]));
}
__device__ __forceinline__ void mma16816h(float* d, const uint32_t* a, const uint32_t* b) {
    asm volatile(
        "mma.sync.aligned.m16n8k16.row.col.f32.f16.f16.f32 "
        "{%0,%1,%2,%3}, {%4,%5,%6,%7}, {%8,%9}, {%0,%1,%2,%3};"
        : "+f"(d[0]), "+f"(d[1]), "+f"(d[2]), "+f"(d[3])
        : "r"(a[0]), "r"(a[1]), "r"(a[2]), "r"(a[3]), "r"(b[0]), "r"(b[1]));
}
__device__ __forceinline__ uint32_t pack_f16(float x, float y) {
    __half2 t = __floats2half2_rn(x, y);
    return *reinterpret_cast<uint32_t*>(&t);
}
__device__ __forceinline__ void split2(float v0, float v1, __nv_bfloat162& ph, __nv_bfloat162& pl) {
    __nv_bfloat16 h0 = __float2bfloat16(v0), h1 = __float2bfloat16(v1);
    ph.x = h0; ph.y = h1;
    pl.x = __float2bfloat16(v0 - __bfloat162float(h0));
    pl.y = __float2bfloat16(v1 - __bfloat162float(h1));
}
__device__ __forceinline__ void split2h(float v0, float v1, __half2& ph, __half2& pl) {
    __half h0 = __float2half_rn(v0), h1 = __float2half_rn(v1);
    ph = __halves2half2(h0, h1);
    pl = __halves2half2(__float2half_rn(v0 - __half2float(h0)),
                        __float2half_rn(v1 - __half2float(h1)));
}

// ---------------- counter reset ----------------
__global__ void reset_ctr() { g_ctr = 0; }

// ---------------- x: fp32 -> bf16 hi/lo + fp16 hi/lo ----------------
__global__ void xsplit_all(const float* __restrict__ in,
                           __nv_bfloat16* __restrict__ bh, __nv_bfloat16* __restrict__ bl,
                           __half* __restrict__ fh, __half* __restrict__ fl, int n4)
{
    int i = blockIdx.x * blockDim.x + threadIdx.x;
    if (i >= n4) return;
    float4 v = reinterpret_cast<const float4*>(in)[i];
    __nv_bfloat162 ph, pl;
    split2(v.x, v.y, ph, pl);
    reinterpret_cast<__nv_bfloat162*>(bh)[2 * i] = ph;
    reinterpret_cast<__nv_bfloat162*>(bl)[2 * i] = pl;
    split2(v.z, v.w, ph, pl);
    reinterpret_cast<__nv_bfloat162*>(bh)[2 * i + 1] = ph;
    reinterpret_cast<__nv_bfloat162*>(bl)[2 * i + 1] = pl;
    __half2 hh, hl;
    split2h(v.x, v.y, hh, hl);
    reinterpret_cast<__half2*>(fh)[2 * i] = hh;
    reinterpret_cast<__half2*>(fl)[2 * i] = hl;
    split2h(v.z, v.w, hh, hl);
    reinterpret_cast<__half2*>(fh)[2 * i + 1] = hh;
    reinterpret_cast<__half2*>(fl)[2 * i + 1] = hl;
}

// ---------------- transpose+split: W[K,N] fp32 -> hi/lo bf16 [N,K] ----------------
__global__ void tsplit_kernel(const float* __restrict__ w,
                              __nv_bfloat16* __restrict__ hi,
                              __nv_bfloat16* __restrict__ lo, int K, int N)
{
    __shared__ float t[32][33];
    int n0 = blockIdx.x * 32, k0 = blockIdx.y * 32;
    int tx = threadIdx.x, ty = threadIdx.y;
    for (int r = ty; r < 32; r += 8)
        t[r][tx] = w[(size_t)(k0 + r) * N + n0 + tx];
    __syncthreads();
    for (int r = ty; r < 32; r += 8) {
        float v = t[tx][r];
        __nv_bfloat16 h = __float2bfloat16(v);
        __nv_bfloat16 l = __float2bfloat16(v - __bfloat162float(h));
        size_t o = (size_t)(n0 + r) * K + k0 + tx;
        hi[o] = h; lo[o] = l;
    }
}

// ---------------- transpose: W[K,N] fp32 -> fp16 [N,K] ----------------
__global__ void tsplit16_kernel(const float* __restrict__ w,
                                __half* __restrict__ out, int K, int N)
{
    __shared__ float t[32][33];
    int n0 = blockIdx.x * 32, k0 = blockIdx.y * 32;
    int tx = threadIdx.x, ty = threadIdx.y;
    for (int r = ty; r < 32; r += 8)
        t[r][tx] = w[(size_t)(k0 + r) * N + n0 + tx];
    __syncthreads();
    for (int r = ty; r < 32; r += 8)
        out[(size_t)(n0 + r) * K + k0 + tx] = __float2half_rn(t[tx][r]);
}

#define GTILE  8192u
#define GSTAGE 32768u

// tile map: [0,128) K tiles (heavy), [128,640) Q tiles, [640,768) V tiles (light)
#define NT_K 128
#define NT_Q 512
#define NT_TOT 768

// ---------------- unified persistent projection kernel ----------------
__global__ __launch_bounds__(256, 2) void proj_kernel(
    const __nv_bfloat16* __restrict__ Xhi, const __nv_bfloat16* __restrict__ Xlo,
    const __half* __restrict__ X16h, const __half* __restrict__ X16l,
    const __half* __restrict__ Wq16,
    const __nv_bfloat16* __restrict__ Wkhi, const __nv_bfloat16* __restrict__ Wklo,
    const __half* __restrict__ Wv16,
    __nv_bfloat16* __restrict__ Qhi, __nv_bfloat16* __restrict__ Qlo,
    __nv_bfloat16* __restrict__ Khi, __nv_bfloat16* __restrict__ Klo,
    __half* __restrict__ Vt16,
    const float* __restrict__ cosb, const float* __restrict__ sinb, float qscale)
{
    extern __shared__ char dsm[];
    const uint32_t smem = s2u(dsm);
    __shared__ int s_tile;

    const int tid = threadIdx.x;
    const int wid = tid >> 5;
    const int lane = tid & 31;
    const int wm = (wid & 1) * 64;
    const int wn = (wid >> 1) * 32;
    const int grp = lane >> 3;
    const int ri = lane & 7;
    const int erow = lane >> 2;
    const int ecol = (lane & 3) * 2;
    const int nchunks = D >> 5;

    while (true) {
        __syncthreads();
        if (tid == 0) s_tile = atomicAdd(&g_ctr, 1);
        __syncthreads();
        const int t = s_tile;
        if (t >= NT_TOT) break;

        float acc[4][4][4];
#pragma unroll
        for (int i = 0; i < 4; i++)
#pragma unroll
            for (int j = 0; j < 4; j++)
#pragma unroll
                for (int e = 0; e < 4; e++) acc[i][j][e] = 0.0f;

        if (t < NT_K) {
            // ---- K tile: bf16 3-term ----
            const int bx = (t & 7) * 128;
            const int by = (t >> 3) * 128;

            auto load_stage = [&](int c, int stage) {
                const uint32_t sb = smem + stage * GSTAGE;
                const int k0 = c << 5;
#pragma unroll
                for (int i = 0; i < 2; i++) {
                    int idx = tid + i * 256;
                    int row = idx >> 2, cc = idx & 3;
                    uint32_t sc = (uint32_t)(cc ^ ((row >> 1) & 3));
                    uint32_t so = (uint32_t)row * 64u + sc * 16u;
                    size_t ga = (size_t)(by + row) * D + k0 + cc * 8;
                    size_t gb = (size_t)(bx + row) * D + k0 + cc * 8;
                    cpasync16(sb + so,              Xhi + ga);
                    cpasync16(sb + GTILE + so,      Xlo + ga);
                    cpasync16(sb + 2 * GTILE + so,  Wkhi + gb);
                    cpasync16(sb + 3 * GTILE + so,  Wklo + gb);
                }
            };

            load_stage(0, 0);
            asm volatile("cp.async.commit_group;");
            load_stage(1, 1);
            asm volatile("cp.async.commit_group;");

            for (int c = 0; c < nchunks; c++) {
                if (c + 1 < nchunks) asm volatile("cp.async.wait_group 1;");
                else                 asm volatile("cp.async.wait_group 0;");
                __syncthreads();
                if (c + 2 < nchunks) {
                    load_stage(c + 2, (c + 2) % 3);
                    asm volatile("cp.async.commit_group;");
                }
                const uint32_t sb = smem + (c % 3) * GSTAGE;
#pragma unroll
                for (int k16 = 0; k16 < 2; k16++) {
                    const int lchunk = k16 * 2 + (grp >> 1);
                    uint32_t ah[4][4], al[4][4];
#pragma unroll
                    for (int fm = 0; fm < 4; fm++) {
                        int row = wm + fm * 16 + (grp & 1) * 8 + ri;
                        uint32_t ad = sb + (uint32_t)row * 64u
                                    + (uint32_t)((lchunk ^ ((row >> 1) & 3)) * 16);
                        ldmx4(ah[fm], ad);
                        ldmx4(al[fm], ad + GTILE);
                    }
#pragma unroll
                    for (int fnp = 0; fnp < 2; fnp++) {
                        int row = wn + fnp * 16 + (grp & 1) * 8 + ri;
                        uint32_t bd = sb + 2 * GTILE + (uint32_t)row * 64u
                                    + (uint32_t)((lchunk ^ ((row >> 1) & 3)) * 16);
                        uint32_t bh4[4], bl4[4];
                        ldmx4(bh4, bd);
                        ldmx4(bl4, bd + GTILE);
                        uint32_t be[2]  = {bh4[0], bh4[2]};
                        uint32_t bo[2]  = {bh4[1], bh4[3]};
                        uint32_t ble[2] = {bl4[0], bl4[2]};
                        uint32_t blo[2] = {bl4[1], bl4[3]};
#pragma unroll
                        for (int fm = 0; fm < 4; fm++) {
                            mma16816(acc[fm][2 * fnp],     ah[fm], be);
                            mma16816(acc[fm][2 * fnp],     al[fm], be);
                            mma16816(acc[fm][2 * fnp],     ah[fm], ble);
                            mma16816(acc[fm][2 * fnp + 1], ah[fm], bo);
                            mma16816(acc[fm][2 * fnp + 1], al[fm], bo);
                            mma16816(acc[fm][2 * fnp + 1], ah[fm], blo);
                        }
                    }
                }
            }

            // RoPE + bf16 split -> K
#pragma unroll
            for (int fm = 0; fm < 4; fm++) {
#pragma unroll
                for (int fn = 0; fn < 4; fn++) {
                    int col = bx + wn + fn * 8 + ecol;
                    int i = (col & 127) >> 1;
#pragma unroll
                    for (int half = 0; half < 2; half++) {
                        int row = by + wm + fm * 16 + erow + half * 8;
                        float cv = cosb[row * 64 + i];
                        float sv = sinb[row * 64 + i];
                        float t0 = acc[fm][fn][half * 2], t1 = acc[fm][fn][half * 2 + 1];
                        float o0 = t0 * cv - t1 * sv;
                        float o1 = t0 * sv + t1 * cv;
                        __nv_bfloat162 ph, pl;
                        split2(o0, o1, ph, pl);
                        size_t o = (size_t)row * KVD + col;
                        *reinterpret_cast<__nv_bfloat162*>(Khi + o) = ph;
                        *reinterpret_cast<__nv_bfloat162*>(Klo + o) = pl;
                    }
                }
            }
        } else if (t < NT_K + NT_Q) {
            // ---- Q tile: fp16 2-term ----
            const int q = t - NT_K;
            const int bx = (q & 31) * 128;
            const int by = (q >> 5) * 128;

            auto load_stage = [&](int c, int stage) {
                const uint32_t sb = smem + stage * GSTAGE;
                const int k0 = c << 5;
#pragma unroll
                for (int i = 0; i < 2; i++) {
                    int idx = tid + i * 256;
                    int row = idx >> 2, cc = idx & 3;
                    uint32_t sc = (uint32_t)(cc ^ ((row >> 1) & 3));
                    uint32_t so = (uint32_t)row * 64u + sc * 16u;
                    size_t ga = (size_t)(by + row) * D + k0 + cc * 8;
                    cpasync16(sb + so,             X16h + ga);
                    cpasync16(sb + GTILE + so,     X16l + ga);
                    cpasync16(sb + 2 * GTILE + so, Wq16 + (size_t)(bx + row) * D + k0 + cc * 8);
                }
            };

            load_stage(0, 0);
            asm volatile("cp.async.commit_group;");
            load_stage(1, 1);
            asm volatile("cp.async.commit_group;");

            for (int c = 0; c < nchunks; c++) {
                if (c + 1 < nchunks) asm volatile("cp.async.wait_group 1;");
                else                 asm volatile("cp.async.wait_group 0;");
                __syncthreads();
                if (c + 2 < nchunks) {
                    load_stage(c + 2, (c + 2) % 3);
                    asm volatile("cp.async.commit_group;");
                }
                const uint32_t sb = smem + (c % 3) * GSTAGE;
#pragma unroll
                for (int k16 = 0; k16 < 2; k16++) {
                    const int lchunk = k16 * 2 + (grp >> 1);
                    uint32_t ah[4][4], al[4][4];
#pragma unroll
                    for (int fm = 0; fm < 4; fm++) {
                        int row = wm + fm * 16 + (grp & 1) * 8 + ri;
                        uint32_t ad = sb + (uint32_t)row * 64u
                                    + (uint32_t)((lchunk ^ ((row >> 1) & 3)) * 16);
                        ldmx4(ah[fm], ad);
                        ldmx4(al[fm], ad + GTILE);
                    }
#pragma unroll
                    for (int fnp = 0; fnp < 2; fnp++) {
                        int row = wn + fnp * 16 + (grp & 1) * 8 + ri;
                        uint32_t bd = sb + 2 * GTILE + (uint32_t)row * 64u
                                    + (uint32_t)((lchunk ^ ((row >> 1) & 3)) * 16);
                        uint32_t bh4[4];
                        ldmx4(bh4, bd);
                        uint32_t be[2] = {bh4[0], bh4[2]};
                        uint32_t bo[2] = {bh4[1], bh4[3]};
#pragma unroll
                        for (int fm = 0; fm < 4; fm++) {
                            mma16816h(acc[fm][2 * fnp],     ah[fm], be);
                            mma16816h(acc[fm][2 * fnp],     al[fm], be);
                            mma16816h(acc[fm][2 * fnp + 1], ah[fm], bo);
                            mma16816h(acc[fm][2 * fnp + 1], al[fm], bo);
                        }
                    }
                }
            }

            // RoPE + qscale + bf16 split -> Q
#pragma unroll
            for (int fm = 0; fm < 4; fm++) {
#pragma unroll
                for (int fn = 0; fn < 4; fn++) {
                    int col = bx + wn + fn * 8 + ecol;
                    int i = (col & 127) >> 1;
#pragma unroll
                    for (int half = 0; half < 2; half++) {
                        int row = by + wm + fm * 16 + erow + half * 8;
                        float cv = cosb[row * 64 + i];
                        float sv = sinb[row * 64 + i];
                        float t0 = acc[fm][fn][half * 2], t1 = acc[fm][fn][half * 2 + 1];
                        float o0 = (t0 * cv - t1 * sv) * qscale;
                        float o1 = (t0 * sv + t1 * cv) * qscale;
                        __nv_bfloat162 ph, pl;
                        split2(o0, o1, ph, pl);
                        size_t o = (size_t)row * D + col;
                        *reinterpret_cast<__nv_bfloat162*>(Qhi + o) = ph;
                        *reinterpret_cast<__nv_bfloat162*>(Qlo + o) = pl;
                    }
                }
            }
        } else {
            // ---- V tile: fp16 1-term, transpose epilogue ----
            const int v = t - NT_K - NT_Q;
            const int bx = (v & 7) * 128;
            const int by = (v >> 3) * 128;

            auto load_stage = [&](int c, int stage) {
                const uint32_t sb = smem + stage * GSTAGE;
                const int k0 = c << 5;
#pragma unroll
                for (int i = 0; i < 2; i++) {
                    int idx = tid + i * 256;
                    int row = idx >> 2, cc = idx & 3;
                    uint32_t sc = (uint32_t)(cc ^ ((row >> 1) & 3));
                    uint32_t so = (uint32_t)row * 64u + sc * 16u;
                    cpasync16(sb + so,             X16h + (size_t)(by + row) * D + k0 + cc * 8);
                    cpasync16(sb + 2 * GTILE + so, Wv16 + (size_t)(bx + row) * D + k0 + cc * 8);
                }
            };

            load_stage(0, 0);
            asm volatile("cp.async.commit_group;");
            load_stage(1, 1);
            asm volatile("cp.async.commit_group;");

            for (int c = 0; c < nchunks; c++) {
                if (c + 1 < nchunks) asm volatile("cp.async.wait_group 1;");
                else                 asm volatile("cp.async.wait_group 0;");
                __syncthreads();
                if (c + 2 < nchunks) {
                    load_stage(c + 2, (c + 2) % 3);
                    asm volatile("cp.async.commit_group;");
                }
                const uint32_t sb = smem + (c % 3) * GSTAGE;
#pragma unroll
                for (int k16 = 0; k16 < 2; k16++) {
                    const int lchunk = k16 * 2 + (grp >> 1);
                    uint32_t ah[4][4];
#pragma unroll
                    for (int fm = 0; fm < 4; fm++) {
                        int row = wm + fm * 16 + (grp & 1) * 8 + ri;
                        uint32_t ad = sb + (uint32_t)row * 64u
                                    + (uint32_t)((lchunk ^ ((row >> 1) & 3)) * 16);
                        ldmx4(ah[fm], ad);
                    }
#pragma unroll
                    for (int fnp = 0; fnp < 2; fnp++) {
                        int row = wn + fnp * 16 + (grp & 1) * 8 + ri;
                        uint32_t bd = sb + 2 * GTILE + (uint32_t)row * 64u
                                    + (uint32_t)((lchunk ^ ((row >> 1) & 3)) * 16);
                        uint32_t bh4[4];
                        ldmx4(bh4, bd);
                        uint32_t be[2] = {bh4[0], bh4[2]};
                        uint32_t bo[2] = {bh4[1], bh4[3]};
#pragma unroll
                        for (int fm = 0; fm < 4; fm++) {
                            mma16816h(acc[fm][2 * fnp],     ah[fm], be);
                            mma16816h(acc[fm][2 * fnp + 1], ah[fm], bo);
                        }
                    }
                }
            }

            // transpose fp16 -> Vt
#pragma unroll
            for (int fm = 0; fm < 4; fm++) {
#pragma unroll
                for (int fn = 0; fn < 4; fn++) {
                    int col = bx + wn + fn * 8 + ecol;
#pragma unroll
                    for (int half = 0; half < 2; half++) {
                        int row = by + wm + fm * 16 + erow + half * 8;
#pragma unroll
                        for (int e = 0; e < 2; e++) {
                            float vv = acc[fm][fn][half * 2 + e];
                            Vt16[(size_t)(col + e) * S + row] = __float2half_rn(vv);
                        }
                    }
                }
            }
        }
    }
}

// ---------------- fp16 1-term GEMM: O projection, persistent ----------------
#define G16STAGE 16384u

__global__ __launch_bounds__(256, 2) void gemmo_kernel(
    const __half* __restrict__ A16, const __half* __restrict__ B16,
    float* __restrict__ Cf, int Ndim, int Kdim, int ntx, int ntiles)
{
    extern __shared__ char dsm[];
    const uint32_t smem = s2u(dsm);

    const int tid = threadIdx.x;
    const int wid = tid >> 5;
    const int lane = tid & 31;
    const int wm = (wid & 1) * 64;
    const int wn = (wid >> 1) * 32;
    const int grp = lane >> 3;
    const int ri = lane & 7;

    for (int tile = blockIdx.x; tile < ntiles; tile += gridDim.x) {
        const int bx = (tile % ntx) * 128;
        const int by = (tile / ntx) * 128;

        float acc[4][4][4];
#pragma unroll
        for (int i = 0; i < 4; i++)
#pragma unroll
            for (int j = 0; j < 4; j++)
#pragma unroll
                for (int e = 0; e < 4; e++) acc[i][j][e] = 0.0f;

        auto load_stage = [&](int c, int stage) {
            const uint32_t sb = smem + stage * G16STAGE;
            const int k0 = c << 5;
#pragma unroll
            for (int i = 0; i < 2; i++) {
                int idx = tid + i * 256;
                int row = idx >> 2, cc = idx & 3;
                uint32_t sc = (uint32_t)(cc ^ ((row >> 1) & 3));
                uint32_t so = (uint32_t)row * 64u + sc * 16u;
                cpasync16(sb + so,         A16 + (size_t)(by + row) * Kdim + k0 + cc * 8);
                cpasync16(sb + GTILE + so, B16 + (size_t)(bx + row) * Kdim + k0 + cc * 8);
            }
        };

        load_stage(0, 0);
        asm volatile("cp.async.commit_group;");
        load_stage(1, 1);
        asm volatile("cp.async.commit_group;");

        const int nchunks = Kdim >> 5;
        for (int c = 0; c < nchunks; c++) {
            if (c + 1 < nchunks) asm volatile("cp.async.wait_group 1;");
            else                 asm volatile("cp.async.wait_group 0;");
            __syncthreads();
            if (c + 2 < nchunks) {
                load_stage(c + 2, (c + 2) % 3);
                asm volatile("cp.async.commit_group;");
            }
            const uint32_t sb = smem + (c % 3) * G16STAGE;
#pragma unroll
            for (int k16 = 0; k16 < 2; k16++) {
                const int lchunk = k16 * 2 + (grp >> 1);
                uint32_t ah[4][4];
#pragma unroll
                for (int fm = 0; fm < 4; fm++) {
                    int row = wm + fm * 16 + (grp & 1) * 8 + ri;
                    uint32_t ad = sb + (uint32_t)row * 64u
                                + (uint32_t)((lchunk ^ ((row >> 1) & 3)) * 16);
                    ldmx4(ah[fm], ad);
                }
#pragma unroll
                for (int fnp = 0; fnp < 2; fnp++) {
                    int row = wn + fnp * 16 + (grp & 1) * 8 + ri;
                    uint32_t bd = sb + GTILE + (uint32_t)row * 64u
                                + (uint32_t)((lchunk ^ ((row >> 1) & 3)) * 16);
                    uint32_t bh4[4];
                    ldmx4(bh4, bd);
                    uint32_t be[2] = {bh4[0], bh4[2]};
                    uint32_t bo[2] = {bh4[1], bh4[3]};
#pragma unroll
                    for (int fm = 0; fm < 4; fm++) {
                        mma16816h(acc[fm][2 * fnp],     ah[fm], be);
                        mma16816h(acc[fm][2 * fnp + 1], ah[fm], bo);
                    }
                }
            }
        }

        const int erow = lane >> 2;
        const int ecol = (lane & 3) * 2;
#pragma unroll
        for (int fm = 0; fm < 4; fm++) {
#pragma unroll
            for (int fn = 0; fn < 4; fn++) {
                float* cp0 = Cf + (size_t)(by + wm + fm * 16 + erow) * Ndim + bx + wn + fn * 8 + ecol;
                float* cp1 = cp0 + 8 * (size_t)Ndim;
                *reinterpret_cast<float2*>(cp0) = make_float2(acc[fm][fn][0], acc[fm][fn][1]);
                *reinterpret_cast<float2*>(cp1) = make_float2(acc[fm][fn][2], acc[fm][fn][3]);
            }
        }
        __syncthreads();
    }
}

// ---------------- flash attention: QK bf16 3-term (log2 domain), PV fp16 1-term ----------------
#define KPAD 272u
#define VPAD 144u
#define SM_QH 0u
#define SM_QL 17408u
#define SM_KH 34816u
#define SM_KL 52224u
#define SM_VH 69632u
#define SM_TOT 88064u

__global__ __launch_bounds__(128) void fattn_kernel(
    const __nv_bfloat16* __restrict__ Qh, const __nv_bfloat16* __restrict__ Ql,
    const __nv_bfloat16* __restrict__ Kh, const __nv_bfloat16* __restrict__ Kl,
    const __half* __restrict__ Vt16, __half* __restrict__ O16)
{
    extern __shared__ char dsm[];
    const uint32_t smem = s2u(dsm);
    const int tid = threadIdx.x;
    const int wid = tid >> 5, lane = tid & 31;
    const int qt = gridDim.x - 1 - blockIdx.x;
    const int h = blockIdx.y;
    const int kvh = h / NREP;
    const int q0 = qt * 64;

    const int r = lane >> 2;
    const int cgrp = lane & 3;
    const int grp = lane >> 3;
    const int ri = lane & 7;

    auto loadK = [&](int t) {
#pragma unroll
        for (int i = 0; i < 8; i++) {
            int idx = tid + i * 128;
            int row = idx >> 4, cc = idx & 15;
            size_t g = (size_t)(t * 64 + row) * KVD + kvh * HD + cc * 8;
            cpasync16(smem + SM_KH + row * KPAD + cc * 16, Kh + g);
            cpasync16(smem + SM_KL + row * KPAD + cc * 16, Kl + g);
        }
    };
    auto loadV = [&](int t) {
#pragma unroll
        for (int i = 0; i < 8; i++) {
            int idx = tid + i * 128;
            int row = idx >> 3, cc = idx & 7;
            size_t g = (size_t)(kvh * HD + row) * S + t * 64 + cc * 8;
            cpasync16(smem + SM_VH + row * VPAD + cc * 16, Vt16 + g);
        }
    };

#pragma unroll
    for (int i = 0; i < 8; i++) {
        int idx = tid + i * 128;
        int row = idx >> 4, cc = idx & 15;
        size_t g = (size_t)(q0 + row) * D + h * HD + cc * 8;
        cpasync16(smem + SM_QH + row * KPAD + cc * 16, Qh + g);
        cpasync16(smem + SM_QL + row * KPAD + cc * 16, Ql + g);
    }
    loadK(0);
    asm volatile("cp.async.commit_group;");
    asm volatile("cp.async.wait_group 0;");
    __syncthreads();

    uint32_t qh[8][4], ql[8][4];
    {
        int qrow = wid * 16 + (grp & 1) * 8 + ri;
        uint32_t qbase = smem + SM_QH + (uint32_t)qrow * KPAD + (grp >> 1) * 16u;
#pragma unroll
        for (int ks = 0; ks < 8; ks++) {
            ldmx4(qh[ks], qbase + ks * 32u);
            ldmx4(ql[ks], qbase + ks * 32u + (SM_QL - SM_QH));
        }
    }

    float m0 = -1e30f, m1 = -1e30f, l0 = 0.0f, l1 = 0.0f;
    float oacc[16][4];
#pragma unroll
    for (int f = 0; f < 16; f++)
#pragma unroll
        for (int e = 0; e < 4; e++) oacc[f][e] = 0.0f;

    const int rowA = wid * 16 + r;
    const int rowB = rowA + 8;

    for (int t = 0; t <= qt; t++) {
        if (t > 0) {
            asm volatile("cp.async.wait_group 0;");
            __syncthreads();
        }
        loadV(t);
        asm volatile("cp.async.commit_group;");

        float sacc[8][4];
#pragma unroll
        for (int f = 0; f < 8; f++)
#pragma unroll
            for (int e = 0; e < 4; e++) sacc[f][e] = 0.0f;

#pragma unroll
        for (int ks = 0; ks < 8; ks++) {
#pragma unroll
            for (int fnp = 0; fnp < 4; fnp++) {
                int krow = fnp * 16 + (grp & 1) * 8 + ri;
                uint32_t ka = smem + SM_KH + (uint32_t)krow * KPAD + ks * 32u + (grp >> 1) * 16u;
                uint32_t bh4[4], bl4[4];
                ldmx4(bh4, ka);
                ldmx4(bl4, ka + (SM_KL - SM_KH));
                uint32_t be[2]  = {bh4[0], bh4[2]};
                uint32_t bo[2]  = {bh4[1], bh4[3]};
                uint32_t ble[2] = {bl4[0], bl4[2]};
                uint32_t blo[2] = {bl4[1], bl4[3]};
                mma16816(sacc[2 * fnp],     qh[ks], be);
                mma16816(sacc[2 * fnp],     ql[ks], be);
                mma16816(sacc[2 * fnp],     qh[ks], ble);
                mma16816(sacc[2 * fnp + 1], qh[ks], bo);
                mma16816(sacc[2 * fnp + 1], ql[ks], bo);
                mma16816(sacc[2 * fnp + 1], qh[ks], blo);
            }
        }

        if (t == qt) {
#pragma unroll
            for (int fn = 0; fn < 8; fn++) {
                int c0 = fn * 8 + cgrp * 2;
                if (c0 > rowA) sacc[fn][0] = -1e30f;
                if (c0 + 1 > rowA) sacc[fn][1] = -1e30f;
                if (c0 > rowB) sacc[fn][2] = -1e30f;
                if (c0 + 1 > rowB) sacc[fn][3] = -1e30f;
            }
        }

        float tm0 = -1e30f, tm1 = -1e30f;
#pragma unroll
        for (int fn = 0; fn < 8; fn++) {
            tm0 = fmaxf(tm0, fmaxf(sacc[fn][0], sacc[fn][1]));
            tm1 = fmaxf(tm1, fmaxf(sacc[fn][2], sacc[fn][3]));
        }
        tm0 = fmaxf(tm0, __shfl_xor_sync(0xFFFFFFFFu, tm0, 1));
        tm0 = fmaxf(tm0, __shfl_xor_sync(0xFFFFFFFFu, tm0, 2));
        tm1 = fmaxf(tm1, __shfl_xor_sync(0xFFFFFFFFu, tm1, 1));
        tm1 = fmaxf(tm1, __shfl_xor_sync(0xFFFFFFFFu, tm1, 2));

        float mn0 = fmaxf(m0, tm0), mn1 = fmaxf(m1, tm1);
        float corr0 = exp2f(m0 - mn0), corr1 = exp2f(m1 - mn1);
        m0 = mn0; m1 = mn1;

        float rs0 = 0.0f, rs1 = 0.0f;
#pragma unroll
        for (int fn = 0; fn < 8; fn++) {
            sacc[fn][0] = exp2f(sacc[fn][0] - m0);
            sacc[fn][1] = exp2f(sacc[fn][1] - m0);
            sacc[fn][2] = exp2f(sacc[fn][2] - m1);
            sacc[fn][3] = exp2f(sacc[fn][3] - m1);
            rs0 += sacc[fn][0] + sacc[fn][1];
            rs1 += sacc[fn][2] + sacc[fn][3];
        }
        rs0 += __shfl_xor_sync(0xFFFFFFFFu, rs0, 1);
        rs0 += __shfl_xor_sync(0xFFFFFFFFu, rs0, 2);
        rs1 += __shfl_xor_sync(0xFFFFFFFFu, rs1, 1);
        rs1 += __shfl_xor_sync(0xFFFFFFFFu, rs1, 2);
        l0 = l0 * corr0 + rs0;
        l1 = l1 * corr1 + rs1;

#pragma unroll
        for (int f = 0; f < 16; f++) {
            oacc[f][0] *= corr0; oacc[f][1] *= corr0;
            oacc[f][2] *= corr1; oacc[f][3] *= corr1;
        }

        asm volatile("cp.async.wait_group 0;");
        __syncthreads();
        if (t < qt) {
            loadK(t + 1);
            asm volatile("cp.async.commit_group;");
        }

#pragma unroll
        for (int kk = 0; kk < 4; kk++) {
            uint32_t aph[4];
#pragma unroll
            for (int half = 0; half < 2; half++) {
                const float* sp = sacc[2 * kk + half];
                aph[half * 2 + 0] = pack_f16(sp[0], sp[1]);
                aph[half * 2 + 1] = pack_f16(sp[2], sp[3]);
            }
#pragma unroll
            for (int fnp = 0; fnp < 8; fnp++) {
                int vrow = fnp * 16 + (grp & 1) * 8 + ri;
                uint32_t va = smem + SM_VH + (uint32_t)vrow * VPAD + kk * 32u + (grp >> 1) * 16u;
                uint32_t bh4[4];
                ldmx4(bh4, va);
                uint32_t be[2] = {bh4[0], bh4[2]};
                uint32_t bo[2] = {bh4[1], bh4[3]};
                mma16816h(oacc[2 * fnp],     aph, be);
                mma16816h(oacc[2 * fnp + 1], aph, bo);
            }
        }
    }

    float inv0 = 1.0f / l0, inv1 = 1.0f / l1;
    const size_t gr0 = (size_t)(q0 + rowA) * D + h * HD + cgrp * 2;
    const size_t gr1 = (size_t)(q0 + rowB) * D + h * HD + cgrp * 2;
#pragma unroll
    for (int fn = 0; fn < 16; fn++) {
        *reinterpret_cast<__half2*>(O16 + gr0 + fn * 8) =
            __floats2half2_rn(oacc[fn][0] * inv0, oacc[fn][1] * inv0);
        *reinterpret_cast<__half2*>(O16 + gr1 + fn * 8) =
            __floats2half2_rn(oacc[fn][2] * inv1, oacc[fn][3] * inv1);
    }
}

// ---------------- launch ----------------
extern "C" void kernel_launch(void* const* d_in, const int* in_sizes, int n_in,
                              void* d_out, int out_size)
{
    const float* x    = (const float*)d_in[0];
    const float* wq   = (const float*)d_in[1];
    const float* wk   = (const float*)d_in[2];
    const float* wv   = (const float*)d_in[3];
    const float* wo   = (const float*)d_in[4];
    const float* cosb = (const float*)d_in[5];
    const float* sinb = (const float*)d_in[6];
    float* out = (float*)d_out;

    __nv_bfloat16 *xhi, *xlo, *qhi, *qlo, *khi, *klo, *wkhi, *wklo;
    __half *x16h, *x16l, *a16, *vt16, *wq16, *wv16, *wo16;
    cudaGetSymbolAddress((void**)&xhi, g_xhi);   cudaGetSymbolAddress((void**)&xlo, g_xlo);
    cudaGetSymbolAddress((void**)&x16h, g_x16h); cudaGetSymbolAddress((void**)&x16l, g_x16l);
    cudaGetSymbolAddress((void**)&a16, g_a16);
    cudaGetSymbolAddress((void**)&qhi, g_qhi);   cudaGetSymbolAddress((void**)&qlo, g_qlo);
    cudaGetSymbolAddress((void**)&khi, g_khi);   cudaGetSymbolAddress((void**)&klo, g_klo);
    cudaGetSymbolAddress((void**)&vt16, g_vt16);
    cudaGetSymbolAddress((void**)&wq16, g_wq16);
    cudaGetSymbolAddress((void**)&wkhi, g_wkhi); cudaGetSymbolAddress((void**)&wklo, g_wklo);
    cudaGetSymbolAddress((void**)&wv16, g_wv16); cudaGetSymbolAddress((void**)&wo16, g_wo16);

    const int shmem = 3 * (int)GSTAGE;        // 98304
    const int shmemo = 3 * (int)G16STAGE;     // 49152
    cudaFuncSetAttribute(proj_kernel, cudaFuncAttributeMaxDynamicSharedMemorySize, shmem);
    cudaFuncSetAttribute(gemmo_kernel, cudaFuncAttributeMaxDynamicSharedMemorySize, shmemo);
    cudaFuncSetAttribute(fattn_kernel, cudaFuncAttributeMaxDynamicSharedMemorySize, (int)SM_TOT);

    const float qscale = 0.08838834764831845f * 1.4426950408889634f;  // 1/sqrt(128) * log2(e)

    // input conversions
    xsplit_all<<<(S * D / 4 + 255) / 256, 256>>>(x, xhi, xlo, x16h, x16l, S * D / 4);
    tsplit16_kernel<<<dim3(D / 32, D / 32), dim3(32, 8)>>>(wq, wq16, D, D);
    tsplit_kernel<<<dim3(KVD / 32, D / 32), dim3(32, 8)>>>(wk, wkhi, wklo, D, KVD);
    tsplit16_kernel<<<dim3(KVD / 32, D / 32), dim3(32, 8)>>>(wv, wv16, D, KVD);
    tsplit16_kernel<<<dim3(D / 32, D / 32), dim3(32, 8)>>>(wo, wo16, D, D);

    // unified Q/K/V projection, dynamic tile scheduler
    reset_ctr<<<1, 1>>>();
    proj_kernel<<<PGRID, 256, shmem>>>(
        xhi, xlo, x16h, x16l, wq16, wkhi, wklo, wv16,
        qhi, qlo, khi, klo, vt16, cosb, sinb, qscale);

    // flash attention (log2-domain softmax) -> fp16
    fattn_kernel<<<dim3(S / 64, H), 128, SM_TOT>>>(qhi, qlo, khi, klo, vt16, a16);

    // output projection: fp16 1-term, fp32 out (persistent)
    gemmo_kernel<<<PGRID, 256, shmemo>>>(
        a16, wo16, out, D, D, D / 128, (D / 128) * (S / 128));
}

// round 12
// speedup vs baseline: 1.5249x; 1.0409x over previous
#include <cuda_runtime.h>
#include <cuda_bf16.h>
#include <cuda_fp16.h>
#include <cstdint>

#define S 2048
#define D 4096
#define H 32
#define KVH 8
#define HD 128
#define NREP (H / KVH)
#define KVD (KVH * HD)
#define PGRID 304

// ---------------- scratch (static device arrays; no allocation) ----------------
__device__ __half g_x16h[S * D], g_x16l[S * D];
__device__ __half g_a16[S * D];
__device__ __half g_q16h[S * D], g_q16l[S * D];
__device__ __half g_k16h[S * KVD], g_k16l[S * KVD];
__device__ __half g_vt16[KVD * S];                 // transposed [KVD][S]
__device__ __half g_wq16[D * D];                   // transposed [N,K]
__device__ __half g_wk16[KVD * D];
__device__ __half g_wv16[KVD * D];
__device__ __half g_wo16[D * D];
__device__ int    g_ctr;

// ---------------- helpers ----------------
__device__ __forceinline__ uint32_t s2u(const void* p) {
    uint32_t a;
    asm("{ .reg .u64 t; cvta.to.shared.u64 t, %1; cvt.u32.u64 %0, t; }" : "=r"(a) : "l"(p));
    return a;
}
__device__ __forceinline__ void cpasync16(uint32_t saddr, const void* gaddr) {
    asm volatile("cp.async.cg.shared.global [%0], [%1], 16;" :: "r"(saddr), "l"(gaddr));
}
__device__ __forceinline__ void ldmx4(uint32_t* r, uint32_t addr) {
    asm volatile("ldmatrix.sync.aligned.m8n8.x4.shared.b16 {%0,%1,%2,%3}, [%4];"
                 : "=r"(r[0]), "=r"(r[1]), "=r"(r[2]), "=r"(r[3]) : "r"(addr));
}
__device__ __forceinline__ void mma16816h(float* d, const uint32_t* a, const uint32_t* b) {
    asm volatile(
        "mma.sync.aligned.m16n8k16.row.col.f32.f16.f16.f32 "
        "{%0,%1,%2,%3}, {%4,%5,%6,%7}, {%8,%9}, {%0,%1,%2,%3};"
        : "+f"(d[0]), "+f"(d[1]), "+f"(d[2]), "+f"(d[3])
        : "r"(a[0]), "r"(a[1]), "r"(a[2]), "r"(a[3]), "r"(b[0]), "r"(b[1]));
}
__device__ __forceinline__ uint32_t pack_f16(float x, float y) {
    __half2 t = __floats2half2_rn(x, y);
    return *reinterpret_cast<uint32_t*>(&t);
}
__device__ __forceinline__ void split2h(float v0, float v1, __half2& ph, __half2& pl) {
    __half h0 = __float2half_rn(v0), h1 = __float2half_rn(v1);
    ph = __halves2half2(h0, h1);
    pl = __halves2half2(__float2half_rn(v0 - __half2float(h0)),
                        __float2half_rn(v1 - __half2float(h1)));
}

// ---------------- counter reset ----------------
__global__ void reset_ctr() { g_ctr = 0; }

// ---------------- x: fp32 -> fp16 hi/lo ----------------
__global__ void xsplit16(const float* __restrict__ in,
                         __half* __restrict__ fh, __half* __restrict__ fl, int n4)
{
    int i = blockIdx.x * blockDim.x + threadIdx.x;
    if (i >= n4) return;
    float4 v = reinterpret_cast<const float4*>(in)[i];
    __half2 hh, hl;
    split2h(v.x, v.y, hh, hl);
    reinterpret_cast<__half2*>(fh)[2 * i] = hh;
    reinterpret_cast<__half2*>(fl)[2 * i] = hl;
    split2h(v.z, v.w, hh, hl);
    reinterpret_cast<__half2*>(fh)[2 * i + 1] = hh;
    reinterpret_cast<__half2*>(fl)[2 * i + 1] = hl;
}

// ---------------- transpose: W[K,N] fp32 -> fp16 [N,K] ----------------
__global__ void tsplit16_kernel(const float* __restrict__ w,
                                __half* __restrict__ out, int K, int N)
{
    __shared__ float t[32][33];
    int n0 = blockIdx.x * 32, k0 = blockIdx.y * 32;
    int tx = threadIdx.x, ty = threadIdx.y;
    for (int r = ty; r < 32; r += 8)
        t[r][tx] = w[(size_t)(k0 + r) * N + n0 + tx];
    __syncthreads();
    for (int r = ty; r < 32; r += 8)
        out[(size_t)(n0 + r) * K + k0 + tx] = __float2half_rn(t[tx][r]);
}

#define GTILE  8192u
#define GSTAGE 24576u   // 3 tiles: A-hi, A-lo, B

// tile map: [0,128) K tiles, [128,640) Q tiles, [640,768) V tiles (1-term, light)
#define NT_K 128
#define NT_Q 512
#define NT_TOT 768

// ---------------- unified persistent projection kernel (all fp16) ----------------
__global__ __launch_bounds__(256, 2) void proj_kernel(
    const __half* __restrict__ X16h, const __half* __restrict__ X16l,
    const __half* __restrict__ Wq16, const __half* __restrict__ Wk16,
    const __half* __restrict__ Wv16,
    __half* __restrict__ Q16h, __half* __restrict__ Q16l,
    __half* __restrict__ K16h, __half* __restrict__ K16l,
    __half* __restrict__ Vt16,
    const float* __restrict__ cosb, const float* __restrict__ sinb, float qscale)
{
    extern __shared__ char dsm[];
    const uint32_t smem = s2u(dsm);
    __shared__ int s_tile;

    const int tid = threadIdx.x;
    const int wid = tid >> 5;
    const int lane = tid & 31;
    const int wm = (wid & 1) * 64;
    const int wn = (wid >> 1) * 32;
    const int grp = lane >> 3;
    const int ri = lane & 7;
    const int erow = lane >> 2;
    const int ecol = (lane & 3) * 2;
    const int nchunks = D >> 5;

    while (true) {
        __syncthreads();
        if (tid == 0) s_tile = atomicAdd(&g_ctr, 1);
        __syncthreads();
        const int t = s_tile;
        if (t >= NT_TOT) break;

        const bool isV = (t >= NT_K + NT_Q);
        const __half* B;
        __half *Ch = nullptr, *Cl = nullptr;
        int bx, by, Ndim = 0;
        float scale = 1.0f;
        if (t < NT_K) {
            B = Wk16; bx = (t & 7) * 128; by = (t >> 3) * 128;
            Ndim = KVD; Ch = K16h; Cl = K16l;
        } else if (!isV) {
            int q = t - NT_K;
            B = Wq16; bx = (q & 31) * 128; by = (q >> 5) * 128;
            Ndim = D; scale = qscale; Ch = Q16h; Cl = Q16l;
        } else {
            int v = t - NT_K - NT_Q;
            B = Wv16; bx = (v & 7) * 128; by = (v >> 3) * 128;
        }
        const bool two_term = !isV;

        float acc[4][4][4];
#pragma unroll
        for (int i = 0; i < 4; i++)
#pragma unroll
            for (int j = 0; j < 4; j++)
#pragma unroll
                for (int e = 0; e < 4; e++) acc[i][j][e] = 0.0f;

        auto load_stage = [&](int c, int stage) {
            const uint32_t sb = smem + stage * GSTAGE;
            const int k0 = c << 5;
#pragma unroll
            for (int i = 0; i < 2; i++) {
                int idx = tid + i * 256;
                int row = idx >> 2, cc = idx & 3;
                uint32_t sc = (uint32_t)(cc ^ ((row >> 1) & 3));
                uint32_t so = (uint32_t)row * 64u + sc * 16u;
                size_t ga = (size_t)(by + row) * D + k0 + cc * 8;
                cpasync16(sb + so, X16h + ga);
                if (two_term) cpasync16(sb + GTILE + so, X16l + ga);
                cpasync16(sb + 2 * GTILE + so, B + (size_t)(bx + row) * D + k0 + cc * 8);
            }
        };

        load_stage(0, 0);
        asm volatile("cp.async.commit_group;");
        load_stage(1, 1);
        asm volatile("cp.async.commit_group;");

        for (int c = 0; c < nchunks; c++) {
            if (c + 1 < nchunks) asm volatile("cp.async.wait_group 1;");
            else                 asm volatile("cp.async.wait_group 0;");
            __syncthreads();
            if (c + 2 < nchunks) {
                load_stage(c + 2, (c + 2) % 3);
                asm volatile("cp.async.commit_group;");
            }
            const uint32_t sb = smem + (c % 3) * GSTAGE;

#pragma unroll
            for (int k16 = 0; k16 < 2; k16++) {
                const int lchunk = k16 * 2 + (grp >> 1);
                uint32_t ah[4][4], al[4][4];
#pragma unroll
                for (int fm = 0; fm < 4; fm++) {
                    int row = wm + fm * 16 + (grp & 1) * 8 + ri;
                    uint32_t ad = sb + (uint32_t)row * 64u
                                + (uint32_t)((lchunk ^ ((row >> 1) & 3)) * 16);
                    ldmx4(ah[fm], ad);
                    if (two_term) ldmx4(al[fm], ad + GTILE);
                }
#pragma unroll
                for (int fnp = 0; fnp < 2; fnp++) {
                    int row = wn + fnp * 16 + (grp & 1) * 8 + ri;
                    uint32_t bd = sb + 2 * GTILE + (uint32_t)row * 64u
                                + (uint32_t)((lchunk ^ ((row >> 1) & 3)) * 16);
                    uint32_t bh4[4];
                    ldmx4(bh4, bd);
                    uint32_t be[2] = {bh4[0], bh4[2]};
                    uint32_t bo[2] = {bh4[1], bh4[3]};
#pragma unroll
                    for (int fm = 0; fm < 4; fm++) {
                        mma16816h(acc[fm][2 * fnp],     ah[fm], be);
                        mma16816h(acc[fm][2 * fnp + 1], ah[fm], bo);
                        if (two_term) {
                            mma16816h(acc[fm][2 * fnp],     al[fm], be);
                            mma16816h(acc[fm][2 * fnp + 1], al[fm], bo);
                        }
                    }
                }
            }
        }

        if (!isV) {
            // RoPE + scale + fp16 split
#pragma unroll
            for (int fm = 0; fm < 4; fm++) {
#pragma unroll
                for (int fn = 0; fn < 4; fn++) {
                    int col = bx + wn + fn * 8 + ecol;
                    int i = (col & 127) >> 1;
#pragma unroll
                    for (int half = 0; half < 2; half++) {
                        int row = by + wm + fm * 16 + erow + half * 8;
                        float cv = cosb[row * 64 + i];
                        float sv = sinb[row * 64 + i];
                        float t0 = acc[fm][fn][half * 2], t1 = acc[fm][fn][half * 2 + 1];
                        float o0 = (t0 * cv - t1 * sv) * scale;
                        float o1 = (t0 * sv + t1 * cv) * scale;
                        __half2 ph, pl;
                        split2h(o0, o1, ph, pl);
                        size_t o = (size_t)row * Ndim + col;
                        *reinterpret_cast<__half2*>(Ch + o) = ph;
                        *reinterpret_cast<__half2*>(Cl + o) = pl;
                    }
                }
            }
        } else {
            // transpose fp16 -> Vt
#pragma unroll
            for (int fm = 0; fm < 4; fm++) {
#pragma unroll
                for (int fn = 0; fn < 4; fn++) {
                    int col = bx + wn + fn * 8 + ecol;
#pragma unroll
                    for (int half = 0; half < 2; half++) {
                        int row = by + wm + fm * 16 + erow + half * 8;
#pragma unroll
                        for (int e = 0; e < 2; e++) {
                            float vv = acc[fm][fn][half * 2 + e];
                            Vt16[(size_t)(col + e) * S + row] = __float2half_rn(vv);
                        }
                    }
                }
            }
        }
    }
}

// ---------------- fp16 1-term GEMM: O projection, persistent ----------------
#define G16STAGE 16384u

__global__ __launch_bounds__(256, 2) void gemmo_kernel(
    const __half* __restrict__ A16, const __half* __restrict__ B16,
    float* __restrict__ Cf, int Ndim, int Kdim, int ntx, int ntiles)
{
    extern __shared__ char dsm[];
    const uint32_t smem = s2u(dsm);

    const int tid = threadIdx.x;
    const int wid = tid >> 5;
    const int lane = tid & 31;
    const int wm = (wid & 1) * 64;
    const int wn = (wid >> 1) * 32;
    const int grp = lane >> 3;
    const int ri = lane & 7;

    for (int tile = blockIdx.x; tile < ntiles; tile += gridDim.x) {
        const int bx = (tile % ntx) * 128;
        const int by = (tile / ntx) * 128;

        float acc[4][4][4];
#pragma unroll
        for (int i = 0; i < 4; i++)
#pragma unroll
            for (int j = 0; j < 4; j++)
#pragma unroll
                for (int e = 0; e < 4; e++) acc[i][j][e] = 0.0f;

        auto load_stage = [&](int c, int stage) {
            const uint32_t sb = smem + stage * G16STAGE;
            const int k0 = c << 5;
#pragma unroll
            for (int i = 0; i < 2; i++) {
                int idx = tid + i * 256;
                int row = idx >> 2, cc = idx & 3;
                uint32_t sc = (uint32_t)(cc ^ ((row >> 1) & 3));
                uint32_t so = (uint32_t)row * 64u + sc * 16u;
                cpasync16(sb + so,         A16 + (size_t)(by + row) * Kdim + k0 + cc * 8);
                cpasync16(sb + GTILE + so, B16 + (size_t)(bx + row) * Kdim + k0 + cc * 8);
            }
        };

        load_stage(0, 0);
        asm volatile("cp.async.commit_group;");
        load_stage(1, 1);
        asm volatile("cp.async.commit_group;");

        const int nchunks = Kdim >> 5;
        for (int c = 0; c < nchunks; c++) {
            if (c + 1 < nchunks) asm volatile("cp.async.wait_group 1;");
            else                 asm volatile("cp.async.wait_group 0;");
            __syncthreads();
            if (c + 2 < nchunks) {
                load_stage(c + 2, (c + 2) % 3);
                asm volatile("cp.async.commit_group;");
            }
            const uint32_t sb = smem + (c % 3) * G16STAGE;
#pragma unroll
            for (int k16 = 0; k16 < 2; k16++) {
                const int lchunk = k16 * 2 + (grp >> 1);
                uint32_t ah[4][4];
#pragma unroll
                for (int fm = 0; fm < 4; fm++) {
                    int row = wm + fm * 16 + (grp & 1) * 8 + ri;
                    uint32_t ad = sb + (uint32_t)row * 64u
                                + (uint32_t)((lchunk ^ ((row >> 1) & 3)) * 16);
                    ldmx4(ah[fm], ad);
                }
#pragma unroll
                for (int fnp = 0; fnp < 2; fnp++) {
                    int row = wn + fnp * 16 + (grp & 1) * 8 + ri;
                    uint32_t bd = sb + GTILE + (uint32_t)row * 64u
                                + (uint32_t)((lchunk ^ ((row >> 1) & 3)) * 16);
                    uint32_t bh4[4];
                    ldmx4(bh4, bd);
                    uint32_t be[2] = {bh4[0], bh4[2]};
                    uint32_t bo[2] = {bh4[1], bh4[3]};
#pragma unroll
                    for (int fm = 0; fm < 4; fm++) {
                        mma16816h(acc[fm][2 * fnp],     ah[fm], be);
                        mma16816h(acc[fm][2 * fnp + 1], ah[fm], bo);
                    }
                }
            }
        }

        const int erow = lane >> 2;
        const int ecol = (lane & 3) * 2;
#pragma unroll
        for (int fm = 0; fm < 4; fm++) {
#pragma unroll
            for (int fn = 0; fn < 4; fn++) {
                float* cp0 = Cf + (size_t)(by + wm + fm * 16 + erow) * Ndim + bx + wn + fn * 8 + ecol;
                float* cp1 = cp0 + 8 * (size_t)Ndim;
                *reinterpret_cast<float2*>(cp0) = make_float2(acc[fm][fn][0], acc[fm][fn][1]);
                *reinterpret_cast<float2*>(cp1) = make_float2(acc[fm][fn][2], acc[fm][fn][3]);
            }
        }
        __syncthreads();
    }
}

// ---------------- flash attention: all-fp16, Q overlaid on K smem ----------------
#define KPAD 272u
#define VPAD 144u
#define SM_KH 0u
#define SM_KL 17408u
#define SM_V  34816u
#define SM_TOT 53248u

__global__ __launch_bounds__(128, 3) void fattn_kernel(
    const __half* __restrict__ Qh, const __half* __restrict__ Ql,
    const __half* __restrict__ Kh, const __half* __restrict__ Kl,
    const __half* __restrict__ Vt16, __half* __restrict__ O16)
{
    extern __shared__ char dsm[];
    const uint32_t smem = s2u(dsm);
    const int tid = threadIdx.x;
    const int wid = tid >> 5, lane = tid & 31;
    const int qt = gridDim.x - 1 - blockIdx.x;
    const int h = blockIdx.y;
    const int kvh = h / NREP;
    const int q0 = qt * 64;

    const int r = lane >> 2;
    const int cgrp = lane & 3;
    const int grp = lane >> 3;
    const int ri = lane & 7;

    auto loadK = [&](int t) {
#pragma unroll
        for (int i = 0; i < 8; i++) {
            int idx = tid + i * 128;
            int row = idx >> 4, cc = idx & 15;
            size_t g = (size_t)(t * 64 + row) * KVD + kvh * HD + cc * 8;
            cpasync16(smem + SM_KH + row * KPAD + cc * 16, Kh + g);
            cpasync16(smem + SM_KL + row * KPAD + cc * 16, Kl + g);
        }
    };
    auto loadV = [&](int t) {
#pragma unroll
        for (int i = 0; i < 8; i++) {
            int idx = tid + i * 128;
            int row = idx >> 3, cc = idx & 7;
            size_t g = (size_t)(kvh * HD + row) * S + t * 64 + cc * 8;
            cpasync16(smem + SM_V + row * VPAD + cc * 16, Vt16 + g);
        }
    };

    // ---- stage Q into the K region, read to registers, then release ----
#pragma unroll
    for (int i = 0; i < 8; i++) {
        int idx = tid + i * 128;
        int row = idx >> 4, cc = idx & 15;
        size_t g = (size_t)(q0 + row) * D + h * HD + cc * 8;
        cpasync16(smem + SM_KH + row * KPAD + cc * 16, Qh + g);
        cpasync16(smem + SM_KL + row * KPAD + cc * 16, Ql + g);
    }
    asm volatile("cp.async.commit_group;");
    asm volatile("cp.async.wait_group 0;");
    __syncthreads();

    uint32_t qh[8][4], ql[8][4];
    {
        int qrow = wid * 16 + (grp & 1) * 8 + ri;
        uint32_t qbase = smem + SM_KH + (uint32_t)qrow * KPAD + (grp >> 1) * 16u;
#pragma unroll
        for (int ks = 0; ks < 8; ks++) {
            ldmx4(qh[ks], qbase + ks * 32u);
            ldmx4(ql[ks], qbase + ks * 32u + (SM_KL - SM_KH));
        }
    }
    __syncthreads();   // all warps done reading Q before K overwrites

    loadK(0);
    asm volatile("cp.async.commit_group;");

    float m0 = -1e30f, m1 = -1e30f, l0 = 0.0f, l1 = 0.0f;
    float oacc[16][4];
#pragma unroll
    for (int f = 0; f < 16; f++)
#pragma unroll
        for (int e = 0; e < 4; e++) oacc[f][e] = 0.0f;

    const int rowA = wid * 16 + r;
    const int rowB = rowA + 8;

    for (int t = 0; t <= qt; t++) {
        asm volatile("cp.async.wait_group 0;");
        __syncthreads();
        loadV(t);
        asm volatile("cp.async.commit_group;");

        float sacc[8][4];
#pragma unroll
        for (int f = 0; f < 8; f++)
#pragma unroll
            for (int e = 0; e < 4; e++) sacc[f][e] = 0.0f;

#pragma unroll
        for (int ks = 0; ks < 8; ks++) {
#pragma unroll
            for (int fnp = 0; fnp < 4; fnp++) {
                int krow = fnp * 16 + (grp & 1) * 8 + ri;
                uint32_t ka = smem + SM_KH + (uint32_t)krow * KPAD + ks * 32u + (grp >> 1) * 16u;
                uint32_t bh4[4], bl4[4];
                ldmx4(bh4, ka);
                ldmx4(bl4, ka + (SM_KL - SM_KH));
                uint32_t be[2]  = {bh4[0], bh4[2]};
                uint32_t bo[2]  = {bh4[1], bh4[3]};
                uint32_t ble[2] = {bl4[0], bl4[2]};
                uint32_t blo[2] = {bl4[1], bl4[3]};
                mma16816h(sacc[2 * fnp],     qh[ks], be);
                mma16816h(sacc[2 * fnp],     ql[ks], be);
                mma16816h(sacc[2 * fnp],     qh[ks], ble);
                mma16816h(sacc[2 * fnp + 1], qh[ks], bo);
                mma16816h(sacc[2 * fnp + 1], ql[ks], bo);
                mma16816h(sacc[2 * fnp + 1], qh[ks], blo);
            }
        }

        if (t == qt) {
#pragma unroll
            for (int fn = 0; fn < 8; fn++) {
                int c0 = fn * 8 + cgrp * 2;
                if (c0 > rowA) sacc[fn][0] = -1e30f;
                if (c0 + 1 > rowA) sacc[fn][1] = -1e30f;
                if (c0 > rowB) sacc[fn][2] = -1e30f;
                if (c0 + 1 > rowB) sacc[fn][3] = -1e30f;
            }
        }

        float tm0 = -1e30f, tm1 = -1e30f;
#pragma unroll
        for (int fn = 0; fn < 8; fn++) {
            tm0 = fmaxf(tm0, fmaxf(sacc[fn][0], sacc[fn][1]));
            tm1 = fmaxf(tm1, fmaxf(sacc[fn][2], sacc[fn][3]));
        }
        tm0 = fmaxf(tm0, __shfl_xor_sync(0xFFFFFFFFu, tm0, 1));
        tm0 = fmaxf(tm0, __shfl_xor_sync(0xFFFFFFFFu, tm0, 2));
        tm1 = fmaxf(tm1, __shfl_xor_sync(0xFFFFFFFFu, tm1, 1));
        tm1 = fmaxf(tm1, __shfl_xor_sync(0xFFFFFFFFu, tm1, 2));

        float mn0 = fmaxf(m0, tm0), mn1 = fmaxf(m1, tm1);
        float corr0 = exp2f(m0 - mn0), corr1 = exp2f(m1 - mn1);
        m0 = mn0; m1 = mn1;

        float rs0 = 0.0f, rs1 = 0.0f;
#pragma unroll
        for (int fn = 0; fn < 8; fn++) {
            sacc[fn][0] = exp2f(sacc[fn][0] - m0);
            sacc[fn][1] = exp2f(sacc[fn][1] - m0);
            sacc[fn][2] = exp2f(sacc[fn][2] - m1);
            sacc[fn][3] = exp2f(sacc[fn][3] - m1);
            rs0 += sacc[fn][0] + sacc[fn][1];
            rs1 += sacc[fn][2] + sacc[fn][3];
        }
        rs0 += __shfl_xor_sync(0xFFFFFFFFu, rs0, 1);
        rs0 += __shfl_xor_sync(0xFFFFFFFFu, rs0, 2);
        rs1 += __shfl_xor_sync(0xFFFFFFFFu, rs1, 1);
        rs1 += __shfl_xor_sync(0xFFFFFFFFu, rs1, 2);
        l0 = l0 * corr0 + rs0;
        l1 = l1 * corr1 + rs1;

#pragma unroll
        for (int f = 0; f < 16; f++) {
            oacc[f][0] *= corr0; oacc[f][1] *= corr0;
            oacc[f][2] *= corr1; oacc[f][3] *= corr1;
        }

        asm volatile("cp.async.wait_group 0;");
        __syncthreads();
        if (t < qt) {
            loadK(t + 1);
            asm volatile("cp.async.commit_group;");
        }

        // ---- O += P V (P single fp16, V single fp16) ----
#pragma unroll
        for (int kk = 0; kk < 4; kk++) {
            uint32_t aph[4];
#pragma unroll
            for (int half = 0; half < 2; half++) {
                const float* sp = sacc[2 * kk + half];
                aph[half * 2 + 0] = pack_f16(sp[0], sp[1]);
                aph[half * 2 + 1] = pack_f16(sp[2], sp[3]);
            }
#pragma unroll
            for (int fnp = 0; fnp < 8; fnp++) {
                int vrow = fnp * 16 + (grp & 1) * 8 + ri;
                uint32_t va = smem + SM_V + (uint32_t)vrow * VPAD + kk * 32u + (grp >> 1) * 16u;
                uint32_t bh4[4];
                ldmx4(bh4, va);
                uint32_t be[2] = {bh4[0], bh4[2]};
                uint32_t bo[2] = {bh4[1], bh4[3]};
                mma16816h(oacc[2 * fnp],     aph, be);
                mma16816h(oacc[2 * fnp + 1], aph, bo);
            }
        }
    }

    float inv0 = 1.0f / l0, inv1 = 1.0f / l1;
    const size_t gr0 = (size_t)(q0 + rowA) * D + h * HD + cgrp * 2;
    const size_t gr1 = (size_t)(q0 + rowB) * D + h * HD + cgrp * 2;
#pragma unroll
    for (int fn = 0; fn < 16; fn++) {
        *reinterpret_cast<__half2*>(O16 + gr0 + fn * 8) =
            __floats2half2_rn(oacc[fn][0] * inv0, oacc[fn][1] * inv0);
        *reinterpret_cast<__half2*>(O16 + gr1 + fn * 8) =
            __floats2half2_rn(oacc[fn][2] * inv1, oacc[fn][3] * inv1);
    }
}

// ---------------- launch ----------------
extern "C" void kernel_launch(void* const* d_in, const int* in_sizes, int n_in,
                              void* d_out, int out_size)
{
    const float* x    = (const float*)d_in[0];
    const float* wq   = (const float*)d_in[1];
    const float* wk   = (const float*)d_in[2];
    const float* wv   = (const float*)d_in[3];
    const float* wo   = (const float*)d_in[4];
    const float* cosb = (const float*)d_in[5];
    const float* sinb = (const float*)d_in[6];
    float* out = (float*)d_out;

    __half *x16h, *x16l, *a16, *q16h, *q16l, *k16h, *k16l, *vt16;
    __half *wq16, *wk16, *wv16, *wo16;
    cudaGetSymbolAddress((void**)&x16h, g_x16h); cudaGetSymbolAddress((void**)&x16l, g_x16l);
    cudaGetSymbolAddress((void**)&a16, g_a16);
    cudaGetSymbolAddress((void**)&q16h, g_q16h); cudaGetSymbolAddress((void**)&q16l, g_q16l);
    cudaGetSymbolAddress((void**)&k16h, g_k16h); cudaGetSymbolAddress((void**)&k16l, g_k16l);
    cudaGetSymbolAddress((void**)&vt16, g_vt16);
    cudaGetSymbolAddress((void**)&wq16, g_wq16); cudaGetSymbolAddress((void**)&wk16, g_wk16);
    cudaGetSymbolAddress((void**)&wv16, g_wv16); cudaGetSymbolAddress((void**)&wo16, g_wo16);

    const int shmem = 3 * (int)GSTAGE;        // 73728
    const int shmemo = 3 * (int)G16STAGE;     // 49152
    cudaFuncSetAttribute(proj_kernel, cudaFuncAttributeMaxDynamicSharedMemorySize, shmem);
    cudaFuncSetAttribute(gemmo_kernel, cudaFuncAttributeMaxDynamicSharedMemorySize, shmemo);
    cudaFuncSetAttribute(fattn_kernel, cudaFuncAttributeMaxDynamicSharedMemorySize, (int)SM_TOT);

    const float qscale = 0.08838834764831845f * 1.4426950408889634f;  // 1/sqrt(128)*log2(e)

    // input conversions (all fp16 now)
    xsplit16<<<(S * D / 4 + 255) / 256, 256>>>(x, x16h, x16l, S * D / 4);
    tsplit16_kernel<<<dim3(D / 32, D / 32), dim3(32, 8)>>>(wq, wq16, D, D);
    tsplit16_kernel<<<dim3(KVD / 32, D / 32), dim3(32, 8)>>>(wk, wk16, D, KVD);
    tsplit16_kernel<<<dim3(KVD / 32, D / 32), dim3(32, 8)>>>(wv, wv16, D, KVD);
    tsplit16_kernel<<<dim3(D / 32, D / 32), dim3(32, 8)>>>(wo, wo16, D, D);

    // unified Q/K/V projection, dynamic tile scheduler
    reset_ctr<<<1, 1>>>();
    proj_kernel<<<PGRID, 256, shmem>>>(
        x16h, x16l, wq16, wk16, wv16,
        q16h, q16l, k16h, k16l, vt16, cosb, sinb, qscale);

    // flash attention (log2-domain softmax, all fp16) -> fp16
    fattn_kernel<<<dim3(S / 64, H), 128, SM_TOT>>>(q16h, q16l, k16h, k16l, vt16, a16);

    // output projection: fp16 1-term, fp32 out (persistent)
    gemmo_kernel<<<PGRID, 256, shmemo>>>(
        a16, wo16, out, D, D, D / 128, (D / 128) * (S / 128));
}